// round 1
// baseline (speedup 1.0000x reference)
#include <cuda_runtime.h>
#include <math.h>

// ---------------------------------------------------------------------------
// WanCrossAttention  (B=1, L=8192, S=512, C=2048, CTX=4096, H=16, D=128)
//
//   q = RMSNorm(x @ Wq + bq) * g_q
//   k = RMSNorm(ctx @ Wk + bk) * g_k
//   v = ctx @ Wv + bv
//   per head: P = softmax(Q K^T / sqrt(128));  A = P V
//   out = A @ Wo + bo
//
// Round-1: fp32 baseline. One generic register-tiled SGEMM (128x128x16,
// 256 threads, 8x8 micro-tile with 4+4 split for conflict-free LDS.128),
// used for all 6 GEMMs (batched-per-head via blockIdx.z strides, NT variant
// for scores). RMSNorm and softmax are small memory-bound kernels.
// ---------------------------------------------------------------------------

#define L_Q   8192
#define S_KV  512
#define C_DIM 2048
#define CTXD  4096
#define NH    16
#define HD    128

// Scratch (static device globals — allocation rules forbid cudaMalloc)
__device__ float g_qbuf[L_Q * C_DIM];              //  64 MB
__device__ float g_kbuf[S_KV * C_DIM];             //   4 MB
__device__ float g_vbuf[S_KV * C_DIM];             //   4 MB
__device__ float g_scores[(size_t)NH * L_Q * S_KV];// 256 MB
__device__ float g_attn[L_Q * C_DIM];              //  64 MB

// ---------------------------------------------------------------------------
// Generic SGEMM:  C[z] = A[z] (MxK) * B[z] (KxN) (+ bias)
//   A row-major with leading dim lda, per-z offset sA (in elements)
//   B: if BCOL==false, row-major KxN (ldb = row stride)
//      if BCOL==true,  B[k][n] = Bptr[n*ldb + k]   (i.e. N-major / "B^T")
//   C row-major, leading dim ldc, per-z offset sC
// All of M, N divisible by 128; K divisible by 16. No bounds checks needed
// for this problem's fixed shapes.
// ---------------------------------------------------------------------------
template <bool BCOL>
__global__ __launch_bounds__(256)
void sgemm_kernel(const float* __restrict__ A, int lda, long sA,
                  const float* __restrict__ B, int ldb, long sB,
                  const float* __restrict__ bias,
                  float* __restrict__ C, int ldc, long sC,
                  int K)
{
    const int m0 = blockIdx.y * 128;
    const int n0 = blockIdx.x * 128;
    A += (long)blockIdx.z * sA + (long)m0 * lda;
    B += (long)blockIdx.z * sB;
    C += (long)blockIdx.z * sC + (long)m0 * ldc + n0;
    const float* biasp = bias ? (bias + n0) : nullptr;

    __shared__ float As[16][128];
    __shared__ float Bs[16][128];

    const int tx = threadIdx.x & 15;   // 0..15 -> columns
    const int ty = threadIdx.x >> 4;   // 0..15 -> rows

    float acc[8][8];
#pragma unroll
    for (int i = 0; i < 8; ++i)
#pragma unroll
        for (int j = 0; j < 8; ++j) acc[i][j] = 0.f;

    for (int kt = 0; kt < K; kt += 16) {
        // ---- load A tile (128 rows x 16 k), store transposed As[k][m]
        {
            int idx = threadIdx.x;
#pragma unroll
            for (int r = 0; r < 2; ++r, idx += 256) {
                int row = idx >> 2;            // 0..127
                int c4  = (idx & 3) << 2;      // 0,4,8,12
                float4 f = *(const float4*)(A + (long)row * lda + kt + c4);
                As[c4 + 0][row] = f.x;
                As[c4 + 1][row] = f.y;
                As[c4 + 2][row] = f.z;
                As[c4 + 3][row] = f.w;
            }
        }
        // ---- load B tile (16 k x 128 n)
        if (!BCOL) {
            int idx = threadIdx.x;
#pragma unroll
            for (int r = 0; r < 2; ++r, idx += 256) {
                int row = idx >> 5;            // 0..15
                int c   = (idx & 31) << 2;     // 0..124
                *(float4*)&Bs[row][c] =
                    *(const float4*)(B + (long)(kt + row) * ldb + n0 + c);
            }
        } else {
            int idx = threadIdx.x;
#pragma unroll
            for (int r = 0; r < 2; ++r, idx += 256) {
                int n  = idx >> 2;             // 0..127
                int c4 = (idx & 3) << 2;       // 0,4,8,12
                float4 f = *(const float4*)(B + (long)(n0 + n) * ldb + kt + c4);
                Bs[c4 + 0][n] = f.x;
                Bs[c4 + 1][n] = f.y;
                Bs[c4 + 2][n] = f.z;
                Bs[c4 + 3][n] = f.w;
            }
        }
        __syncthreads();

#pragma unroll
        for (int k = 0; k < 16; ++k) {
            float4 a0 = *(const float4*)&As[k][ty * 4];
            float4 a1 = *(const float4*)&As[k][64 + ty * 4];
            float4 b0 = *(const float4*)&Bs[k][tx * 4];
            float4 b1 = *(const float4*)&Bs[k][64 + tx * 4];
            float a[8] = {a0.x, a0.y, a0.z, a0.w, a1.x, a1.y, a1.z, a1.w};
            float b[8] = {b0.x, b0.y, b0.z, b0.w, b1.x, b1.y, b1.z, b1.w};
#pragma unroll
            for (int i = 0; i < 8; ++i)
#pragma unroll
                for (int j = 0; j < 8; ++j) acc[i][j] += a[i] * b[j];
        }
        __syncthreads();
    }

    // ---- epilogue
    float badd[8];
    if (biasp) {
#pragma unroll
        for (int j = 0; j < 4; ++j) {
            badd[j]     = biasp[tx * 4 + j];
            badd[4 + j] = biasp[64 + tx * 4 + j];
        }
    } else {
#pragma unroll
        for (int j = 0; j < 8; ++j) badd[j] = 0.f;
    }

#pragma unroll
    for (int i = 0; i < 8; ++i) {
        int row = (i < 4) ? (ty * 4 + i) : (64 + ty * 4 + (i - 4));
        float4 o0 = make_float4(acc[i][0] + badd[0], acc[i][1] + badd[1],
                                acc[i][2] + badd[2], acc[i][3] + badd[3]);
        float4 o1 = make_float4(acc[i][4] + badd[4], acc[i][5] + badd[5],
                                acc[i][6] + badd[6], acc[i][7] + badd[7]);
        *(float4*)(C + (long)row * ldc + tx * 4)      = o0;
        *(float4*)(C + (long)row * ldc + 64 + tx * 4) = o1;
    }
}

// ---------------------------------------------------------------------------
// RMSNorm over rows of length 2048, in place:  y = x * rsqrt(mean(x^2)+eps) * g
// One block (256 threads) per row; each thread owns 2 float4.
// ---------------------------------------------------------------------------
__global__ __launch_bounds__(256)
void rmsnorm_kernel(float* __restrict__ buf, const float* __restrict__ g)
{
    float* row = buf + (long)blockIdx.x * C_DIM;
    const int t = threadIdx.x;
    float4 v0 = *(float4*)(row + t * 4);
    float4 v1 = *(float4*)(row + 1024 + t * 4);
    float ss = v0.x * v0.x + v0.y * v0.y + v0.z * v0.z + v0.w * v0.w
             + v1.x * v1.x + v1.y * v1.y + v1.z * v1.z + v1.w * v1.w;
#pragma unroll
    for (int o = 16; o > 0; o >>= 1) ss += __shfl_xor_sync(0xffffffffu, ss, o);

    __shared__ float ws[8];
    __shared__ float s_inv;
    if ((t & 31) == 0) ws[t >> 5] = ss;
    __syncthreads();
    if (t == 0) {
        float s = 0.f;
#pragma unroll
        for (int i = 0; i < 8; ++i) s += ws[i];
        s_inv = rsqrtf(s * (1.0f / C_DIM) + 1e-6f);
    }
    __syncthreads();
    const float inv = s_inv;

    float4 w0 = *(const float4*)(g + t * 4);
    float4 w1 = *(const float4*)(g + 1024 + t * 4);
    v0.x *= inv * w0.x; v0.y *= inv * w0.y; v0.z *= inv * w0.z; v0.w *= inv * w0.w;
    v1.x *= inv * w1.x; v1.y *= inv * w1.y; v1.z *= inv * w1.z; v1.w *= inv * w1.w;
    *(float4*)(row + t * 4)        = v0;
    *(float4*)(row + 1024 + t * 4) = v1;
}

// ---------------------------------------------------------------------------
// Softmax over rows of length 512, in place, with 1/sqrt(128) pre-scale.
// One block (128 threads) per row; each thread owns one float4.
// ---------------------------------------------------------------------------
__global__ __launch_bounds__(128)
void softmax_kernel(float* __restrict__ sc)
{
    const float scale = 0.08838834764831845f;   // 1/sqrt(128)
    float* row = sc + (long)blockIdx.x * S_KV;
    const int t = threadIdx.x;

    float4 v = *(float4*)(row + t * 4);
    v.x *= scale; v.y *= scale; v.z *= scale; v.w *= scale;

    float m = fmaxf(fmaxf(v.x, v.y), fmaxf(v.z, v.w));
#pragma unroll
    for (int o = 16; o > 0; o >>= 1)
        m = fmaxf(m, __shfl_xor_sync(0xffffffffu, m, o));

    __shared__ float wm[4];
    __shared__ float ws[4];
    if ((t & 31) == 0) wm[t >> 5] = m;
    __syncthreads();
    m = fmaxf(fmaxf(wm[0], wm[1]), fmaxf(wm[2], wm[3]));

    float e0 = expf(v.x - m), e1 = expf(v.y - m);
    float e2 = expf(v.z - m), e3 = expf(v.w - m);
    float s = e0 + e1 + e2 + e3;
#pragma unroll
    for (int o = 16; o > 0; o >>= 1) s += __shfl_xor_sync(0xffffffffu, s, o);
    if ((t & 31) == 0) ws[t >> 5] = s;
    __syncthreads();
    s = ws[0] + ws[1] + ws[2] + ws[3];
    const float inv = 1.0f / s;

    *(float4*)(row + t * 4) = make_float4(e0 * inv, e1 * inv, e2 * inv, e3 * inv);
}

// ---------------------------------------------------------------------------
extern "C" void kernel_launch(void* const* d_in, const int* in_sizes, int n_in,
                              void* d_out, int out_size)
{
    (void)in_sizes; (void)n_in; (void)out_size;
    const float* x   = (const float*)d_in[0];
    const float* ctx = (const float*)d_in[1];
    const float* Wq  = (const float*)d_in[2];
    const float* bq  = (const float*)d_in[3];
    const float* Wk  = (const float*)d_in[4];
    const float* bk  = (const float*)d_in[5];
    const float* Wv  = (const float*)d_in[6];
    const float* bv  = (const float*)d_in[7];
    const float* Wo  = (const float*)d_in[8];
    const float* bo  = (const float*)d_in[9];
    const float* gq  = (const float*)d_in[10];
    const float* gk  = (const float*)d_in[11];
    float* out = (float*)d_out;

    float *qb, *kb, *vb, *sc, *at;
    cudaGetSymbolAddress((void**)&qb, g_qbuf);
    cudaGetSymbolAddress((void**)&kb, g_kbuf);
    cudaGetSymbolAddress((void**)&vb, g_vbuf);
    cudaGetSymbolAddress((void**)&sc, g_scores);
    cudaGetSymbolAddress((void**)&at, g_attn);

    // 1) Q = x @ Wq + bq            (8192 x 2048 x 2048)
    sgemm_kernel<false><<<dim3(16, 64, 1), 256>>>(
        x, C_DIM, 0, Wq, C_DIM, 0, bq, qb, C_DIM, 0, C_DIM);
    // 2) K = ctx @ Wk + bk          (512 x 2048 x 4096)
    sgemm_kernel<false><<<dim3(16, 4, 1), 256>>>(
        ctx, CTXD, 0, Wk, C_DIM, 0, bk, kb, C_DIM, 0, CTXD);
    // 3) V = ctx @ Wv + bv
    sgemm_kernel<false><<<dim3(16, 4, 1), 256>>>(
        ctx, CTXD, 0, Wv, C_DIM, 0, bv, vb, C_DIM, 0, CTXD);
    // 4) RMSNorm(Q) * g_q, RMSNorm(K) * g_k  (in place)
    rmsnorm_kernel<<<L_Q, 256>>>(qb, gq);
    rmsnorm_kernel<<<S_KV, 256>>>(kb, gk);
    // 5) scores[h] = Q_h @ K_h^T    (per head: 8192 x 512 x 128, B col-major)
    sgemm_kernel<true><<<dim3(4, 64, NH), 256>>>(
        qb, C_DIM, HD, kb, C_DIM, HD, nullptr,
        sc, S_KV, (long)L_Q * S_KV, HD);
    // 6) softmax rows (scale folded in)
    softmax_kernel<<<NH * L_Q, 128>>>(sc);
    // 7) attn[h] = P_h @ V_h        (per head: 8192 x 128 x 512)
    sgemm_kernel<false><<<dim3(1, 64, NH), 256>>>(
        sc, S_KV, (long)L_Q * S_KV, vb, C_DIM, HD, nullptr,
        at, C_DIM, HD, S_KV);
    // 8) out = attn @ Wo + bo       (8192 x 2048 x 2048)
    sgemm_kernel<false><<<dim3(16, 64, 1), 256>>>(
        at, C_DIM, 0, Wo, C_DIM, 0, bo, out, C_DIM, 0, C_DIM);
}

// round 3
// speedup vs baseline: 2.3017x; 2.3017x over previous
#include <cuda_runtime.h>
#include <cuda_bf16.h>
#include <cstdint>
#include <math.h>

// ===========================================================================
// WanCrossAttention  (B=1, L=8192, S=512, C=2048, CTX=4096, H=16, D=128)
// Round-3: bf16 hi/lo split GEMMs on mma.sync.m16n8k16 (sm_100 base target;
// tcgen05 is rejected by this harness's PTX target). 4-stage cp.async pipe.
// ===========================================================================

#define L_Q   8192
#define S_KV  512
#define C_DIM 2048
#define CTXD  4096
#define NH    16
#define HD    128

// GEMM tiling
#define TM 128
#define TN 128
#define TK 32
#define RSB 80                       // padded row stride (bytes) in smem
#define MATB (128 * RSB)             // 10240 B per matrix tile
#define STGB (4 * MATB)              // 40960 B per stage (Ah, Al, Bh, Bl)
#define NSTAGE 4
#define SMSZ (NSTAGE * STGB)         // 163840

// ---------------- scratch (device globals; no allocation allowed) ----------
__device__ float g_qf[L_Q * C_DIM];
__device__ float g_kf[S_KV * C_DIM];
__device__ float g_vtf[C_DIM * S_KV];
__device__ float g_scf[NH * L_Q * S_KV];
__device__ float g_atf[L_Q * C_DIM];

__device__ __nv_bfloat16 g_xh[L_Q * C_DIM],  g_xl[L_Q * C_DIM];
__device__ __nv_bfloat16 g_ch[S_KV * CTXD],  g_cl[S_KV * CTXD];
__device__ __nv_bfloat16 g_wqh[C_DIM * C_DIM], g_wql[C_DIM * C_DIM];
__device__ __nv_bfloat16 g_wkh[C_DIM * CTXD],  g_wkl[C_DIM * CTXD];
__device__ __nv_bfloat16 g_wvh[C_DIM * CTXD],  g_wvl[C_DIM * CTXD];
__device__ __nv_bfloat16 g_woh[C_DIM * C_DIM], g_wol[C_DIM * C_DIM];
__device__ __nv_bfloat16 g_qh[L_Q * C_DIM],  g_ql[L_Q * C_DIM];
__device__ __nv_bfloat16 g_kh[S_KV * C_DIM], g_kl[S_KV * C_DIM];
__device__ __nv_bfloat16 g_vth[C_DIM * S_KV], g_vtl[C_DIM * S_KV];
__device__ __nv_bfloat16 g_ph[NH * L_Q * S_KV], g_pl[NH * L_Q * S_KV];
__device__ __nv_bfloat16 g_ah[L_Q * C_DIM],  g_al[L_Q * C_DIM];

// ---------------- asm helpers ----------------------------------------------
__device__ __forceinline__ uint32_t smem_u32(const void* p) {
    uint32_t a;
    asm("{ .reg .u64 t; cvta.to.shared.u64 t, %1; cvt.u32.u64 %0, t; }"
        : "=r"(a) : "l"(p));
    return a;
}
__device__ __forceinline__ void ldsm4(uint32_t* r, uint32_t a) {
    asm volatile("ldmatrix.sync.aligned.m8n8.x4.shared.b16 {%0,%1,%2,%3}, [%4];"
                 : "=r"(r[0]), "=r"(r[1]), "=r"(r[2]), "=r"(r[3]) : "r"(a));
}
__device__ __forceinline__ void mma16816(float* c, const uint32_t* a,
                                         uint32_t b0, uint32_t b1) {
    asm volatile(
        "mma.sync.aligned.m16n8k16.row.col.f32.bf16.bf16.f32 "
        "{%0,%1,%2,%3}, {%4,%5,%6,%7}, {%8,%9}, {%0,%1,%2,%3};"
        : "+f"(c[0]), "+f"(c[1]), "+f"(c[2]), "+f"(c[3])
        : "r"(a[0]), "r"(a[1]), "r"(a[2]), "r"(a[3]), "r"(b0), "r"(b1));
}
#define CP_ASYNC16(dst, src) \
    asm volatile("cp.async.cg.shared.global [%0], [%1], 16;" :: "r"(dst), "l"(src))
#define CP_COMMIT() asm volatile("cp.async.commit_group;" ::: "memory")
#define CP_WAIT2()  asm volatile("cp.async.wait_group 2;" ::: "memory")

// ---------------------------------------------------------------------------
// bf16-split GEMM via mma.sync:
//   C[z][m][n] = sum_k (Ahi+Alo)[m,k] * (Bhi+Blo)[n,k]   (+ bias)
// A: [M,K] row-major (lda), per-z stride sA. B: [N,K] row-major (ldb), per-z sB.
// BIASMODE: 0 none, 1 per-column (bias[n]), 2 per-row (bias[m]).
// M%128==0, N%128==0, K%32==0, K/32 >= 3 required.
// ---------------------------------------------------------------------------
template <int BIASMODE>
__global__ __launch_bounds__(256, 1)
void mma_gemm(const __nv_bfloat16* __restrict__ Ahi, const __nv_bfloat16* __restrict__ Alo,
              int lda, long sA,
              const __nv_bfloat16* __restrict__ Bhi, const __nv_bfloat16* __restrict__ Blo,
              int ldb, long sB,
              const float* __restrict__ bias,
              float* __restrict__ C, int ldc, long sC, int K)
{
    extern __shared__ char smem[];
    const uint32_t sb = smem_u32(smem);
    const int tid = threadIdx.x, wid = tid >> 5, lid = tid & 31;
    const int m0 = blockIdx.y * TM, n0 = blockIdx.x * TN;

    // ---- loader geometry: 2048 16B-chunks per stage, 8 per thread ----------
    const __nv_bfloat16* baseM[4];
    baseM[0] = Ahi + (long)blockIdx.z * sA + (long)m0 * lda;
    baseM[1] = Alo + (long)blockIdx.z * sA + (long)m0 * lda;
    baseM[2] = Bhi + (long)blockIdx.z * sB + (long)n0 * ldb;
    baseM[3] = Blo + (long)blockIdx.z * sB + (long)n0 * ldb;

    const char* gp[8];
    uint32_t so[8];
#pragma unroll
    for (int i = 0; i < 8; ++i) {
        const int mat = i >> 1;
        const int row = (((i & 1) << 8) + tid) >> 2;   // 0..127
        const int kc  = tid & 3;                       // 16B chunk in row
        const int ld  = (mat < 2) ? lda : ldb;
        gp[i] = (const char*)(baseM[mat] + (long)row * ld + kc * 8);
        so[i] = (uint32_t)(mat * MATB + row * RSB + kc * 16);
    }

#define ISSUE_STAGE(stage, kidx) do {                                  \
        const uint32_t _db = sb + (uint32_t)(stage) * STGB;            \
        const long _go = (long)(kidx) * (TK * 2);                      \
        _Pragma("unroll")                                              \
        for (int _i = 0; _i < 8; ++_i)                                 \
            CP_ASYNC16(_db + so[_i], gp[_i] + _go);                    \
    } while (0)

    // ---- compute-side lane offsets -----------------------------------------
    const int wm = wid >> 2, wn = wid & 3;             // 2 x 4 warp grid
    const uint32_t offA = (uint32_t)((wm * 64 + (lid & 7) + ((lid >> 3) & 1) * 8) * RSB
                                     + ((lid >> 4) * 8) * 2);
    const uint32_t offB = (uint32_t)((wn * 32 + (lid & 7) + ((lid >> 4) & 1) * 8) * RSB
                                     + (((lid >> 3) & 1) * 8) * 2);

    float acc[4][4][4];
#pragma unroll
    for (int i = 0; i < 4; ++i)
#pragma unroll
        for (int j = 0; j < 4; ++j)
#pragma unroll
            for (int q = 0; q < 4; ++q) acc[i][j][q] = 0.f;

    const int nch = K / TK;

    ISSUE_STAGE(0, 0); CP_COMMIT();
    ISSUE_STAGE(1, 1); CP_COMMIT();
    ISSUE_STAGE(2, 2); CP_COMMIT();

    for (int c = 0; c < nch; ++c) {
        CP_WAIT2();
        __syncthreads();
        if (c + 3 < nch) ISSUE_STAGE((c + 3) & 3, c + 3);
        CP_COMMIT();

        const uint32_t stg = sb + (uint32_t)(c & 3) * STGB;
#pragma unroll
        for (int kb = 0; kb < 2; ++kb) {
            const uint32_t koff = kb * 32;       // 16 bf16 = 32 bytes
            uint32_t Ah[4][4], Al[4][4], Bh[2][4], Bl[2][4];
#pragma unroll
            for (int mt = 0; mt < 4; ++mt) {
                ldsm4(Ah[mt], stg + offA + mt * (16 * RSB) + koff);
                ldsm4(Al[mt], stg + MATB + offA + mt * (16 * RSB) + koff);
            }
#pragma unroll
            for (int p = 0; p < 2; ++p) {
                ldsm4(Bh[p], stg + 2 * MATB + offB + p * (16 * RSB) + koff);
                ldsm4(Bl[p], stg + 3 * MATB + offB + p * (16 * RSB) + koff);
            }
#pragma unroll
            for (int mt = 0; mt < 4; ++mt)
#pragma unroll
                for (int nt = 0; nt < 4; ++nt) {
                    const int p = nt >> 1, e = (nt & 1) * 2;
                    mma16816(acc[mt][nt], Ah[mt], Bh[p][e], Bh[p][e + 1]);
                    mma16816(acc[mt][nt], Ah[mt], Bl[p][e], Bl[p][e + 1]);
                    mma16816(acc[mt][nt], Al[mt], Bh[p][e], Bh[p][e + 1]);
                }
        }
    }
#undef ISSUE_STAGE

    // ---- epilogue ----------------------------------------------------------
    float* Cp = C + (long)blockIdx.z * sC;
    const int row_base = m0 + wm * 64;
    const int col_base = n0 + wn * 32;
    const int lr = lid >> 2, lc = (lid & 3) * 2;
#pragma unroll
    for (int mt = 0; mt < 4; ++mt) {
        const int r0 = row_base + mt * 16 + lr;
        const float rbA = (BIASMODE == 2) ? bias[r0] : 0.f;
        const float rbB = (BIASMODE == 2) ? bias[r0 + 8] : 0.f;
#pragma unroll
        for (int nt = 0; nt < 4; ++nt) {
            const int cix = col_base + nt * 8 + lc;
            float b0 = 0.f, b1 = 0.f;
            if (BIASMODE == 1) { b0 = bias[cix]; b1 = bias[cix + 1]; }
            float2* p0 = (float2*)(Cp + (long)r0 * ldc + cix);
            float2* p1 = (float2*)(Cp + (long)(r0 + 8) * ldc + cix);
            *p0 = make_float2(acc[mt][nt][0] + b0 + rbA, acc[mt][nt][1] + b1 + rbA);
            *p1 = make_float2(acc[mt][nt][2] + b0 + rbB, acc[mt][nt][3] + b1 + rbB);
        }
    }
}

// ---------------------------------------------------------------------------
// bf16 split helpers
// ---------------------------------------------------------------------------
__device__ __forceinline__ void split1(float v, __nv_bfloat16& h, __nv_bfloat16& l) {
    h = __float2bfloat16(v);
    l = __float2bfloat16(v - __bfloat162float(h));
}
__device__ __forceinline__ uint32_t pk(__nv_bfloat16 a, __nv_bfloat16 b) {
    __nv_bfloat162 t; t.x = a; t.y = b;
    return *(uint32_t*)&t;
}

__global__ __launch_bounds__(256)
void split_kernel(const float* __restrict__ src, __nv_bfloat16* __restrict__ hi,
                  __nv_bfloat16* __restrict__ lo)
{
    long i = ((long)blockIdx.x * 256 + threadIdx.x) * 4;
    float4 v = *(const float4*)(src + i);
    __nv_bfloat16 h0, h1, h2, h3, l0, l1, l2, l3;
    split1(v.x, h0, l0); split1(v.y, h1, l1); split1(v.z, h2, l2); split1(v.w, h3, l3);
    *(uint2*)(hi + i) = make_uint2(pk(h0, h1), pk(h2, h3));
    *(uint2*)(lo + i) = make_uint2(pk(l0, l1), pk(l2, l3));
}

__global__ __launch_bounds__(256)
void splitT_kernel(const float* __restrict__ W, __nv_bfloat16* __restrict__ hiT,
                   __nv_bfloat16* __restrict__ loT, int Kd, int Nd)
{
    __shared__ float t[32][33];
    const int k0 = blockIdx.y * 32, n0 = blockIdx.x * 32;
    const int tx = threadIdx.x & 31, ty = threadIdx.x >> 5;
#pragma unroll
    for (int r = 0; r < 4; ++r)
        t[ty + 8 * r][tx] = W[(long)(k0 + ty + 8 * r) * Nd + n0 + tx];
    __syncthreads();
#pragma unroll
    for (int r = 0; r < 4; ++r) {
        float v = t[tx][ty + 8 * r];
        __nv_bfloat16 h, l; split1(v, h, l);
        long o = (long)(n0 + ty + 8 * r) * Kd + k0 + tx;
        hiT[o] = h; loT[o] = l;
    }
}

__global__ __launch_bounds__(256)
void rmsnorm_split_kernel(const float* __restrict__ in, const float* __restrict__ g,
                          __nv_bfloat16* __restrict__ hi, __nv_bfloat16* __restrict__ lo)
{
    const float* row = in + (long)blockIdx.x * C_DIM;
    const int t = threadIdx.x;
    float4 v0 = *(const float4*)(row + t * 4);
    float4 v1 = *(const float4*)(row + 1024 + t * 4);
    float ss = v0.x * v0.x + v0.y * v0.y + v0.z * v0.z + v0.w * v0.w
             + v1.x * v1.x + v1.y * v1.y + v1.z * v1.z + v1.w * v1.w;
#pragma unroll
    for (int o = 16; o > 0; o >>= 1) ss += __shfl_xor_sync(0xffffffffu, ss, o);
    __shared__ float ws[8]; __shared__ float s_inv;
    if ((t & 31) == 0) ws[t >> 5] = ss;
    __syncthreads();
    if (t == 0) {
        float s = 0.f;
#pragma unroll
        for (int i = 0; i < 8; ++i) s += ws[i];
        s_inv = rsqrtf(s * (1.0f / C_DIM) + 1e-6f);
    }
    __syncthreads();
    const float inv = s_inv;
    float4 w0 = *(const float4*)(g + t * 4);
    float4 w1 = *(const float4*)(g + 1024 + t * 4);
    float o0[4] = {v0.x * inv * w0.x, v0.y * inv * w0.y, v0.z * inv * w0.z, v0.w * inv * w0.w};
    float o1[4] = {v1.x * inv * w1.x, v1.y * inv * w1.y, v1.z * inv * w1.z, v1.w * inv * w1.w};
    __nv_bfloat16 h[8], l[8];
#pragma unroll
    for (int i = 0; i < 4; ++i) { split1(o0[i], h[i], l[i]); split1(o1[i], h[4 + i], l[4 + i]); }
    long base = (long)blockIdx.x * C_DIM;
    *(uint2*)(hi + base + t * 4)        = make_uint2(pk(h[0], h[1]), pk(h[2], h[3]));
    *(uint2*)(hi + base + 1024 + t * 4) = make_uint2(pk(h[4], h[5]), pk(h[6], h[7]));
    *(uint2*)(lo + base + t * 4)        = make_uint2(pk(l[0], l[1]), pk(l[2], l[3]));
    *(uint2*)(lo + base + 1024 + t * 4) = make_uint2(pk(l[4], l[5]), pk(l[6], l[7]));
}

__global__ __launch_bounds__(128)
void softmax_split_kernel(const float* __restrict__ sc, __nv_bfloat16* __restrict__ Ph,
                          __nv_bfloat16* __restrict__ Pl)
{
    const float scale = 0.08838834764831845f;
    const float* row = sc + (long)blockIdx.x * S_KV;
    const int t = threadIdx.x;
    float4 v = *(const float4*)(row + t * 4);
    v.x *= scale; v.y *= scale; v.z *= scale; v.w *= scale;
    float m = fmaxf(fmaxf(v.x, v.y), fmaxf(v.z, v.w));
#pragma unroll
    for (int o = 16; o > 0; o >>= 1) m = fmaxf(m, __shfl_xor_sync(0xffffffffu, m, o));
    __shared__ float wm[4]; __shared__ float wsum[4];
    if ((t & 31) == 0) wm[t >> 5] = m;
    __syncthreads();
    m = fmaxf(fmaxf(wm[0], wm[1]), fmaxf(wm[2], wm[3]));
    float e0 = expf(v.x - m), e1 = expf(v.y - m), e2 = expf(v.z - m), e3 = expf(v.w - m);
    float s = e0 + e1 + e2 + e3;
#pragma unroll
    for (int o = 16; o > 0; o >>= 1) s += __shfl_xor_sync(0xffffffffu, s, o);
    if ((t & 31) == 0) wsum[t >> 5] = s;
    __syncthreads();
    s = wsum[0] + wsum[1] + wsum[2] + wsum[3];
    const float inv = 1.0f / s;
    float p0 = e0 * inv, p1 = e1 * inv, p2 = e2 * inv, p3 = e3 * inv;
    __nv_bfloat16 h0, h1, h2, h3, l0, l1, l2, l3;
    split1(p0, h0, l0); split1(p1, h1, l1); split1(p2, h2, l2); split1(p3, h3, l3);
    long base = (long)blockIdx.x * S_KV;
    *(uint2*)(Ph + base + t * 4) = make_uint2(pk(h0, h1), pk(h2, h3));
    *(uint2*)(Pl + base + t * 4) = make_uint2(pk(l0, l1), pk(l2, l3));
}

// ---------------------------------------------------------------------------
extern "C" void kernel_launch(void* const* d_in, const int* in_sizes, int n_in,
                              void* d_out, int out_size)
{
    (void)in_sizes; (void)n_in; (void)out_size;
    const float* x   = (const float*)d_in[0];
    const float* ctx = (const float*)d_in[1];
    const float* Wq  = (const float*)d_in[2];
    const float* bq  = (const float*)d_in[3];
    const float* Wk  = (const float*)d_in[4];
    const float* bk  = (const float*)d_in[5];
    const float* Wv  = (const float*)d_in[6];
    const float* bv  = (const float*)d_in[7];
    const float* Wo  = (const float*)d_in[8];
    const float* bo  = (const float*)d_in[9];
    const float* gq  = (const float*)d_in[10];
    const float* gk  = (const float*)d_in[11];
    float* out = (float*)d_out;

    cudaFuncSetAttribute(mma_gemm<0>, cudaFuncAttributeMaxDynamicSharedMemorySize, SMSZ);
    cudaFuncSetAttribute(mma_gemm<1>, cudaFuncAttributeMaxDynamicSharedMemorySize, SMSZ);
    cudaFuncSetAttribute(mma_gemm<2>, cudaFuncAttributeMaxDynamicSharedMemorySize, SMSZ);

    float *qf, *kf, *vtf, *scf, *atf;
    __nv_bfloat16 *xh, *xl, *ch, *cl, *wqh, *wql, *wkh, *wkl, *wvh, *wvl, *woh, *wol;
    __nv_bfloat16 *qh, *ql, *kh, *kl, *vth, *vtl, *Ph, *Pl, *ah, *al;
    cudaGetSymbolAddress((void**)&qf,  g_qf);
    cudaGetSymbolAddress((void**)&kf,  g_kf);
    cudaGetSymbolAddress((void**)&vtf, g_vtf);
    cudaGetSymbolAddress((void**)&scf, g_scf);
    cudaGetSymbolAddress((void**)&atf, g_atf);
    cudaGetSymbolAddress((void**)&xh,  g_xh);  cudaGetSymbolAddress((void**)&xl, g_xl);
    cudaGetSymbolAddress((void**)&ch,  g_ch);  cudaGetSymbolAddress((void**)&cl, g_cl);
    cudaGetSymbolAddress((void**)&wqh, g_wqh); cudaGetSymbolAddress((void**)&wql, g_wql);
    cudaGetSymbolAddress((void**)&wkh, g_wkh); cudaGetSymbolAddress((void**)&wkl, g_wkl);
    cudaGetSymbolAddress((void**)&wvh, g_wvh); cudaGetSymbolAddress((void**)&wvl, g_wvl);
    cudaGetSymbolAddress((void**)&woh, g_woh); cudaGetSymbolAddress((void**)&wol, g_wol);
    cudaGetSymbolAddress((void**)&qh,  g_qh);  cudaGetSymbolAddress((void**)&ql, g_ql);
    cudaGetSymbolAddress((void**)&kh,  g_kh);  cudaGetSymbolAddress((void**)&kl, g_kl);
    cudaGetSymbolAddress((void**)&vth, g_vth); cudaGetSymbolAddress((void**)&vtl, g_vtl);
    cudaGetSymbolAddress((void**)&Ph,  g_ph);  cudaGetSymbolAddress((void**)&Pl, g_pl);
    cudaGetSymbolAddress((void**)&ah,  g_ah);  cudaGetSymbolAddress((void**)&al, g_al);

    // ---- input conversions -------------------------------------------------
    split_kernel<<<(L_Q * C_DIM) / 1024, 256>>>(x, xh, xl);
    split_kernel<<<(S_KV * CTXD) / 1024, 256>>>(ctx, ch, cl);
    splitT_kernel<<<dim3(C_DIM / 32, C_DIM / 32), 256>>>(Wq, wqh, wql, C_DIM, C_DIM);
    splitT_kernel<<<dim3(C_DIM / 32, CTXD / 32), 256>>>(Wk, wkh, wkl, CTXD, C_DIM);
    splitT_kernel<<<dim3(C_DIM / 32, CTXD / 32), 256>>>(Wv, wvh, wvl, CTXD, C_DIM);
    splitT_kernel<<<dim3(C_DIM / 32, C_DIM / 32), 256>>>(Wo, woh, wol, C_DIM, C_DIM);

    // ---- projections -------------------------------------------------------
    // q = x @ Wq + bq        M=8192 N=2048 K=2048
    mma_gemm<1><<<dim3(16, 64, 1), 256, SMSZ>>>(xh, xl, C_DIM, 0, wqh, wql, C_DIM, 0,
                                                bq, qf, C_DIM, 0, C_DIM);
    // k = ctx @ Wk + bk      M=512 N=2048 K=4096
    mma_gemm<1><<<dim3(16, 4, 1), 256, SMSZ>>>(ch, cl, CTXD, 0, wkh, wkl, CTXD, 0,
                                               bk, kf, C_DIM, 0, CTXD);
    // V^T = Wv^T @ ctx^T + bv(row)   M=2048 N=512 K=4096
    mma_gemm<2><<<dim3(4, 16, 1), 256, SMSZ>>>(wvh, wvl, CTXD, 0, ch, cl, CTXD, 0,
                                               bv, vtf, S_KV, 0, CTXD);

    // ---- norms + splits ----------------------------------------------------
    rmsnorm_split_kernel<<<L_Q, 256>>>(qf, gq, qh, ql);
    rmsnorm_split_kernel<<<S_KV, 256>>>(kf, gk, kh, kl);
    split_kernel<<<(C_DIM * S_KV) / 1024, 256>>>(vtf, vth, vtl);

    // ---- attention ---------------------------------------------------------
    // scores[h] = Q_h @ K_h^T   M=8192 N=512 K=128
    mma_gemm<0><<<dim3(4, 64, NH), 256, SMSZ>>>(qh, ql, C_DIM, HD, kh, kl, C_DIM, HD,
                                                nullptr, scf, S_KV, (long)L_Q * S_KV, HD);
    softmax_split_kernel<<<NH * L_Q, 128>>>(scf, Ph, Pl);
    // attn[h] = P_h @ V_h       M=8192 N=128 K=512
    mma_gemm<0><<<dim3(1, 64, NH), 256, SMSZ>>>(Ph, Pl, S_KV, (long)L_Q * S_KV,
                                                vth, vtl, S_KV, (long)HD * S_KV,
                                                nullptr, atf, C_DIM, HD, S_KV);

    // ---- output projection -------------------------------------------------
    split_kernel<<<(L_Q * C_DIM) / 1024, 256>>>(atf, ah, al);
    mma_gemm<1><<<dim3(16, 64, 1), 256, SMSZ>>>(ah, al, C_DIM, 0, woh, wol, C_DIM, 0,
                                                bo, out, C_DIM, 0, C_DIM);
}

// round 5
// speedup vs baseline: 2.3413x; 1.0172x over previous
#include <cuda_runtime.h>
#include <cuda_bf16.h>
#include <cstdint>
#include <math.h>

// ===========================================================================
// WanCrossAttention  (B=1, L=8192, S=512, C=2048, CTX=4096, H=16, D=128)
// Round-5 (= Round-4 resubmit; prior bench died to container infra failure):
//  - bf16 hi/lo split GEMMs on mma.sync.m16n8k16
//  - K+V projections merged into one z=2 launch (128 CTAs, was 2x64 serial)
//  - Q-proj / O-proj on a 128x256-tile variant (better mma:ldsm, less L2)
// ===========================================================================

#define L_Q   8192
#define S_KV  512
#define C_DIM 2048
#define CTXD  4096
#define NH    16
#define HD    128

// 128x128 kernel tiling
#define TM 128
#define TN 128
#define TK 32
#define RSB 80                       // padded row stride (bytes) in smem
#define MATB (128 * RSB)             // 10240 B per matrix tile
#define STGB (4 * MATB)              // 40960 B per stage (Ah, Al, Bh, Bl)
#define NSTAGE 4
#define SMSZ (NSTAGE * STGB)         // 163840

// 128x256 kernel tiling (3 stages)
#define ATILE 10240                  // 128 rows * 80B
#define BTILE 20480                  // 256 rows * 80B
#define STG2B (2 * ATILE + 2 * BTILE)   // 61440
#define SMSZ2 (3 * STG2B)               // 184320

// ---------------- scratch (device globals; no allocation allowed) ----------
__device__ float g_qf[L_Q * C_DIM];
__device__ float g_kvf[2 * S_KV * C_DIM];            // [k | v] fp32
__device__ float g_scf[NH * L_Q * S_KV];
__device__ float g_atf[L_Q * C_DIM];
__device__ float g_bkv[2 * C_DIM];

__device__ __nv_bfloat16 g_xh[L_Q * C_DIM],  g_xl[L_Q * C_DIM];
__device__ __nv_bfloat16 g_ch[S_KV * CTXD],  g_cl[S_KV * CTXD];
__device__ __nv_bfloat16 g_wqh[C_DIM * C_DIM], g_wql[C_DIM * C_DIM];
__device__ __nv_bfloat16 g_wkvh[2 * C_DIM * CTXD], g_wkvl[2 * C_DIM * CTXD]; // [Wk^T|Wv^T]
__device__ __nv_bfloat16 g_woh[C_DIM * C_DIM], g_wol[C_DIM * C_DIM];
__device__ __nv_bfloat16 g_qh[L_Q * C_DIM],  g_ql[L_Q * C_DIM];
__device__ __nv_bfloat16 g_kh[S_KV * C_DIM], g_kl[S_KV * C_DIM];
__device__ __nv_bfloat16 g_vth[C_DIM * S_KV], g_vtl[C_DIM * S_KV];
__device__ __nv_bfloat16 g_ph[NH * L_Q * S_KV], g_pl[NH * L_Q * S_KV];
__device__ __nv_bfloat16 g_ah[L_Q * C_DIM],  g_al[L_Q * C_DIM];

// ---------------- asm helpers ----------------------------------------------
__device__ __forceinline__ uint32_t smem_u32(const void* p) {
    uint32_t a;
    asm("{ .reg .u64 t; cvta.to.shared.u64 t, %1; cvt.u32.u64 %0, t; }"
        : "=r"(a) : "l"(p));
    return a;
}
__device__ __forceinline__ void ldsm4(uint32_t* r, uint32_t a) {
    asm volatile("ldmatrix.sync.aligned.m8n8.x4.shared.b16 {%0,%1,%2,%3}, [%4];"
                 : "=r"(r[0]), "=r"(r[1]), "=r"(r[2]), "=r"(r[3]) : "r"(a));
}
__device__ __forceinline__ void mma16816(float* c, const uint32_t* a,
                                         uint32_t b0, uint32_t b1) {
    asm volatile(
        "mma.sync.aligned.m16n8k16.row.col.f32.bf16.bf16.f32 "
        "{%0,%1,%2,%3}, {%4,%5,%6,%7}, {%8,%9}, {%0,%1,%2,%3};"
        : "+f"(c[0]), "+f"(c[1]), "+f"(c[2]), "+f"(c[3])
        : "r"(a[0]), "r"(a[1]), "r"(a[2]), "r"(a[3]), "r"(b0), "r"(b1));
}
#define CP_ASYNC16(dst, src) \
    asm volatile("cp.async.cg.shared.global [%0], [%1], 16;" :: "r"(dst), "l"(src))
#define CP_COMMIT() asm volatile("cp.async.commit_group;" ::: "memory")
#define CP_WAIT2()  asm volatile("cp.async.wait_group 2;" ::: "memory")

// ---------------------------------------------------------------------------
// 128x128 bf16-split GEMM:
//   C[z][m][n] = sum_k (Ahi+Alo)[m,k] * (Bhi+Blo)[n,k]   (+ bias)
// BIASMODE: 0 none, 1 per-column (bias[n]), 2 per-row (bias[m]).
// M%128==0, N%128==0, K%32==0, K/32 >= 3.
// ---------------------------------------------------------------------------
template <int BIASMODE>
__global__ __launch_bounds__(256, 1)
void mma_gemm(const __nv_bfloat16* __restrict__ Ahi, const __nv_bfloat16* __restrict__ Alo,
              int lda, long sA,
              const __nv_bfloat16* __restrict__ Bhi, const __nv_bfloat16* __restrict__ Blo,
              int ldb, long sB,
              const float* __restrict__ bias, long sBias,
              float* __restrict__ C, int ldc, long sC, int K)
{
    extern __shared__ char smem[];
    const uint32_t sb = smem_u32(smem);
    const int tid = threadIdx.x, wid = tid >> 5, lid = tid & 31;
    const int m0 = blockIdx.y * TM, n0 = blockIdx.x * TN;

    if (BIASMODE != 0) bias += (long)blockIdx.z * sBias;

    const __nv_bfloat16* baseM[4];
    baseM[0] = Ahi + (long)blockIdx.z * sA + (long)m0 * lda;
    baseM[1] = Alo + (long)blockIdx.z * sA + (long)m0 * lda;
    baseM[2] = Bhi + (long)blockIdx.z * sB + (long)n0 * ldb;
    baseM[3] = Blo + (long)blockIdx.z * sB + (long)n0 * ldb;

    const char* gp[8];
    uint32_t so[8];
#pragma unroll
    for (int i = 0; i < 8; ++i) {
        const int mat = i >> 1;
        const int row = (((i & 1) << 8) + tid) >> 2;   // 0..127
        const int kc  = tid & 3;
        const int ld  = (mat < 2) ? lda : ldb;
        gp[i] = (const char*)(baseM[mat] + (long)row * ld + kc * 8);
        so[i] = (uint32_t)(mat * MATB + row * RSB + kc * 16);
    }

#define ISSUE_STAGE(stage, kidx) do {                                  \
        const uint32_t _db = sb + (uint32_t)(stage) * STGB;            \
        const long _go = (long)(kidx) * (TK * 2);                      \
        _Pragma("unroll")                                              \
        for (int _i = 0; _i < 8; ++_i)                                 \
            CP_ASYNC16(_db + so[_i], gp[_i] + _go);                    \
    } while (0)

    const int wm = wid >> 2, wn = wid & 3;
    const uint32_t offA = (uint32_t)((wm * 64 + (lid & 7) + ((lid >> 3) & 1) * 8) * RSB
                                     + ((lid >> 4) * 8) * 2);
    const uint32_t offB = (uint32_t)((wn * 32 + (lid & 7) + ((lid >> 4) & 1) * 8) * RSB
                                     + (((lid >> 3) & 1) * 8) * 2);

    float acc[4][4][4];
#pragma unroll
    for (int i = 0; i < 4; ++i)
#pragma unroll
        for (int j = 0; j < 4; ++j)
#pragma unroll
            for (int q = 0; q < 4; ++q) acc[i][j][q] = 0.f;

    const int nch = K / TK;

    ISSUE_STAGE(0, 0); CP_COMMIT();
    ISSUE_STAGE(1, 1); CP_COMMIT();
    ISSUE_STAGE(2, 2); CP_COMMIT();

    for (int c = 0; c < nch; ++c) {
        CP_WAIT2();
        __syncthreads();
        if (c + 3 < nch) ISSUE_STAGE((c + 3) & 3, c + 3);
        CP_COMMIT();

        const uint32_t stg = sb + (uint32_t)(c & 3) * STGB;
#pragma unroll
        for (int kb = 0; kb < 2; ++kb) {
            const uint32_t koff = kb * 32;
            uint32_t Ah[4][4], Al[4][4], Bh[2][4], Bl[2][4];
#pragma unroll
            for (int mt = 0; mt < 4; ++mt) {
                ldsm4(Ah[mt], stg + offA + mt * (16 * RSB) + koff);
                ldsm4(Al[mt], stg + MATB + offA + mt * (16 * RSB) + koff);
            }
#pragma unroll
            for (int p = 0; p < 2; ++p) {
                ldsm4(Bh[p], stg + 2 * MATB + offB + p * (16 * RSB) + koff);
                ldsm4(Bl[p], stg + 3 * MATB + offB + p * (16 * RSB) + koff);
            }
#pragma unroll
            for (int mt = 0; mt < 4; ++mt)
#pragma unroll
                for (int nt = 0; nt < 4; ++nt) {
                    const int p = nt >> 1, e = (nt & 1) * 2;
                    mma16816(acc[mt][nt], Ah[mt], Bh[p][e], Bh[p][e + 1]);
                    mma16816(acc[mt][nt], Ah[mt], Bl[p][e], Bl[p][e + 1]);
                    mma16816(acc[mt][nt], Al[mt], Bh[p][e], Bh[p][e + 1]);
                }
        }
    }
#undef ISSUE_STAGE

    float* Cp = C + (long)blockIdx.z * sC;
    const int row_base = m0 + wm * 64;
    const int col_base = n0 + wn * 32;
    const int lr = lid >> 2, lc = (lid & 3) * 2;
#pragma unroll
    for (int mt = 0; mt < 4; ++mt) {
        const int r0 = row_base + mt * 16 + lr;
        const float rbA = (BIASMODE == 2) ? bias[r0] : 0.f;
        const float rbB = (BIASMODE == 2) ? bias[r0 + 8] : 0.f;
#pragma unroll
        for (int nt = 0; nt < 4; ++nt) {
            const int cix = col_base + nt * 8 + lc;
            float b0 = 0.f, b1 = 0.f;
            if (BIASMODE == 1) { b0 = bias[cix]; b1 = bias[cix + 1]; }
            float2* p0 = (float2*)(Cp + (long)r0 * ldc + cix);
            float2* p1 = (float2*)(Cp + (long)(r0 + 8) * ldc + cix);
            *p0 = make_float2(acc[mt][nt][0] + b0 + rbA, acc[mt][nt][1] + b1 + rbA);
            *p1 = make_float2(acc[mt][nt][2] + b0 + rbB, acc[mt][nt][3] + b1 + rbB);
        }
    }
}

// ---------------------------------------------------------------------------
// 128x256 bf16-split GEMM, 3-stage pipeline (issue-after-compute).
// For the big M=8192, N=2048, K=2048 projections.  bias[n] only.
// ---------------------------------------------------------------------------
__global__ __launch_bounds__(256, 1)
void mma_gemm256(const __nv_bfloat16* __restrict__ Ahi, const __nv_bfloat16* __restrict__ Alo,
                 int lda,
                 const __nv_bfloat16* __restrict__ Bhi, const __nv_bfloat16* __restrict__ Blo,
                 int ldb,
                 const float* __restrict__ bias,
                 float* __restrict__ C, int ldc, int K)
{
    extern __shared__ char smem[];
    const uint32_t sb = smem_u32(smem);
    const int tid = threadIdx.x, wid = tid >> 5, lid = tid & 31;
    const int m0 = blockIdx.y * 128, n0 = blockIdx.x * 256;

    const __nv_bfloat16* A0 = Ahi + (long)m0 * lda;
    const __nv_bfloat16* A1 = Alo + (long)m0 * lda;
    const __nv_bfloat16* B0 = Bhi + (long)n0 * ldb;
    const __nv_bfloat16* B1 = Blo + (long)n0 * ldb;

#define ISSUE2(buf, kidx) do {                                                  \
        const uint32_t _db = sb + (uint32_t)(buf) * STG2B;                      \
        _Pragma("unroll")                                                       \
        for (int _i = 0; _i < 4; ++_i) {                                        \
            const int _idx = _i * 256 + tid;                                    \
            const int _mat = _idx >> 9, _row = (_idx >> 2) & 127, _kc = _idx & 3; \
            const __nv_bfloat16* _s = (_mat ? A1 : A0)                          \
                + (long)_row * lda + _kc * 8 + (long)(kidx) * 32;               \
            CP_ASYNC16(_db + _mat * ATILE + _row * RSB + _kc * 16, _s);         \
        }                                                                       \
        _Pragma("unroll")                                                       \
        for (int _i = 0; _i < 8; ++_i) {                                        \
            const int _idx = _i * 256 + tid;                                    \
            const int _mat = _idx >> 10, _row = (_idx >> 2) & 255, _kc = _idx & 3; \
            const __nv_bfloat16* _s = (_mat ? B1 : B0)                          \
                + (long)_row * ldb + _kc * 8 + (long)(kidx) * 32;               \
            CP_ASYNC16(_db + 2 * ATILE + _mat * BTILE + _row * RSB + _kc * 16, _s); \
        }                                                                       \
    } while (0)

    const int wm = wid >> 2, wn = wid & 3;           // 2 x 4 warps, warp 64x64
    const uint32_t offA = (uint32_t)((wm * 64 + (lid & 7) + ((lid >> 3) & 1) * 8) * RSB
                                     + (lid >> 4) * 16);
    const uint32_t offB = (uint32_t)((wn * 64 + (lid & 7) + ((lid >> 4) & 1) * 8) * RSB
                                     + ((lid >> 3) & 1) * 16);

    float acc[4][8][4];
#pragma unroll
    for (int i = 0; i < 4; ++i)
#pragma unroll
        for (int j = 0; j < 8; ++j)
#pragma unroll
            for (int q = 0; q < 4; ++q) acc[i][j][q] = 0.f;

    const int nch = K / 32;

    ISSUE2(0, 0); CP_COMMIT();
    ISSUE2(1, 1); CP_COMMIT();
    ISSUE2(2, 2); CP_COMMIT();

    for (int c = 0; c < nch; ++c) {
        CP_WAIT2();
        __syncthreads();

        const int buf = c % 3;
        const uint32_t stg = sb + (uint32_t)buf * STG2B;
#pragma unroll
        for (int kb = 0; kb < 2; ++kb) {
            const uint32_t koff = kb * 32;
            uint32_t Ah[4][4], Al[4][4];
#pragma unroll
            for (int mt = 0; mt < 4; ++mt) {
                ldsm4(Ah[mt], stg + offA + mt * (16 * RSB) + koff);
                ldsm4(Al[mt], stg + ATILE + offA + mt * (16 * RSB) + koff);
            }
#pragma unroll
            for (int nh = 0; nh < 4; ++nh) {
                uint32_t Bh[4], Bl[4];
                ldsm4(Bh, stg + 2 * ATILE + offB + nh * (16 * RSB) + koff);
                ldsm4(Bl, stg + 2 * ATILE + BTILE + offB + nh * (16 * RSB) + koff);
#pragma unroll
                for (int mt = 0; mt < 4; ++mt)
#pragma unroll
                    for (int s = 0; s < 2; ++s) {
                        const int e = s * 2;
                        float* a = acc[mt][nh * 2 + s];
                        mma16816(a, Ah[mt], Bh[e], Bh[e + 1]);
                        mma16816(a, Ah[mt], Bl[e], Bl[e + 1]);
                        mma16816(a, Al[mt], Bh[e], Bh[e + 1]);
                    }
            }
        }
        __syncthreads();
        if (c + 3 < nch) ISSUE2(buf, c + 3);
        CP_COMMIT();
    }
#undef ISSUE2

    const int row_base = m0 + wm * 64;
    const int col_base = n0 + wn * 64;
    const int lr = lid >> 2, lc = (lid & 3) * 2;
#pragma unroll
    for (int mt = 0; mt < 4; ++mt) {
        const int r0 = row_base + mt * 16 + lr;
#pragma unroll
        for (int nt = 0; nt < 8; ++nt) {
            const int cix = col_base + nt * 8 + lc;
            const float b0 = bias[cix], b1 = bias[cix + 1];
            float2* p0 = (float2*)(C + (long)r0 * ldc + cix);
            float2* p1 = (float2*)(C + (long)(r0 + 8) * ldc + cix);
            *p0 = make_float2(acc[mt][nt][0] + b0, acc[mt][nt][1] + b1);
            *p1 = make_float2(acc[mt][nt][2] + b0, acc[mt][nt][3] + b1);
        }
    }
}

// ---------------------------------------------------------------------------
// bf16 split helpers
// ---------------------------------------------------------------------------
__device__ __forceinline__ void split1(float v, __nv_bfloat16& h, __nv_bfloat16& l) {
    h = __float2bfloat16(v);
    l = __float2bfloat16(v - __bfloat162float(h));
}
__device__ __forceinline__ uint32_t pk(__nv_bfloat16 a, __nv_bfloat16 b) {
    __nv_bfloat162 t; t.x = a; t.y = b;
    return *(uint32_t*)&t;
}

__global__ __launch_bounds__(256)
void split_kernel(const float* __restrict__ src, __nv_bfloat16* __restrict__ hi,
                  __nv_bfloat16* __restrict__ lo)
{
    long i = ((long)blockIdx.x * 256 + threadIdx.x) * 4;
    float4 v = *(const float4*)(src + i);
    __nv_bfloat16 h0, h1, h2, h3, l0, l1, l2, l3;
    split1(v.x, h0, l0); split1(v.y, h1, l1); split1(v.z, h2, l2); split1(v.w, h3, l3);
    *(uint2*)(hi + i) = make_uint2(pk(h0, h1), pk(h2, h3));
    *(uint2*)(lo + i) = make_uint2(pk(l0, l1), pk(l2, l3));
}

__global__ __launch_bounds__(256)
void splitT_kernel(const float* __restrict__ W, __nv_bfloat16* __restrict__ hiT,
                   __nv_bfloat16* __restrict__ loT, int Kd, int Nd)
{
    __shared__ float t[32][33];
    const int k0 = blockIdx.y * 32, n0 = blockIdx.x * 32;
    const int tx = threadIdx.x & 31, ty = threadIdx.x >> 5;
#pragma unroll
    for (int r = 0; r < 4; ++r)
        t[ty + 8 * r][tx] = W[(long)(k0 + ty + 8 * r) * Nd + n0 + tx];
    __syncthreads();
#pragma unroll
    for (int r = 0; r < 4; ++r) {
        float v = t[tx][ty + 8 * r];
        __nv_bfloat16 h, l; split1(v, h, l);
        long o = (long)(n0 + ty + 8 * r) * Kd + k0 + tx;
        hiT[o] = h; loT[o] = l;
    }
}

__global__ void concat_bias_kernel(const float* __restrict__ bk,
                                   const float* __restrict__ bv,
                                   float* __restrict__ o)
{
    int i = blockIdx.x * 256 + threadIdx.x;
    o[i] = bk[i];
    o[C_DIM + i] = bv[i];
}

__global__ __launch_bounds__(256)
void rmsnorm_split_kernel(const float* __restrict__ in, const float* __restrict__ g,
                          __nv_bfloat16* __restrict__ hi, __nv_bfloat16* __restrict__ lo)
{
    const float* row = in + (long)blockIdx.x * C_DIM;
    const int t = threadIdx.x;
    float4 v0 = *(const float4*)(row + t * 4);
    float4 v1 = *(const float4*)(row + 1024 + t * 4);
    float ss = v0.x * v0.x + v0.y * v0.y + v0.z * v0.z + v0.w * v0.w
             + v1.x * v1.x + v1.y * v1.y + v1.z * v1.z + v1.w * v1.w;
#pragma unroll
    for (int o = 16; o > 0; o >>= 1) ss += __shfl_xor_sync(0xffffffffu, ss, o);
    __shared__ float ws[8]; __shared__ float s_inv;
    if ((t & 31) == 0) ws[t >> 5] = ss;
    __syncthreads();
    if (t == 0) {
        float s = 0.f;
#pragma unroll
        for (int i = 0; i < 8; ++i) s += ws[i];
        s_inv = rsqrtf(s * (1.0f / C_DIM) + 1e-6f);
    }
    __syncthreads();
    const float inv = s_inv;
    float4 w0 = *(const float4*)(g + t * 4);
    float4 w1 = *(const float4*)(g + 1024 + t * 4);
    float o0[4] = {v0.x * inv * w0.x, v0.y * inv * w0.y, v0.z * inv * w0.z, v0.w * inv * w0.w};
    float o1[4] = {v1.x * inv * w1.x, v1.y * inv * w1.y, v1.z * inv * w1.z, v1.w * inv * w1.w};
    __nv_bfloat16 h[8], l[8];
#pragma unroll
    for (int i = 0; i < 4; ++i) { split1(o0[i], h[i], l[i]); split1(o1[i], h[4 + i], l[4 + i]); }
    long base = (long)blockIdx.x * C_DIM;
    *(uint2*)(hi + base + t * 4)        = make_uint2(pk(h[0], h[1]), pk(h[2], h[3]));
    *(uint2*)(hi + base + 1024 + t * 4) = make_uint2(pk(h[4], h[5]), pk(h[6], h[7]));
    *(uint2*)(lo + base + t * 4)        = make_uint2(pk(l[0], l[1]), pk(l[2], l[3]));
    *(uint2*)(lo + base + 1024 + t * 4) = make_uint2(pk(l[4], l[5]), pk(l[6], l[7]));
}

__global__ __launch_bounds__(128)
void softmax_split_kernel(const float* __restrict__ sc, __nv_bfloat16* __restrict__ Ph,
                          __nv_bfloat16* __restrict__ Pl)
{
    const float scale = 0.08838834764831845f;
    const float* row = sc + (long)blockIdx.x * S_KV;
    const int t = threadIdx.x;
    float4 v = *(const float4*)(row + t * 4);
    v.x *= scale; v.y *= scale; v.z *= scale; v.w *= scale;
    float m = fmaxf(fmaxf(v.x, v.y), fmaxf(v.z, v.w));
#pragma unroll
    for (int o = 16; o > 0; o >>= 1) m = fmaxf(m, __shfl_xor_sync(0xffffffffu, m, o));
    __shared__ float wm[4]; __shared__ float wsum[4];
    if ((t & 31) == 0) wm[t >> 5] = m;
    __syncthreads();
    m = fmaxf(fmaxf(wm[0], wm[1]), fmaxf(wm[2], wm[3]));
    float e0 = expf(v.x - m), e1 = expf(v.y - m), e2 = expf(v.z - m), e3 = expf(v.w - m);
    float s = e0 + e1 + e2 + e3;
#pragma unroll
    for (int o = 16; o > 0; o >>= 1) s += __shfl_xor_sync(0xffffffffu, s, o);
    if ((t & 31) == 0) wsum[t >> 5] = s;
    __syncthreads();
    s = wsum[0] + wsum[1] + wsum[2] + wsum[3];
    const float inv = 1.0f / s;
    float p0 = e0 * inv, p1 = e1 * inv, p2 = e2 * inv, p3 = e3 * inv;
    __nv_bfloat16 h0, h1, h2, h3, l0, l1, l2, l3;
    split1(p0, h0, l0); split1(p1, h1, l1); split1(p2, h2, l2); split1(p3, h3, l3);
    long base = (long)blockIdx.x * S_KV;
    *(uint2*)(Ph + base + t * 4) = make_uint2(pk(h0, h1), pk(h2, h3));
    *(uint2*)(Pl + base + t * 4) = make_uint2(pk(l0, l1), pk(l2, l3));
}

// ---------------------------------------------------------------------------
extern "C" void kernel_launch(void* const* d_in, const int* in_sizes, int n_in,
                              void* d_out, int out_size)
{
    (void)in_sizes; (void)n_in; (void)out_size;
    const float* x   = (const float*)d_in[0];
    const float* ctx = (const float*)d_in[1];
    const float* Wq  = (const float*)d_in[2];
    const float* bq  = (const float*)d_in[3];
    const float* Wk  = (const float*)d_in[4];
    const float* bk  = (const float*)d_in[5];
    const float* Wv  = (const float*)d_in[6];
    const float* bv  = (const float*)d_in[7];
    const float* Wo  = (const float*)d_in[8];
    const float* bo  = (const float*)d_in[9];
    const float* gq  = (const float*)d_in[10];
    const float* gk  = (const float*)d_in[11];
    float* out = (float*)d_out;

    cudaFuncSetAttribute(mma_gemm<0>, cudaFuncAttributeMaxDynamicSharedMemorySize, SMSZ);
    cudaFuncSetAttribute(mma_gemm<1>, cudaFuncAttributeMaxDynamicSharedMemorySize, SMSZ);
    cudaFuncSetAttribute(mma_gemm256, cudaFuncAttributeMaxDynamicSharedMemorySize, SMSZ2);

    float *qf, *kvf, *scf, *atf, *bkv;
    __nv_bfloat16 *xh, *xl, *ch, *cl, *wqh, *wql, *wkvh, *wkvl, *woh, *wol;
    __nv_bfloat16 *qh, *ql, *kh, *kl, *vth, *vtl, *Ph, *Pl, *ah, *al;
    cudaGetSymbolAddress((void**)&qf,   g_qf);
    cudaGetSymbolAddress((void**)&kvf,  g_kvf);
    cudaGetSymbolAddress((void**)&scf,  g_scf);
    cudaGetSymbolAddress((void**)&atf,  g_atf);
    cudaGetSymbolAddress((void**)&bkv,  g_bkv);
    cudaGetSymbolAddress((void**)&xh,   g_xh);   cudaGetSymbolAddress((void**)&xl, g_xl);
    cudaGetSymbolAddress((void**)&ch,   g_ch);   cudaGetSymbolAddress((void**)&cl, g_cl);
    cudaGetSymbolAddress((void**)&wqh,  g_wqh);  cudaGetSymbolAddress((void**)&wql, g_wql);
    cudaGetSymbolAddress((void**)&wkvh, g_wkvh); cudaGetSymbolAddress((void**)&wkvl, g_wkvl);
    cudaGetSymbolAddress((void**)&woh,  g_woh);  cudaGetSymbolAddress((void**)&wol, g_wol);
    cudaGetSymbolAddress((void**)&qh,   g_qh);   cudaGetSymbolAddress((void**)&ql, g_ql);
    cudaGetSymbolAddress((void**)&kh,   g_kh);   cudaGetSymbolAddress((void**)&kl, g_kl);
    cudaGetSymbolAddress((void**)&vth,  g_vth);  cudaGetSymbolAddress((void**)&vtl, g_vtl);
    cudaGetSymbolAddress((void**)&Ph,   g_ph);   cudaGetSymbolAddress((void**)&Pl, g_pl);
    cudaGetSymbolAddress((void**)&ah,   g_ah);   cudaGetSymbolAddress((void**)&al, g_al);

    const long WKV = (long)C_DIM * CTXD;      // per-z weight stride
    const long SKV = (long)S_KV * C_DIM;      // per-z output stride

    // ---- input conversions -------------------------------------------------
    split_kernel<<<(L_Q * C_DIM) / 1024, 256>>>(x, xh, xl);
    split_kernel<<<(S_KV * CTXD) / 1024, 256>>>(ctx, ch, cl);
    splitT_kernel<<<dim3(C_DIM / 32, C_DIM / 32), 256>>>(Wq, wqh, wql, C_DIM, C_DIM);
    splitT_kernel<<<dim3(C_DIM / 32, CTXD / 32), 256>>>(Wk, wkvh, wkvl, CTXD, C_DIM);
    splitT_kernel<<<dim3(C_DIM / 32, CTXD / 32), 256>>>(Wv, wkvh + WKV, wkvl + WKV,
                                                        CTXD, C_DIM);
    splitT_kernel<<<dim3(C_DIM / 32, C_DIM / 32), 256>>>(Wo, woh, wol, C_DIM, C_DIM);
    concat_bias_kernel<<<C_DIM / 256, 256>>>(bk, bv, bkv);

    // ---- projections -------------------------------------------------------
    // q = x @ Wq + bq        M=8192 N=2048 K=2048   (128x256 tiles)
    mma_gemm256<<<dim3(8, 64, 1), 256, SMSZ2>>>(xh, xl, C_DIM, wqh, wql, C_DIM,
                                                bq, qf, C_DIM, C_DIM);
    // [k | v] = ctx @ [Wk | Wv] + [bk | bv]   merged z=2, 128 CTAs
    mma_gemm<1><<<dim3(16, 4, 2), 256, SMSZ>>>(ch, cl, CTXD, 0,
                                               wkvh, wkvl, CTXD, WKV,
                                               bkv, C_DIM,
                                               kvf, C_DIM, SKV, CTXD);

    // ---- norms + splits ----------------------------------------------------
    rmsnorm_split_kernel<<<L_Q, 256>>>(qf, gq, qh, ql);
    rmsnorm_split_kernel<<<S_KV, 256>>>(kvf, gk, kh, kl);
    // V^T split: v fp32 [512,2048] -> vth/vtl [2048,512]
    splitT_kernel<<<dim3(C_DIM / 32, S_KV / 32), 256>>>(kvf + SKV, vth, vtl, S_KV, C_DIM);

    // ---- attention ---------------------------------------------------------
    // scores[h] = Q_h @ K_h^T   M=8192 N=512 K=128
    mma_gemm<0><<<dim3(4, 64, NH), 256, SMSZ>>>(qh, ql, C_DIM, HD, kh, kl, C_DIM, HD,
                                                nullptr, 0,
                                                scf, S_KV, (long)L_Q * S_KV, HD);
    softmax_split_kernel<<<NH * L_Q, 128>>>(scf, Ph, Pl);
    // attn[h] = P_h @ V_h       M=8192 N=128 K=512
    mma_gemm<0><<<dim3(1, 64, NH), 256, SMSZ>>>(Ph, Pl, S_KV, (long)L_Q * S_KV,
                                                vth, vtl, S_KV, (long)HD * S_KV,
                                                nullptr, 0,
                                                atf, C_DIM, HD, S_KV);

    // ---- output projection -------------------------------------------------
    split_kernel<<<(L_Q * C_DIM) / 1024, 256>>>(atf, ah, al);
    mma_gemm256<<<dim3(8, 64, 1), 256, SMSZ2>>>(ah, al, C_DIM, woh, wol, C_DIM,
                                                bo, out, C_DIM, C_DIM);
}

// round 7
// speedup vs baseline: 3.0208x; 1.2902x over previous
#include <cuda_runtime.h>
#include <cstdint>
#include <math.h>

// ===========================================================================
// WanCrossAttention  (B=1, L=8192, S=512, C=2048, CTX=4096, H=16, D=128)
// Round-7 (= Round-6 resubmit; prior bench died to container infra failure):
// single-product TF32 GEMMs via mma.sync.m16n8k8.tf32.
//   All operands pre-rounded with cvt.rna.tf32.f32 (stored fp32) -> MMA exact.
//   1.5x less tensor-pipe work than the bf16 hi/lo 3-product scheme.
// ===========================================================================

#define L_Q   8192
#define S_KV  512
#define C_DIM 2048
#define CTXD  4096
#define NH    16
#define HD    128

// tf32 GEMM tiling: CTA 128x128, TK=32 fp32, 4-stage cp.async pipeline
#define RSF   36                     // smem row stride (floats): 32 + 4 pad
#define RSFB  144                    // bytes
#define MTB   (128 * RSFB)           // 18432 B per matrix tile
#define STGF  (2 * MTB)              // 36864 B per stage (A, B)
#define SMF   (4 * STGF)             // 147456 B

// ---------------- scratch (device globals; no allocation allowed) ----------
__device__ float g_xt[L_Q * C_DIM];                  // x, tf32-rounded
__device__ float g_ct[S_KV * CTXD];                  // ctx, tf32-rounded
__device__ float g_wqt[C_DIM * C_DIM];               // Wq^T rounded
__device__ float g_wkvt[2 * C_DIM * CTXD];           // [Wk^T | Wv^T] rounded
__device__ float g_wot[C_DIM * C_DIM];               // Wo^T rounded
__device__ float g_qf[L_Q * C_DIM];                  // q (raw -> rmsnorm in-place rounded)
__device__ float g_kvf[2 * S_KV * C_DIM];            // [k | v]
__device__ float g_vt[C_DIM * S_KV];                 // V^T rounded
__device__ float g_scf[NH * L_Q * S_KV];             // scores (softmax in-place rounded)
__device__ float g_atf[L_Q * C_DIM];                 // attn out (rounded in epilogue)
__device__ float g_bkv[2 * C_DIM];

// ---------------- asm helpers ----------------------------------------------
__device__ __forceinline__ uint32_t smem_u32(const void* p) {
    uint32_t a;
    asm("{ .reg .u64 t; cvta.to.shared.u64 t, %1; cvt.u32.u64 %0, t; }"
        : "=r"(a) : "l"(p));
    return a;
}
__device__ __forceinline__ float tf32r(float x) {
    uint32_t o;
    asm("cvt.rna.tf32.f32 %0, %1;" : "=r"(o) : "f"(x));
    return __uint_as_float(o);
}
__device__ __forceinline__ void mma_tf32(float* c, uint32_t a0, uint32_t a1,
                                         uint32_t a2, uint32_t a3,
                                         uint32_t b0, uint32_t b1) {
    asm volatile(
        "mma.sync.aligned.m16n8k8.row.col.f32.tf32.tf32.f32 "
        "{%0,%1,%2,%3}, {%4,%5,%6,%7}, {%8,%9}, {%0,%1,%2,%3};"
        : "+f"(c[0]), "+f"(c[1]), "+f"(c[2]), "+f"(c[3])
        : "r"(a0), "r"(a1), "r"(a2), "r"(a3), "r"(b0), "r"(b1));
}
#define CP_ASYNC16(dst, src) \
    asm volatile("cp.async.cg.shared.global [%0], [%1], 16;" :: "r"(dst), "l"(src))
#define CP_COMMIT() asm volatile("cp.async.commit_group;" ::: "memory")
#define CP_WAIT2()  asm volatile("cp.async.wait_group 2;" ::: "memory")

// ---------------------------------------------------------------------------
// TF32 GEMM:  C[z][m][n] = sum_k A[m,k]*B[n,k]  (+ bias)
// A [M,K] row-major (lda, per-z sA); B [N,K] row-major (ldb, per-z sB).
// Operands MUST be tf32-pre-rounded. BIASMODE: 0 none, 1 bias[n].
// ROUND: 1 -> round output to tf32 before store.
// M%128==0, N%128==0, K%32==0, K/32>=3.
// ---------------------------------------------------------------------------
template <int BIASMODE, int ROUND>
__global__ __launch_bounds__(256, 1)
void tf_gemm(const float* __restrict__ A, int lda, long sA,
             const float* __restrict__ B, int ldb, long sB,
             const float* __restrict__ bias, long sBias,
             float* __restrict__ C, int ldc, long sC, int K)
{
    extern __shared__ char smem[];
    const uint32_t sb = smem_u32(smem);
    const uint32_t* sw = (const uint32_t*)smem;
    const int tid = threadIdx.x, wid = tid >> 5, lid = tid & 31;
    const int m0 = blockIdx.y * 128, n0 = blockIdx.x * 128;

    if (BIASMODE != 0) bias += (long)blockIdx.z * sBias;
    const float* Ab = A + (long)blockIdx.z * sA + (long)m0 * lda;
    const float* Bb = B + (long)blockIdx.z * sB + (long)n0 * ldb;

    // loader: 2048 16B chunks per stage (A:1024, B:1024), 8 per thread
    const float* gp[8];
    uint32_t so[8];
#pragma unroll
    for (int i = 0; i < 8; ++i) {
        const int idx = i * 256 + tid;
        const int mat = idx >> 10;            // 0 = A, 1 = B
        const int row = (idx >> 3) & 127;
        const int ch  = idx & 7;              // 16B chunk within 128B row
        gp[i] = (mat ? Bb : Ab) + (long)row * (mat ? ldb : lda) + ch * 4;
        so[i] = (uint32_t)(mat * MTB + row * RSFB + ch * 16);
    }

#define ISSUE_STAGE(stage, kidx) do {                                  \
        const uint32_t _db = sb + (uint32_t)(stage) * STGF;            \
        const long _go = (long)(kidx) * 32;                            \
        _Pragma("unroll")                                              \
        for (int _i = 0; _i < 8; ++_i)                                 \
            CP_ASYNC16(_db + so[_i], gp[_i] + _go);                    \
    } while (0)

    // fragment addressing (32-bit word offsets within a stage)
    const int gid = lid >> 2, t4 = lid & 3;
    const int wm = wid >> 2, wn = wid & 3;        // 2x4 warps, warp 64x32
    const uint32_t fA = (uint32_t)((wm * 64 + gid) * RSF + t4);
    const uint32_t fB = (uint32_t)(MTB / 4 + (wn * 32 + gid) * RSF + t4);

    float acc[4][4][4];
#pragma unroll
    for (int i = 0; i < 4; ++i)
#pragma unroll
        for (int j = 0; j < 4; ++j)
#pragma unroll
            for (int q = 0; q < 4; ++q) acc[i][j][q] = 0.f;

    const int nch = K >> 5;

    ISSUE_STAGE(0, 0); CP_COMMIT();
    ISSUE_STAGE(1, 1); CP_COMMIT();
    ISSUE_STAGE(2, 2); CP_COMMIT();

    for (int c = 0; c < nch; ++c) {
        CP_WAIT2();
        __syncthreads();
        if (c + 3 < nch) ISSUE_STAGE((c + 3) & 3, c + 3);
        CP_COMMIT();

        const uint32_t base = ((uint32_t)(c & 3) * STGF) >> 2;
#pragma unroll
        for (int s = 0; s < 4; ++s) {          // 4 x k8 steps per TK=32
            const uint32_t ko = s * 8;
            uint32_t a[4][4], b[4][2];
#pragma unroll
            for (int mt = 0; mt < 4; ++mt) {
                const uint32_t p = base + fA + mt * (16 * RSF) + ko;
                a[mt][0] = sw[p];
                a[mt][1] = sw[p + 8 * RSF];
                a[mt][2] = sw[p + 4];
                a[mt][3] = sw[p + 8 * RSF + 4];
            }
#pragma unroll
            for (int nt = 0; nt < 4; ++nt) {
                const uint32_t p = base + fB + nt * (8 * RSF) + ko;
                b[nt][0] = sw[p];
                b[nt][1] = sw[p + 4];
            }
#pragma unroll
            for (int mt = 0; mt < 4; ++mt)
#pragma unroll
                for (int nt = 0; nt < 4; ++nt)
                    mma_tf32(acc[mt][nt], a[mt][0], a[mt][1], a[mt][2], a[mt][3],
                             b[nt][0], b[nt][1]);
        }
    }
#undef ISSUE_STAGE

    // ---- epilogue ----------------------------------------------------------
    float* Cp = C + (long)blockIdx.z * sC;
    const int row_base = m0 + wm * 64;
    const int col_base = n0 + wn * 32;
    const int lr = lid >> 2, lc = (lid & 3) * 2;
#pragma unroll
    for (int mt = 0; mt < 4; ++mt) {
        const int r0 = row_base + mt * 16 + lr;
#pragma unroll
        for (int nt = 0; nt < 4; ++nt) {
            const int cix = col_base + nt * 8 + lc;
            float b0 = 0.f, b1 = 0.f;
            if (BIASMODE == 1) { b0 = bias[cix]; b1 = bias[cix + 1]; }
            float v00 = acc[mt][nt][0] + b0, v01 = acc[mt][nt][1] + b1;
            float v10 = acc[mt][nt][2] + b0, v11 = acc[mt][nt][3] + b1;
            if (ROUND) {
                v00 = tf32r(v00); v01 = tf32r(v01);
                v10 = tf32r(v10); v11 = tf32r(v11);
            }
            *(float2*)(Cp + (long)r0 * ldc + cix)       = make_float2(v00, v01);
            *(float2*)(Cp + (long)(r0 + 8) * ldc + cix) = make_float2(v10, v11);
        }
    }
}

// ---------------------------------------------------------------------------
// elementwise helpers
// ---------------------------------------------------------------------------
__global__ __launch_bounds__(256)
void round_copy_kernel(const float* __restrict__ in, float* __restrict__ out)
{
    long i = ((long)blockIdx.x * 256 + threadIdx.x) * 4;
    float4 v = *(const float4*)(in + i);
    *(float4*)(out + i) = make_float4(tf32r(v.x), tf32r(v.y), tf32r(v.z), tf32r(v.w));
}

// transpose + round: W[K,N] fp32 -> out[N,K] fp32 (tf32-rounded)
__global__ __launch_bounds__(256)
void transT_kernel(const float* __restrict__ W, float* __restrict__ out,
                   int Kd, int Nd)
{
    __shared__ float t[32][33];
    const int k0 = blockIdx.y * 32, n0 = blockIdx.x * 32;
    const int tx = threadIdx.x & 31, ty = threadIdx.x >> 5;
#pragma unroll
    for (int r = 0; r < 4; ++r)
        t[ty + 8 * r][tx] = W[(long)(k0 + ty + 8 * r) * Nd + n0 + tx];
    __syncthreads();
#pragma unroll
    for (int r = 0; r < 4; ++r)
        out[(long)(n0 + ty + 8 * r) * Kd + k0 + tx] = tf32r(t[tx][ty + 8 * r]);
}

__global__ void concat_bias_kernel(const float* __restrict__ bk,
                                   const float* __restrict__ bv,
                                   float* __restrict__ o)
{
    int i = blockIdx.x * 256 + threadIdx.x;
    o[i] = bk[i];
    o[C_DIM + i] = bv[i];
}

// RMSNorm over rows of 2048, in place, output tf32-rounded
__global__ __launch_bounds__(256)
void rmsnorm_kernel(float* __restrict__ buf, const float* __restrict__ g)
{
    float* row = buf + (long)blockIdx.x * C_DIM;
    const int t = threadIdx.x;
    float4 v0 = *(float4*)(row + t * 4);
    float4 v1 = *(float4*)(row + 1024 + t * 4);
    float ss = v0.x * v0.x + v0.y * v0.y + v0.z * v0.z + v0.w * v0.w
             + v1.x * v1.x + v1.y * v1.y + v1.z * v1.z + v1.w * v1.w;
#pragma unroll
    for (int o = 16; o > 0; o >>= 1) ss += __shfl_xor_sync(0xffffffffu, ss, o);
    __shared__ float ws[8]; __shared__ float s_inv;
    if ((t & 31) == 0) ws[t >> 5] = ss;
    __syncthreads();
    if (t == 0) {
        float s = 0.f;
#pragma unroll
        for (int i = 0; i < 8; ++i) s += ws[i];
        s_inv = rsqrtf(s * (1.0f / C_DIM) + 1e-6f);
    }
    __syncthreads();
    const float inv = s_inv;
    float4 w0 = *(const float4*)(g + t * 4);
    float4 w1 = *(const float4*)(g + 1024 + t * 4);
    *(float4*)(row + t * 4) = make_float4(
        tf32r(v0.x * inv * w0.x), tf32r(v0.y * inv * w0.y),
        tf32r(v0.z * inv * w0.z), tf32r(v0.w * inv * w0.w));
    *(float4*)(row + 1024 + t * 4) = make_float4(
        tf32r(v1.x * inv * w1.x), tf32r(v1.y * inv * w1.y),
        tf32r(v1.z * inv * w1.z), tf32r(v1.w * inv * w1.w));
}

// softmax over rows of 512, in place, 1/sqrt(128) pre-scale, tf32-rounded out
__global__ __launch_bounds__(128)
void softmax_kernel(float* __restrict__ sc)
{
    const float scale = 0.08838834764831845f;
    float* row = sc + (long)blockIdx.x * S_KV;
    const int t = threadIdx.x;
    float4 v = *(float4*)(row + t * 4);
    v.x *= scale; v.y *= scale; v.z *= scale; v.w *= scale;
    float m = fmaxf(fmaxf(v.x, v.y), fmaxf(v.z, v.w));
#pragma unroll
    for (int o = 16; o > 0; o >>= 1) m = fmaxf(m, __shfl_xor_sync(0xffffffffu, m, o));
    __shared__ float wm[4]; __shared__ float wsum[4];
    if ((t & 31) == 0) wm[t >> 5] = m;
    __syncthreads();
    m = fmaxf(fmaxf(wm[0], wm[1]), fmaxf(wm[2], wm[3]));
    float e0 = expf(v.x - m), e1 = expf(v.y - m), e2 = expf(v.z - m), e3 = expf(v.w - m);
    float s = e0 + e1 + e2 + e3;
#pragma unroll
    for (int o = 16; o > 0; o >>= 1) s += __shfl_xor_sync(0xffffffffu, s, o);
    if ((t & 31) == 0) wsum[t >> 5] = s;
    __syncthreads();
    s = wsum[0] + wsum[1] + wsum[2] + wsum[3];
    const float inv = 1.0f / s;
    *(float4*)(row + t * 4) = make_float4(tf32r(e0 * inv), tf32r(e1 * inv),
                                          tf32r(e2 * inv), tf32r(e3 * inv));
}

// ---------------------------------------------------------------------------
extern "C" void kernel_launch(void* const* d_in, const int* in_sizes, int n_in,
                              void* d_out, int out_size)
{
    (void)in_sizes; (void)n_in; (void)out_size;
    const float* x   = (const float*)d_in[0];
    const float* ctx = (const float*)d_in[1];
    const float* Wq  = (const float*)d_in[2];
    const float* bq  = (const float*)d_in[3];
    const float* Wk  = (const float*)d_in[4];
    const float* bk  = (const float*)d_in[5];
    const float* Wv  = (const float*)d_in[6];
    const float* bv  = (const float*)d_in[7];
    const float* Wo  = (const float*)d_in[8];
    const float* bo  = (const float*)d_in[9];
    const float* gq  = (const float*)d_in[10];
    const float* gk  = (const float*)d_in[11];
    float* out = (float*)d_out;

    cudaFuncSetAttribute(tf_gemm<0,0>, cudaFuncAttributeMaxDynamicSharedMemorySize, SMF);
    cudaFuncSetAttribute(tf_gemm<0,1>, cudaFuncAttributeMaxDynamicSharedMemorySize, SMF);
    cudaFuncSetAttribute(tf_gemm<1,0>, cudaFuncAttributeMaxDynamicSharedMemorySize, SMF);

    float *xt, *ct, *wqt, *wkvt, *wot, *qf, *kvf, *vt, *scf, *atf, *bkv;
    cudaGetSymbolAddress((void**)&xt,   g_xt);
    cudaGetSymbolAddress((void**)&ct,   g_ct);
    cudaGetSymbolAddress((void**)&wqt,  g_wqt);
    cudaGetSymbolAddress((void**)&wkvt, g_wkvt);
    cudaGetSymbolAddress((void**)&wot,  g_wot);
    cudaGetSymbolAddress((void**)&qf,   g_qf);
    cudaGetSymbolAddress((void**)&kvf,  g_kvf);
    cudaGetSymbolAddress((void**)&vt,   g_vt);
    cudaGetSymbolAddress((void**)&scf,  g_scf);
    cudaGetSymbolAddress((void**)&atf,  g_atf);
    cudaGetSymbolAddress((void**)&bkv,  g_bkv);

    const long WKV = (long)C_DIM * CTXD;      // per-z weight stride
    const long SKV = (long)S_KV * C_DIM;      // per-z [k|v] stride

    // ---- input rounding / transposes ---------------------------------------
    round_copy_kernel<<<(L_Q * C_DIM) / 1024, 256>>>(x, xt);
    round_copy_kernel<<<(S_KV * CTXD) / 1024, 256>>>(ctx, ct);
    transT_kernel<<<dim3(C_DIM / 32, C_DIM / 32), 256>>>(Wq, wqt, C_DIM, C_DIM);
    transT_kernel<<<dim3(C_DIM / 32, CTXD / 32), 256>>>(Wk, wkvt, CTXD, C_DIM);
    transT_kernel<<<dim3(C_DIM / 32, CTXD / 32), 256>>>(Wv, wkvt + WKV, CTXD, C_DIM);
    transT_kernel<<<dim3(C_DIM / 32, C_DIM / 32), 256>>>(Wo, wot, C_DIM, C_DIM);
    concat_bias_kernel<<<C_DIM / 256, 256>>>(bk, bv, bkv);

    // ---- projections -------------------------------------------------------
    // q = x @ Wq + bq           M=8192 N=2048 K=2048
    tf_gemm<1,0><<<dim3(16, 64, 1), 256, SMF>>>(xt, C_DIM, 0, wqt, C_DIM, 0,
                                                bq, 0, qf, C_DIM, 0, C_DIM);
    // [k|v] = ctx @ [Wk|Wv] + [bk|bv]   z=2, 128 CTAs
    tf_gemm<1,0><<<dim3(16, 4, 2), 256, SMF>>>(ct, CTXD, 0, wkvt, CTXD, WKV,
                                               bkv, C_DIM, kvf, C_DIM, SKV, CTXD);

    // ---- norms / transposes ------------------------------------------------
    rmsnorm_kernel<<<L_Q, 256>>>(qf, gq);
    rmsnorm_kernel<<<S_KV, 256>>>(kvf, gk);
    transT_kernel<<<dim3(C_DIM / 32, S_KV / 32), 256>>>(kvf + SKV, vt, S_KV, C_DIM);

    // ---- attention ---------------------------------------------------------
    // scores[h] = Q_h @ K_h^T    M=8192 N=512 K=128
    tf_gemm<0,0><<<dim3(4, 64, NH), 256, SMF>>>(qf, C_DIM, HD, kvf, C_DIM, HD,
                                                nullptr, 0,
                                                scf, S_KV, (long)L_Q * S_KV, HD);
    softmax_kernel<<<NH * L_Q, 128>>>(scf);
    // attn[h] = P_h @ V_h        M=8192 N=128 K=512  (output tf32-rounded)
    tf_gemm<0,1><<<dim3(1, 64, NH), 256, SMF>>>(scf, S_KV, (long)L_Q * S_KV,
                                                vt, S_KV, (long)HD * S_KV,
                                                nullptr, 0,
                                                atf, C_DIM, HD, S_KV);

    // ---- output projection -------------------------------------------------
    tf_gemm<1,0><<<dim3(16, 64, 1), 256, SMF>>>(atf, C_DIM, 0, wot, C_DIM, 0,
                                                bo, 0, out, C_DIM, 0, C_DIM);
}

// round 8
// speedup vs baseline: 3.0636x; 1.0142x over previous
#include <cuda_runtime.h>
#include <cstdint>
#include <math.h>

// ===========================================================================
// WanCrossAttention  (B=1, L=8192, S=512, C=2048, CTX=4096, H=16, D=128)
// Round-8: TF32 mma.sync pipeline +
//   - fused QK^T + softmax kernel (scores never leave registers; writes P)
//   - in-kernel tf32 rounding of A operands (x, ctx read directly)
// ===========================================================================

#define L_Q   8192
#define S_KV  512
#define C_DIM 2048
#define CTXD  4096
#define NH    16
#define HD    128

// tf32 GEMM tiling: CTA 128x128, TK=32 fp32, 4-stage cp.async pipeline
#define RSF   36
#define RSFB  144
#define MTB   (128 * RSFB)           // 18432 B per matrix tile
#define STGF  (2 * MTB)              // 36864 B per stage
#define SMF   (4 * STGF)             // 147456 B

// qk_softmax smem layout (floats)
#define QRS      132                 // 128 + 4 pad
#define QK_QW    (64 * QRS)          // Q tile words        = 8448
#define QK_KW    (128 * QRS)         // one K chunk words   = 16896
#define QK_REDW  (64 * 8)            // one reduce buffer
#define QK_SMW   (QK_QW + 2 * QK_KW + 2 * QK_REDW)
#define QK_SMB   (QK_SMW * 4)        // 173056 B

// ---------------- scratch ---------------------------------------------------
__device__ float g_wqt[C_DIM * C_DIM];               // Wq^T rounded
__device__ float g_wkvt[2 * C_DIM * CTXD];           // [Wk^T | Wv^T] rounded
__device__ float g_wot[C_DIM * C_DIM];               // Wo^T rounded
__device__ float g_qf[L_Q * C_DIM];                  // q (rmsnorm in-place, rounded+scaled)
__device__ float g_kvf[2 * S_KV * C_DIM];            // [k | v]
__device__ float g_vt[C_DIM * S_KV];                 // V^T rounded
__device__ float g_scf[NH * L_Q * S_KV];             // P (tf32-rounded probs)
__device__ float g_atf[L_Q * C_DIM];                 // attn out (rounded in epilogue)
__device__ float g_bkv[2 * C_DIM];

// ---------------- asm helpers ----------------------------------------------
__device__ __forceinline__ uint32_t smem_u32(const void* p) {
    uint32_t a;
    asm("{ .reg .u64 t; cvta.to.shared.u64 t, %1; cvt.u32.u64 %0, t; }"
        : "=r"(a) : "l"(p));
    return a;
}
__device__ __forceinline__ float tf32r(float x) {
    uint32_t o;
    asm("cvt.rna.tf32.f32 %0, %1;" : "=r"(o) : "f"(x));
    return __uint_as_float(o);
}
__device__ __forceinline__ uint32_t tf32rb(uint32_t x) {
    uint32_t o;
    asm("cvt.rna.tf32.f32 %0, %1;" : "=r"(o) : "f"(__uint_as_float(x)));
    return o;
}
__device__ __forceinline__ void mma_tf32(float* c, uint32_t a0, uint32_t a1,
                                         uint32_t a2, uint32_t a3,
                                         uint32_t b0, uint32_t b1) {
    asm volatile(
        "mma.sync.aligned.m16n8k8.row.col.f32.tf32.tf32.f32 "
        "{%0,%1,%2,%3}, {%4,%5,%6,%7}, {%8,%9}, {%0,%1,%2,%3};"
        : "+f"(c[0]), "+f"(c[1]), "+f"(c[2]), "+f"(c[3])
        : "r"(a0), "r"(a1), "r"(a2), "r"(a3), "r"(b0), "r"(b1));
}
#define CP_ASYNC16(dst, src) \
    asm volatile("cp.async.cg.shared.global [%0], [%1], 16;" :: "r"(dst), "l"(src))
#define CP_COMMIT() asm volatile("cp.async.commit_group;" ::: "memory")
#define CP_WAITG(n) asm volatile("cp.async.wait_group %0;" :: "n"(n) : "memory")

// ---------------------------------------------------------------------------
// TF32 GEMM:  C[z][m][n] = sum_k A[m,k]*B[n,k]  (+ bias)
// BIASMODE: 0 none, 1 bias[n]. ROUND: round output to tf32.
// RNDA: round A fragments to tf32 after LDS (A may be raw fp32).
// B MUST be pre-rounded. M%128==0, N%128==0, K%32==0, K/32>=3.
// ---------------------------------------------------------------------------
template <int BIASMODE, int ROUND, int RNDA>
__global__ __launch_bounds__(256, 1)
void tf_gemm(const float* __restrict__ A, int lda, long sA,
             const float* __restrict__ B, int ldb, long sB,
             const float* __restrict__ bias, long sBias,
             float* __restrict__ C, int ldc, long sC, int K)
{
    extern __shared__ char smem[];
    const uint32_t sb = smem_u32(smem);
    const uint32_t* sw = (const uint32_t*)smem;
    const int tid = threadIdx.x, wid = tid >> 5, lid = tid & 31;
    const int m0 = blockIdx.y * 128, n0 = blockIdx.x * 128;

    if (BIASMODE != 0) bias += (long)blockIdx.z * sBias;
    const float* Ab = A + (long)blockIdx.z * sA + (long)m0 * lda;
    const float* Bb = B + (long)blockIdx.z * sB + (long)n0 * ldb;

    const float* gp[8];
    uint32_t so[8];
#pragma unroll
    for (int i = 0; i < 8; ++i) {
        const int idx = i * 256 + tid;
        const int mat = idx >> 10;
        const int row = (idx >> 3) & 127;
        const int ch  = idx & 7;
        gp[i] = (mat ? Bb : Ab) + (long)row * (mat ? ldb : lda) + ch * 4;
        so[i] = (uint32_t)(mat * MTB + row * RSFB + ch * 16);
    }

#define ISSUE_STAGE(stage, kidx) do {                                  \
        const uint32_t _db = sb + (uint32_t)(stage) * STGF;            \
        const long _go = (long)(kidx) * 32;                            \
        _Pragma("unroll")                                              \
        for (int _i = 0; _i < 8; ++_i)                                 \
            CP_ASYNC16(_db + so[_i], gp[_i] + _go);                    \
    } while (0)

    const int gid = lid >> 2, t4 = lid & 3;
    const int wm = wid >> 2, wn = wid & 3;
    const uint32_t fA = (uint32_t)((wm * 64 + gid) * RSF + t4);
    const uint32_t fB = (uint32_t)(MTB / 4 + (wn * 32 + gid) * RSF + t4);

    float acc[4][4][4];
#pragma unroll
    for (int i = 0; i < 4; ++i)
#pragma unroll
        for (int j = 0; j < 4; ++j)
#pragma unroll
            for (int q = 0; q < 4; ++q) acc[i][j][q] = 0.f;

    const int nch = K >> 5;

    ISSUE_STAGE(0, 0); CP_COMMIT();
    ISSUE_STAGE(1, 1); CP_COMMIT();
    ISSUE_STAGE(2, 2); CP_COMMIT();

    for (int c = 0; c < nch; ++c) {
        CP_WAITG(2);
        __syncthreads();
        if (c + 3 < nch) ISSUE_STAGE((c + 3) & 3, c + 3);
        CP_COMMIT();

        const uint32_t base = ((uint32_t)(c & 3) * STGF) >> 2;
#pragma unroll
        for (int s = 0; s < 4; ++s) {
            const uint32_t ko = s * 8;
            uint32_t a[4][4], b[4][2];
#pragma unroll
            for (int mt = 0; mt < 4; ++mt) {
                const uint32_t p = base + fA + mt * (16 * RSF) + ko;
                a[mt][0] = sw[p];
                a[mt][1] = sw[p + 8 * RSF];
                a[mt][2] = sw[p + 4];
                a[mt][3] = sw[p + 8 * RSF + 4];
                if (RNDA) {
#pragma unroll
                    for (int q = 0; q < 4; ++q) a[mt][q] = tf32rb(a[mt][q]);
                }
            }
#pragma unroll
            for (int nt = 0; nt < 4; ++nt) {
                const uint32_t p = base + fB + nt * (8 * RSF) + ko;
                b[nt][0] = sw[p];
                b[nt][1] = sw[p + 4];
            }
#pragma unroll
            for (int mt = 0; mt < 4; ++mt)
#pragma unroll
                for (int nt = 0; nt < 4; ++nt)
                    mma_tf32(acc[mt][nt], a[mt][0], a[mt][1], a[mt][2], a[mt][3],
                             b[nt][0], b[nt][1]);
        }
    }
#undef ISSUE_STAGE

    float* Cp = C + (long)blockIdx.z * sC;
    const int row_base = m0 + wm * 64;
    const int col_base = n0 + wn * 32;
    const int lr = lid >> 2, lc = (lid & 3) * 2;
#pragma unroll
    for (int mt = 0; mt < 4; ++mt) {
        const int r0 = row_base + mt * 16 + lr;
#pragma unroll
        for (int nt = 0; nt < 4; ++nt) {
            const int cix = col_base + nt * 8 + lc;
            float b0 = 0.f, b1 = 0.f;
            if (BIASMODE == 1) { b0 = bias[cix]; b1 = bias[cix + 1]; }
            float v00 = acc[mt][nt][0] + b0, v01 = acc[mt][nt][1] + b1;
            float v10 = acc[mt][nt][2] + b0, v11 = acc[mt][nt][3] + b1;
            if (ROUND) {
                v00 = tf32r(v00); v01 = tf32r(v01);
                v10 = tf32r(v10); v11 = tf32r(v11);
            }
            *(float2*)(Cp + (long)r0 * ldc + cix)       = make_float2(v00, v01);
            *(float2*)(Cp + (long)(r0 + 8) * ldc + cix) = make_float2(v10, v11);
        }
    }
}

// ---------------------------------------------------------------------------
// Fused QK^T + softmax:  P[z][m][s] = softmax_s( Q_z[m,:] . K_z[s,:] )
// CTA: 64 Q-rows x full S=512 for one head. Q,K pre-rounded (rmsnorm);
// scale folded into Q. 8 warps, warp covers 16 cols per 128-col K chunk.
// acc[4][8][4]: mt (4x16 rows) x (chunk*2+nt) x frag.
// ---------------------------------------------------------------------------
__global__ __launch_bounds__(256, 1)
void qk_softmax(const float* __restrict__ Q, const float* __restrict__ Km,
                float* __restrict__ P)
{
    extern __shared__ char smem[];
    const uint32_t sb = smem_u32(smem);
    const uint32_t* swd = (const uint32_t*)smem;
    float* redmx = (float*)smem + QK_QW + 2 * QK_KW;
    float* redsm = redmx + QK_REDW;

    const int tid = threadIdx.x, wid = tid >> 5, lid = tid & 31;
    const int g4 = lid >> 2, t4 = lid & 3;
    const int m0 = blockIdx.x * 64;
    const int z  = blockIdx.y;

    const float* Qg = Q + (long)z * HD + (long)m0 * C_DIM;
    const float* Kg = Km + (long)z * HD;

    // ---- issue Q tile (64x128) + K chunk 0, then K chunk 1 -----------------
    {
#pragma unroll
        for (int i = 0; i < 8; ++i) {           // Q: 2048 16B chunks
            const int idx = i * 256 + tid;
            const int row = idx >> 5, ch = idx & 31;
            CP_ASYNC16(sb + (uint32_t)(row * QRS + ch * 4) * 4,
                       Qg + (long)row * C_DIM + ch * 4);
        }
#pragma unroll
        for (int i = 0; i < 16; ++i) {          // K0: 4096 chunks
            const int idx = i * 256 + tid;
            const int row = idx >> 5, ch = idx & 31;
            CP_ASYNC16(sb + (uint32_t)(QK_QW + row * QRS + ch * 4) * 4,
                       Kg + (long)row * C_DIM + ch * 4);
        }
        CP_COMMIT();
#pragma unroll
        for (int i = 0; i < 16; ++i) {          // K1
            const int idx = i * 256 + tid;
            const int row = idx >> 5, ch = idx & 31;
            CP_ASYNC16(sb + (uint32_t)(QK_QW + QK_KW + row * QRS + ch * 4) * 4,
                       Kg + (long)(128 + row) * C_DIM + ch * 4);
        }
        CP_COMMIT();
    }

    float acc[4][8][4];
#pragma unroll
    for (int i = 0; i < 4; ++i)
#pragma unroll
        for (int j = 0; j < 8; ++j)
#pragma unroll
            for (int q = 0; q < 4; ++q) acc[i][j][q] = 0.f;

    // ---- 4 K chunks of 128 context rows ------------------------------------
#pragma unroll
    for (int c = 0; c < 4; ++c) {
        if (c < 3) { CP_WAITG(1); } else { CP_WAITG(0); }
        __syncthreads();

        const uint32_t kb = (uint32_t)(QK_QW + (c & 1) * QK_KW);
#pragma unroll
        for (int ks = 0; ks < 16; ++ks) {
            uint32_t a[4][4];
#pragma unroll
            for (int mt = 0; mt < 4; ++mt) {
                const uint32_t p = (uint32_t)((16 * mt + g4) * QRS + 8 * ks + t4);
                a[mt][0] = swd[p];
                a[mt][1] = swd[p + 8 * QRS];
                a[mt][2] = swd[p + 4];
                a[mt][3] = swd[p + 8 * QRS + 4];
            }
#pragma unroll
            for (int nt = 0; nt < 2; ++nt) {
                const uint32_t q = kb + (uint32_t)((wid * 16 + 8 * nt + g4) * QRS
                                                   + 8 * ks + t4);
                const uint32_t b0 = swd[q], b1 = swd[q + 4];
#pragma unroll
                for (int mt = 0; mt < 4; ++mt)
                    mma_tf32(acc[mt][2 * c + nt],
                             a[mt][0], a[mt][1], a[mt][2], a[mt][3], b0, b1);
            }
        }
        __syncthreads();
        if (c + 2 < 4) {                        // refill buffer (c&1) with K(c+2)
            const uint32_t kb2 = (uint32_t)(QK_QW + (c & 1) * QK_KW);
#pragma unroll
            for (int i = 0; i < 16; ++i) {
                const int idx = i * 256 + tid;
                const int row = idx >> 5, ch = idx & 31;
                CP_ASYNC16(sb + (kb2 + (uint32_t)(row * QRS + ch * 4)) * 4,
                           Kg + (long)((c + 2) * 128 + row) * C_DIM + ch * 4);
            }
            CP_COMMIT();
        }
    }

    // ---- softmax over the 512 cols (rows live across 8 warps' col slices) --
    // 1) per-thread / in-warp row max
    float gm[4][2];
#pragma unroll
    for (int mt = 0; mt < 4; ++mt)
#pragma unroll
        for (int h = 0; h < 2; ++h) {
            float m = -1e30f;
#pragma unroll
            for (int j = 0; j < 8; ++j)
                m = fmaxf(m, fmaxf(acc[mt][j][2 * h], acc[mt][j][2 * h + 1]));
            m = fmaxf(m, __shfl_xor_sync(0xffffffffu, m, 1));
            m = fmaxf(m, __shfl_xor_sync(0xffffffffu, m, 2));
            if (t4 == 0) redmx[(16 * mt + 8 * h + g4) * 8 + wid] = m;
            gm[mt][h] = m;
        }
    __syncthreads();
#pragma unroll
    for (int mt = 0; mt < 4; ++mt)
#pragma unroll
        for (int h = 0; h < 2; ++h) {
            const int row = 16 * mt + 8 * h + g4;
            float m = gm[mt][h];
#pragma unroll
            for (int w = 0; w < 8; ++w) m = fmaxf(m, redmx[row * 8 + w]);
            gm[mt][h] = m;
        }
    // 2) exp + row sum
    float gs[4][2];
#pragma unroll
    for (int mt = 0; mt < 4; ++mt)
#pragma unroll
        for (int h = 0; h < 2; ++h) {
            float s = 0.f;
            const float m = gm[mt][h];
#pragma unroll
            for (int j = 0; j < 8; ++j) {
                float e0 = __expf(acc[mt][j][2 * h] - m);
                float e1 = __expf(acc[mt][j][2 * h + 1] - m);
                acc[mt][j][2 * h] = e0; acc[mt][j][2 * h + 1] = e1;
                s += e0 + e1;
            }
            s += __shfl_xor_sync(0xffffffffu, s, 1);
            s += __shfl_xor_sync(0xffffffffu, s, 2);
            if (t4 == 0) redsm[(16 * mt + 8 * h + g4) * 8 + wid] = s;
        }
    __syncthreads();
#pragma unroll
    for (int mt = 0; mt < 4; ++mt)
#pragma unroll
        for (int h = 0; h < 2; ++h) {
            const int row = 16 * mt + 8 * h + g4;
            float s = 0.f;
#pragma unroll
            for (int w = 0; w < 8; ++w) s += redsm[row * 8 + w];
            gs[mt][h] = 1.0f / s;
        }
    // 3) normalize, round, store P
    float* Pg = P + (long)z * L_Q * S_KV + (long)m0 * S_KV;
#pragma unroll
    for (int mt = 0; mt < 4; ++mt)
#pragma unroll
        for (int h = 0; h < 2; ++h) {
            const int row = 16 * mt + 8 * h + g4;
            const float inv = gs[mt][h];
#pragma unroll
            for (int j = 0; j < 8; ++j) {
                const int col = 128 * (j >> 1) + wid * 16 + 8 * (j & 1) + 2 * t4;
                *(float2*)(Pg + (long)row * S_KV + col) =
                    make_float2(tf32r(acc[mt][j][2 * h] * inv),
                                tf32r(acc[mt][j][2 * h + 1] * inv));
            }
        }
}

// ---------------------------------------------------------------------------
// elementwise helpers
// ---------------------------------------------------------------------------
__global__ __launch_bounds__(256)
void transT_kernel(const float* __restrict__ W, float* __restrict__ out,
                   int Kd, int Nd)
{
    __shared__ float t[32][33];
    const int k0 = blockIdx.y * 32, n0 = blockIdx.x * 32;
    const int tx = threadIdx.x & 31, ty = threadIdx.x >> 5;
#pragma unroll
    for (int r = 0; r < 4; ++r)
        t[ty + 8 * r][tx] = W[(long)(k0 + ty + 8 * r) * Nd + n0 + tx];
    __syncthreads();
#pragma unroll
    for (int r = 0; r < 4; ++r)
        out[(long)(n0 + ty + 8 * r) * Kd + k0 + tx] = tf32r(t[tx][ty + 8 * r]);
}

__global__ void concat_bias_kernel(const float* __restrict__ bk,
                                   const float* __restrict__ bv,
                                   float* __restrict__ o)
{
    int i = blockIdx.x * 256 + threadIdx.x;
    o[i] = bk[i];
    o[C_DIM + i] = bv[i];
}

// RMSNorm over rows of 2048, in place, output tf32-rounded; extra scalar scale
__global__ __launch_bounds__(256)
void rmsnorm_kernel(float* __restrict__ buf, const float* __restrict__ g, float scale)
{
    float* row = buf + (long)blockIdx.x * C_DIM;
    const int t = threadIdx.x;
    float4 v0 = *(float4*)(row + t * 4);
    float4 v1 = *(float4*)(row + 1024 + t * 4);
    float ss = v0.x * v0.x + v0.y * v0.y + v0.z * v0.z + v0.w * v0.w
             + v1.x * v1.x + v1.y * v1.y + v1.z * v1.z + v1.w * v1.w;
#pragma unroll
    for (int o = 16; o > 0; o >>= 1) ss += __shfl_xor_sync(0xffffffffu, ss, o);
    __shared__ float ws[8]; __shared__ float s_inv;
    if ((t & 31) == 0) ws[t >> 5] = ss;
    __syncthreads();
    if (t == 0) {
        float s = 0.f;
#pragma unroll
        for (int i = 0; i < 8; ++i) s += ws[i];
        s_inv = rsqrtf(s * (1.0f / C_DIM) + 1e-6f) * scale;
    }
    __syncthreads();
    const float inv = s_inv;
    float4 w0 = *(const float4*)(g + t * 4);
    float4 w1 = *(const float4*)(g + 1024 + t * 4);
    *(float4*)(row + t * 4) = make_float4(
        tf32r(v0.x * inv * w0.x), tf32r(v0.y * inv * w0.y),
        tf32r(v0.z * inv * w0.z), tf32r(v0.w * inv * w0.w));
    *(float4*)(row + 1024 + t * 4) = make_float4(
        tf32r(v1.x * inv * w1.x), tf32r(v1.y * inv * w1.y),
        tf32r(v1.z * inv * w1.z), tf32r(v1.w * inv * w1.w));
}

// ---------------------------------------------------------------------------
extern "C" void kernel_launch(void* const* d_in, const int* in_sizes, int n_in,
                              void* d_out, int out_size)
{
    (void)in_sizes; (void)n_in; (void)out_size;
    const float* x   = (const float*)d_in[0];
    const float* ctx = (const float*)d_in[1];
    const float* Wq  = (const float*)d_in[2];
    const float* bq  = (const float*)d_in[3];
    const float* Wk  = (const float*)d_in[4];
    const float* bk  = (const float*)d_in[5];
    const float* Wv  = (const float*)d_in[6];
    const float* bv  = (const float*)d_in[7];
    const float* Wo  = (const float*)d_in[8];
    const float* bo  = (const float*)d_in[9];
    const float* gq  = (const float*)d_in[10];
    const float* gk  = (const float*)d_in[11];
    float* out = (float*)d_out;

    cudaFuncSetAttribute(tf_gemm<1,0,1>, cudaFuncAttributeMaxDynamicSharedMemorySize, SMF);
    cudaFuncSetAttribute(tf_gemm<0,1,0>, cudaFuncAttributeMaxDynamicSharedMemorySize, SMF);
    cudaFuncSetAttribute(tf_gemm<1,0,0>, cudaFuncAttributeMaxDynamicSharedMemorySize, SMF);
    cudaFuncSetAttribute(qk_softmax, cudaFuncAttributeMaxDynamicSharedMemorySize, QK_SMB);

    float *wqt, *wkvt, *wot, *qf, *kvf, *vt, *scf, *atf, *bkv;
    cudaGetSymbolAddress((void**)&wqt,  g_wqt);
    cudaGetSymbolAddress((void**)&wkvt, g_wkvt);
    cudaGetSymbolAddress((void**)&wot,  g_wot);
    cudaGetSymbolAddress((void**)&qf,   g_qf);
    cudaGetSymbolAddress((void**)&kvf,  g_kvf);
    cudaGetSymbolAddress((void**)&vt,   g_vt);
    cudaGetSymbolAddress((void**)&scf,  g_scf);
    cudaGetSymbolAddress((void**)&atf,  g_atf);
    cudaGetSymbolAddress((void**)&bkv,  g_bkv);

    const long WKV = (long)C_DIM * CTXD;
    const long SKV = (long)S_KV * C_DIM;
    const float ATTN_SCALE = 0.08838834764831845f;   // 1/sqrt(128)

    // ---- weight transposes (tf32-rounded) ----------------------------------
    transT_kernel<<<dim3(C_DIM / 32, C_DIM / 32), 256>>>(Wq, wqt, C_DIM, C_DIM);
    transT_kernel<<<dim3(C_DIM / 32, CTXD / 32), 256>>>(Wk, wkvt, CTXD, C_DIM);
    transT_kernel<<<dim3(C_DIM / 32, CTXD / 32), 256>>>(Wv, wkvt + WKV, CTXD, C_DIM);
    transT_kernel<<<dim3(C_DIM / 32, C_DIM / 32), 256>>>(Wo, wot, C_DIM, C_DIM);
    concat_bias_kernel<<<C_DIM / 256, 256>>>(bk, bv, bkv);

    // ---- projections (A = raw x/ctx, rounded in-kernel) --------------------
    tf_gemm<1,0,1><<<dim3(16, 64, 1), 256, SMF>>>(x, C_DIM, 0, wqt, C_DIM, 0,
                                                  bq, 0, qf, C_DIM, 0, C_DIM);
    tf_gemm<1,0,1><<<dim3(16, 4, 2), 256, SMF>>>(ctx, CTXD, 0, wkvt, CTXD, WKV,
                                                 bkv, C_DIM, kvf, C_DIM, SKV, CTXD);

    // ---- norms / transposes ------------------------------------------------
    rmsnorm_kernel<<<L_Q, 256>>>(qf, gq, ATTN_SCALE);   // fold 1/sqrt(d) into q
    rmsnorm_kernel<<<S_KV, 256>>>(kvf, gk, 1.0f);
    transT_kernel<<<dim3(C_DIM / 32, S_KV / 32), 256>>>(kvf + SKV, vt, S_KV, C_DIM);

    // ---- attention ---------------------------------------------------------
    qk_softmax<<<dim3(L_Q / 64, NH), 256, QK_SMB>>>(qf, kvf, scf);
    // attn[h] = P_h @ V_h    M=8192 N=128 K=512 (output tf32-rounded)
    tf_gemm<0,1,0><<<dim3(1, 64, NH), 256, SMF>>>(scf, S_KV, (long)L_Q * S_KV,
                                                  vt, S_KV, (long)HD * S_KV,
                                                  nullptr, 0,
                                                  atf, C_DIM, HD, S_KV);

    // ---- output projection -------------------------------------------------
    tf_gemm<1,0,0><<<dim3(16, 64, 1), 256, SMF>>>(atf, C_DIM, 0, wot, C_DIM, 0,
                                                  bo, 0, out, C_DIM, 0, C_DIM);
}

// round 9
// speedup vs baseline: 3.1320x; 1.0223x over previous
#include <cuda_runtime.h>
#include <cstdint>
#include <math.h>

// ===========================================================================
// WanCrossAttention  (B=1, L=8192, S=512, C=2048, CTX=4096, H=16, D=128)
// Round-9: TF32 mma.sync pipeline + FULL flash attention fusion:
//   attn_fused = QK^T -> softmax (regs) -> P staged in smem -> PV MMA.
//   P never touches global memory; PV kernel and g_scf eliminated.
// ===========================================================================

#define L_Q   8192
#define S_KV  512
#define C_DIM 2048
#define CTXD  4096
#define NH    16
#define HD    128

// tf32 GEMM tiling: CTA 128x128, TK=32 fp32, 4-stage cp.async pipeline
#define RSF   36
#define RSFB  144
#define MTB   (128 * RSFB)
#define STGF  (2 * MTB)
#define SMF   (4 * STGF)             // 147456 B

// attn_fused smem layout (32-bit words)
#define QRS    132                   // Q/K row stride (128 + 4)
#define AF_QW  (64 * QRS)            // Q tile           = 8448
#define AF_KW  (128 * QRS)           // one K chunk      = 16896
// phase 1: Q [0,8448) K0 [8448,25344) K1 [25344,42240)
#define AF_VW  (128 * 68)            // one V chunk      = 8704 (stride 68)
// phase 3: V0 [0,8704) V1 [8704,17408) P [17408,50432)
#define AF_PO  17408
#define AF_PRS 516                   // P row stride (512 + 4)
#define AF_RED 50432                 // redmx 512 + redsm 512
#define AF_SMW 51456
#define AF_SMB (AF_SMW * 4)          // 205824 B

// ---------------- scratch ---------------------------------------------------
__device__ float g_wqt[C_DIM * C_DIM];               // Wq^T rounded
__device__ float g_wkvt[2 * C_DIM * CTXD];           // [Wk^T | Wv^T] rounded
__device__ float g_wot[C_DIM * C_DIM];               // Wo^T rounded
__device__ float g_qf[L_Q * C_DIM];                  // q (rmsnorm in-place, rounded+scaled)
__device__ float g_kvf[2 * S_KV * C_DIM];            // [k | v]
__device__ float g_vt[C_DIM * S_KV];                 // V^T rounded
__device__ float g_atf[L_Q * C_DIM];                 // attn out (tf32-rounded)
__device__ float g_bkv[2 * C_DIM];

// ---------------- asm helpers ----------------------------------------------
__device__ __forceinline__ uint32_t smem_u32(const void* p) {
    uint32_t a;
    asm("{ .reg .u64 t; cvta.to.shared.u64 t, %1; cvt.u32.u64 %0, t; }"
        : "=r"(a) : "l"(p));
    return a;
}
__device__ __forceinline__ float tf32r(float x) {
    uint32_t o;
    asm("cvt.rna.tf32.f32 %0, %1;" : "=r"(o) : "f"(x));
    return __uint_as_float(o);
}
__device__ __forceinline__ uint32_t tf32rb(uint32_t x) {
    uint32_t o;
    asm("cvt.rna.tf32.f32 %0, %1;" : "=r"(o) : "f"(__uint_as_float(x)));
    return o;
}
__device__ __forceinline__ void mma_tf32(float* c, uint32_t a0, uint32_t a1,
                                         uint32_t a2, uint32_t a3,
                                         uint32_t b0, uint32_t b1) {
    asm volatile(
        "mma.sync.aligned.m16n8k8.row.col.f32.tf32.tf32.f32 "
        "{%0,%1,%2,%3}, {%4,%5,%6,%7}, {%8,%9}, {%0,%1,%2,%3};"
        : "+f"(c[0]), "+f"(c[1]), "+f"(c[2]), "+f"(c[3])
        : "r"(a0), "r"(a1), "r"(a2), "r"(a3), "r"(b0), "r"(b1));
}
#define CP_ASYNC16(dst, src) \
    asm volatile("cp.async.cg.shared.global [%0], [%1], 16;" :: "r"(dst), "l"(src))
#define CP_COMMIT() asm volatile("cp.async.commit_group;" ::: "memory")
#define CP_WAITG(n) asm volatile("cp.async.wait_group %0;" :: "n"(n) : "memory")

// ---------------------------------------------------------------------------
// TF32 GEMM (unchanged from round 8)
// ---------------------------------------------------------------------------
template <int BIASMODE, int ROUND, int RNDA>
__global__ __launch_bounds__(256, 1)
void tf_gemm(const float* __restrict__ A, int lda, long sA,
             const float* __restrict__ B, int ldb, long sB,
             const float* __restrict__ bias, long sBias,
             float* __restrict__ C, int ldc, long sC, int K)
{
    extern __shared__ char smem[];
    const uint32_t sb = smem_u32(smem);
    const uint32_t* sw = (const uint32_t*)smem;
    const int tid = threadIdx.x, wid = tid >> 5, lid = tid & 31;
    const int m0 = blockIdx.y * 128, n0 = blockIdx.x * 128;

    if (BIASMODE != 0) bias += (long)blockIdx.z * sBias;
    const float* Ab = A + (long)blockIdx.z * sA + (long)m0 * lda;
    const float* Bb = B + (long)blockIdx.z * sB + (long)n0 * ldb;

    const float* gp[8];
    uint32_t so[8];
#pragma unroll
    for (int i = 0; i < 8; ++i) {
        const int idx = i * 256 + tid;
        const int mat = idx >> 10;
        const int row = (idx >> 3) & 127;
        const int ch  = idx & 7;
        gp[i] = (mat ? Bb : Ab) + (long)row * (mat ? ldb : lda) + ch * 4;
        so[i] = (uint32_t)(mat * MTB + row * RSFB + ch * 16);
    }

#define ISSUE_STAGE(stage, kidx) do {                                  \
        const uint32_t _db = sb + (uint32_t)(stage) * STGF;            \
        const long _go = (long)(kidx) * 32;                            \
        _Pragma("unroll")                                              \
        for (int _i = 0; _i < 8; ++_i)                                 \
            CP_ASYNC16(_db + so[_i], gp[_i] + _go);                    \
    } while (0)

    const int gid = lid >> 2, t4 = lid & 3;
    const int wm = wid >> 2, wn = wid & 3;
    const uint32_t fA = (uint32_t)((wm * 64 + gid) * RSF + t4);
    const uint32_t fB = (uint32_t)(MTB / 4 + (wn * 32 + gid) * RSF + t4);

    float acc[4][4][4];
#pragma unroll
    for (int i = 0; i < 4; ++i)
#pragma unroll
        for (int j = 0; j < 4; ++j)
#pragma unroll
            for (int q = 0; q < 4; ++q) acc[i][j][q] = 0.f;

    const int nch = K >> 5;

    ISSUE_STAGE(0, 0); CP_COMMIT();
    ISSUE_STAGE(1, 1); CP_COMMIT();
    ISSUE_STAGE(2, 2); CP_COMMIT();

    for (int c = 0; c < nch; ++c) {
        CP_WAITG(2);
        __syncthreads();
        if (c + 3 < nch) ISSUE_STAGE((c + 3) & 3, c + 3);
        CP_COMMIT();

        const uint32_t base = ((uint32_t)(c & 3) * STGF) >> 2;
#pragma unroll
        for (int s = 0; s < 4; ++s) {
            const uint32_t ko = s * 8;
            uint32_t a[4][4], b[4][2];
#pragma unroll
            for (int mt = 0; mt < 4; ++mt) {
                const uint32_t p = base + fA + mt * (16 * RSF) + ko;
                a[mt][0] = sw[p];
                a[mt][1] = sw[p + 8 * RSF];
                a[mt][2] = sw[p + 4];
                a[mt][3] = sw[p + 8 * RSF + 4];
                if (RNDA) {
#pragma unroll
                    for (int q = 0; q < 4; ++q) a[mt][q] = tf32rb(a[mt][q]);
                }
            }
#pragma unroll
            for (int nt = 0; nt < 4; ++nt) {
                const uint32_t p = base + fB + nt * (8 * RSF) + ko;
                b[nt][0] = sw[p];
                b[nt][1] = sw[p + 4];
            }
#pragma unroll
            for (int mt = 0; mt < 4; ++mt)
#pragma unroll
                for (int nt = 0; nt < 4; ++nt)
                    mma_tf32(acc[mt][nt], a[mt][0], a[mt][1], a[mt][2], a[mt][3],
                             b[nt][0], b[nt][1]);
        }
    }
#undef ISSUE_STAGE

    float* Cp = C + (long)blockIdx.z * sC;
    const int row_base = m0 + wm * 64;
    const int col_base = n0 + wn * 32;
    const int lr = lid >> 2, lc = (lid & 3) * 2;
#pragma unroll
    for (int mt = 0; mt < 4; ++mt) {
        const int r0 = row_base + mt * 16 + lr;
#pragma unroll
        for (int nt = 0; nt < 4; ++nt) {
            const int cix = col_base + nt * 8 + lc;
            float b0 = 0.f, b1 = 0.f;
            if (BIASMODE == 1) { b0 = bias[cix]; b1 = bias[cix + 1]; }
            float v00 = acc[mt][nt][0] + b0, v01 = acc[mt][nt][1] + b1;
            float v10 = acc[mt][nt][2] + b0, v11 = acc[mt][nt][3] + b1;
            if (ROUND) {
                v00 = tf32r(v00); v01 = tf32r(v01);
                v10 = tf32r(v10); v11 = tf32r(v11);
            }
            *(float2*)(Cp + (long)r0 * ldc + cix)       = make_float2(v00, v01);
            *(float2*)(Cp + (long)(r0 + 8) * ldc + cix) = make_float2(v10, v11);
        }
    }
}

// ---------------------------------------------------------------------------
// Fused attention: per CTA = 64 Q-rows x one head.
//   Phase 1: S = QK^T in regs (8 warps, warp = 16 cols per 128-col K chunk)
//   Phase 2: softmax in regs; P (tf32) staged to smem; V0,V1 prefetched
//   Phase 3: attn = P @ V^T, V streamed in 8 double-buffered 64-k chunks
// Q pre-scaled by 1/sqrt(d) and tf32-rounded; K,V^T tf32-rounded.
// ---------------------------------------------------------------------------
__global__ __launch_bounds__(256, 1)
void attn_fused(const float* __restrict__ Q, const float* __restrict__ Km,
                const float* __restrict__ Vt, float* __restrict__ O)
{
    extern __shared__ char smem[];
    const uint32_t sb = smem_u32(smem);
    const uint32_t* swd = (const uint32_t*)smem;
    float* sf = (float*)smem;
    float* redmx = sf + AF_RED;
    float* redsm = redmx + 512;

    const int tid = threadIdx.x, wid = tid >> 5, lid = tid & 31;
    const int g4 = lid >> 2, t4 = lid & 3;
    const int m0 = blockIdx.x * 64;
    const int z  = blockIdx.y;

    const float* Qg = Q + (long)z * HD + (long)m0 * C_DIM;
    const float* Kg = Km + (long)z * HD;
    const float* Vg = Vt + (long)z * HD * S_KV;      // head z: 128 rows x 512

    // ---- phase 1 loads: Q tile + K0, K1 ------------------------------------
    {
#pragma unroll
        for (int i = 0; i < 8; ++i) {
            const int idx = i * 256 + tid;
            const int row = idx >> 5, ch = idx & 31;
            CP_ASYNC16(sb + (uint32_t)(row * QRS + ch * 4) * 4,
                       Qg + (long)row * C_DIM + ch * 4);
        }
#pragma unroll
        for (int i = 0; i < 16; ++i) {
            const int idx = i * 256 + tid;
            const int row = idx >> 5, ch = idx & 31;
            CP_ASYNC16(sb + (uint32_t)(AF_QW + row * QRS + ch * 4) * 4,
                       Kg + (long)row * C_DIM + ch * 4);
        }
        CP_COMMIT();
#pragma unroll
        for (int i = 0; i < 16; ++i) {
            const int idx = i * 256 + tid;
            const int row = idx >> 5, ch = idx & 31;
            CP_ASYNC16(sb + (uint32_t)(AF_QW + AF_KW + row * QRS + ch * 4) * 4,
                       Kg + (long)(128 + row) * C_DIM + ch * 4);
        }
        CP_COMMIT();
    }

    float acc[4][8][4];
#pragma unroll
    for (int i = 0; i < 4; ++i)
#pragma unroll
        for (int j = 0; j < 8; ++j)
#pragma unroll
            for (int q = 0; q < 4; ++q) acc[i][j][q] = 0.f;

    // ---- phase 1 MMA: 4 K chunks -------------------------------------------
#pragma unroll
    for (int c = 0; c < 4; ++c) {
        if (c < 3) { CP_WAITG(1); } else { CP_WAITG(0); }
        __syncthreads();

        const uint32_t kb = (uint32_t)(AF_QW + (c & 1) * AF_KW);
#pragma unroll
        for (int ks = 0; ks < 16; ++ks) {
            uint32_t a[4][4];
#pragma unroll
            for (int mt = 0; mt < 4; ++mt) {
                const uint32_t p = (uint32_t)((16 * mt + g4) * QRS + 8 * ks + t4);
                a[mt][0] = swd[p];
                a[mt][1] = swd[p + 8 * QRS];
                a[mt][2] = swd[p + 4];
                a[mt][3] = swd[p + 8 * QRS + 4];
            }
#pragma unroll
            for (int nt = 0; nt < 2; ++nt) {
                const uint32_t q = kb + (uint32_t)((wid * 16 + 8 * nt + g4) * QRS
                                                   + 8 * ks + t4);
                const uint32_t b0 = swd[q], b1 = swd[q + 4];
#pragma unroll
                for (int mt = 0; mt < 4; ++mt)
                    mma_tf32(acc[mt][2 * c + nt],
                             a[mt][0], a[mt][1], a[mt][2], a[mt][3], b0, b1);
            }
        }
        __syncthreads();
        if (c + 2 < 4) {
            const uint32_t kb2 = (uint32_t)(AF_QW + (c & 1) * AF_KW);
#pragma unroll
            for (int i = 0; i < 16; ++i) {
                const int idx = i * 256 + tid;
                const int row = idx >> 5, ch = idx & 31;
                CP_ASYNC16(sb + (kb2 + (uint32_t)(row * QRS + ch * 4)) * 4,
                           Kg + (long)((c + 2) * 128 + row) * C_DIM + ch * 4);
            }
            CP_COMMIT();
        }
    }

    // ---- prefetch V chunks 0,1 (Q/K smem dead; hides under softmax) --------
#pragma unroll
    for (int b = 0; b < 2; ++b) {
#pragma unroll
        for (int i = 0; i < 8; ++i) {
            const int idx = i * 256 + tid;
            const int row = idx >> 4, ch = idx & 15;
            CP_ASYNC16(sb + (uint32_t)(b * AF_VW + row * 68 + ch * 4) * 4,
                       Vg + (long)row * S_KV + b * 64 + ch * 4);
        }
        CP_COMMIT();
    }

    // ---- softmax -----------------------------------------------------------
    float gm[4][2];
#pragma unroll
    for (int mt = 0; mt < 4; ++mt)
#pragma unroll
        for (int h = 0; h < 2; ++h) {
            float m = -1e30f;
#pragma unroll
            for (int j = 0; j < 8; ++j)
                m = fmaxf(m, fmaxf(acc[mt][j][2 * h], acc[mt][j][2 * h + 1]));
            m = fmaxf(m, __shfl_xor_sync(0xffffffffu, m, 1));
            m = fmaxf(m, __shfl_xor_sync(0xffffffffu, m, 2));
            if (t4 == 0) redmx[(16 * mt + 8 * h + g4) * 8 + wid] = m;
            gm[mt][h] = m;
        }
    __syncthreads();
#pragma unroll
    for (int mt = 0; mt < 4; ++mt)
#pragma unroll
        for (int h = 0; h < 2; ++h) {
            const int row = 16 * mt + 8 * h + g4;
            float m = gm[mt][h];
#pragma unroll
            for (int w = 0; w < 8; ++w) m = fmaxf(m, redmx[row * 8 + w]);
            gm[mt][h] = m;
        }
    float gs[4][2];
#pragma unroll
    for (int mt = 0; mt < 4; ++mt)
#pragma unroll
        for (int h = 0; h < 2; ++h) {
            float s = 0.f;
            const float m = gm[mt][h];
#pragma unroll
            for (int j = 0; j < 8; ++j) {
                float e0 = __expf(acc[mt][j][2 * h] - m);
                float e1 = __expf(acc[mt][j][2 * h + 1] - m);
                acc[mt][j][2 * h] = e0; acc[mt][j][2 * h + 1] = e1;
                s += e0 + e1;
            }
            s += __shfl_xor_sync(0xffffffffu, s, 1);
            s += __shfl_xor_sync(0xffffffffu, s, 2);
            if (t4 == 0) redsm[(16 * mt + 8 * h + g4) * 8 + wid] = s;
        }
    __syncthreads();
#pragma unroll
    for (int mt = 0; mt < 4; ++mt)
#pragma unroll
        for (int h = 0; h < 2; ++h) {
            const int row = 16 * mt + 8 * h + g4;
            float s = 0.f;
#pragma unroll
            for (int w = 0; w < 8; ++w) s += redsm[row * 8 + w];
            gs[mt][h] = 1.0f / s;
        }

    // ---- stage P (tf32-rounded probs) into smem ----------------------------
#pragma unroll
    for (int mt = 0; mt < 4; ++mt)
#pragma unroll
        for (int h = 0; h < 2; ++h) {
            const int row = 16 * mt + 8 * h + g4;
            const float inv = gs[mt][h];
#pragma unroll
            for (int j = 0; j < 8; ++j) {
                const int col = 128 * (j >> 1) + wid * 16 + 8 * (j & 1) + 2 * t4;
                *(float2*)(sf + AF_PO + (uint32_t)(row * AF_PRS + col)) =
                    make_float2(tf32r(acc[mt][j][2 * h] * inv),
                                tf32r(acc[mt][j][2 * h + 1] * inv));
            }
        }
    __syncthreads();

    // ---- phase 3: attn = P @ V^T  (output 64x128, warp grid 2x4) -----------
    const int pwm = wid & 1, pwn = wid >> 1;
    float accP[2][4][4];
#pragma unroll
    for (int i = 0; i < 2; ++i)
#pragma unroll
        for (int j = 0; j < 4; ++j)
#pragma unroll
            for (int q = 0; q < 4; ++q) accP[i][j][q] = 0.f;

#pragma unroll
    for (int c = 0; c < 8; ++c) {
        if (c < 7) { CP_WAITG(1); } else { CP_WAITG(0); }
        __syncthreads();

        const uint32_t vb = (uint32_t)((c & 1) * AF_VW);
#pragma unroll
        for (int ks = 0; ks < 8; ++ks) {
            uint32_t a[2][4];
#pragma unroll
            for (int mt = 0; mt < 2; ++mt) {
                const uint32_t p = (uint32_t)(AF_PO + (32 * pwm + 16 * mt + g4) * AF_PRS
                                              + 64 * c + 8 * ks + t4);
                a[mt][0] = swd[p];
                a[mt][1] = swd[p + 8 * AF_PRS];
                a[mt][2] = swd[p + 4];
                a[mt][3] = swd[p + 8 * AF_PRS + 4];
            }
#pragma unroll
            for (int nt = 0; nt < 4; ++nt) {
                const uint32_t q = vb + (uint32_t)((32 * pwn + 8 * nt + g4) * 68
                                                   + 8 * ks + t4);
                const uint32_t b0 = swd[q], b1 = swd[q + 4];
#pragma unroll
                for (int mt = 0; mt < 2; ++mt)
                    mma_tf32(accP[mt][nt],
                             a[mt][0], a[mt][1], a[mt][2], a[mt][3], b0, b1);
            }
        }
        __syncthreads();
        if (c + 2 < 8) {                 // refill buffer (c&1) with V chunk c+2
            const uint32_t vb2 = (uint32_t)((c & 1) * AF_VW);
#pragma unroll
            for (int i = 0; i < 8; ++i) {
                const int idx = i * 256 + tid;
                const int row = idx >> 4, ch = idx & 15;
                CP_ASYNC16(sb + (vb2 + (uint32_t)(row * 68 + ch * 4)) * 4,
                           Vg + (long)row * S_KV + (c + 2) * 64 + ch * 4);
            }
            CP_COMMIT();
        }
    }

    // ---- epilogue: write attn rows (tf32-rounded) --------------------------
    float* Og = O + (long)m0 * C_DIM + (long)z * HD;
    const int lr = lid >> 2, lc = (lid & 3) * 2;
#pragma unroll
    for (int mt = 0; mt < 2; ++mt) {
        const int r0 = 32 * pwm + 16 * mt + lr;
#pragma unroll
        for (int nt = 0; nt < 4; ++nt) {
            const int cix = 32 * pwn + 8 * nt + lc;
            *(float2*)(Og + (long)r0 * C_DIM + cix) =
                make_float2(tf32r(accP[mt][nt][0]), tf32r(accP[mt][nt][1]));
            *(float2*)(Og + (long)(r0 + 8) * C_DIM + cix) =
                make_float2(tf32r(accP[mt][nt][2]), tf32r(accP[mt][nt][3]));
        }
    }
}

// ---------------------------------------------------------------------------
// elementwise helpers
// ---------------------------------------------------------------------------
__global__ __launch_bounds__(256)
void transT_kernel(const float* __restrict__ W, float* __restrict__ out,
                   int Kd, int Nd)
{
    __shared__ float t[32][33];
    const int k0 = blockIdx.y * 32, n0 = blockIdx.x * 32;
    const int tx = threadIdx.x & 31, ty = threadIdx.x >> 5;
#pragma unroll
    for (int r = 0; r < 4; ++r)
        t[ty + 8 * r][tx] = W[(long)(k0 + ty + 8 * r) * Nd + n0 + tx];
    __syncthreads();
#pragma unroll
    for (int r = 0; r < 4; ++r)
        out[(long)(n0 + ty + 8 * r) * Kd + k0 + tx] = tf32r(t[tx][ty + 8 * r]);
}

__global__ void concat_bias_kernel(const float* __restrict__ bk,
                                   const float* __restrict__ bv,
                                   float* __restrict__ o)
{
    int i = blockIdx.x * 256 + threadIdx.x;
    o[i] = bk[i];
    o[C_DIM + i] = bv[i];
}

__global__ __launch_bounds__(256)
void rmsnorm_kernel(float* __restrict__ buf, const float* __restrict__ g, float scale)
{
    float* row = buf + (long)blockIdx.x * C_DIM;
    const int t = threadIdx.x;
    float4 v0 = *(float4*)(row + t * 4);
    float4 v1 = *(float4*)(row + 1024 + t * 4);
    float ss = v0.x * v0.x + v0.y * v0.y + v0.z * v0.z + v0.w * v0.w
             + v1.x * v1.x + v1.y * v1.y + v1.z * v1.z + v1.w * v1.w;
#pragma unroll
    for (int o = 16; o > 0; o >>= 1) ss += __shfl_xor_sync(0xffffffffu, ss, o);
    __shared__ float ws[8]; __shared__ float s_inv;
    if ((t & 31) == 0) ws[t >> 5] = ss;
    __syncthreads();
    if (t == 0) {
        float s = 0.f;
#pragma unroll
        for (int i = 0; i < 8; ++i) s += ws[i];
        s_inv = rsqrtf(s * (1.0f / C_DIM) + 1e-6f) * scale;
    }
    __syncthreads();
    const float inv = s_inv;
    float4 w0 = *(const float4*)(g + t * 4);
    float4 w1 = *(const float4*)(g + 1024 + t * 4);
    *(float4*)(row + t * 4) = make_float4(
        tf32r(v0.x * inv * w0.x), tf32r(v0.y * inv * w0.y),
        tf32r(v0.z * inv * w0.z), tf32r(v0.w * inv * w0.w));
    *(float4*)(row + 1024 + t * 4) = make_float4(
        tf32r(v1.x * inv * w1.x), tf32r(v1.y * inv * w1.y),
        tf32r(v1.z * inv * w1.z), tf32r(v1.w * inv * w1.w));
}

// ---------------------------------------------------------------------------
extern "C" void kernel_launch(void* const* d_in, const int* in_sizes, int n_in,
                              void* d_out, int out_size)
{
    (void)in_sizes; (void)n_in; (void)out_size;
    const float* x   = (const float*)d_in[0];
    const float* ctx = (const float*)d_in[1];
    const float* Wq  = (const float*)d_in[2];
    const float* bq  = (const float*)d_in[3];
    const float* Wk  = (const float*)d_in[4];
    const float* bk  = (const float*)d_in[5];
    const float* Wv  = (const float*)d_in[6];
    const float* bv  = (const float*)d_in[7];
    const float* Wo  = (const float*)d_in[8];
    const float* bo  = (const float*)d_in[9];
    const float* gq  = (const float*)d_in[10];
    const float* gk  = (const float*)d_in[11];
    float* out = (float*)d_out;

    cudaFuncSetAttribute(tf_gemm<1,0,1>, cudaFuncAttributeMaxDynamicSharedMemorySize, SMF);
    cudaFuncSetAttribute(tf_gemm<1,0,0>, cudaFuncAttributeMaxDynamicSharedMemorySize, SMF);
    cudaFuncSetAttribute(attn_fused, cudaFuncAttributeMaxDynamicSharedMemorySize, AF_SMB);

    float *wqt, *wkvt, *wot, *qf, *kvf, *vt, *atf, *bkv;
    cudaGetSymbolAddress((void**)&wqt,  g_wqt);
    cudaGetSymbolAddress((void**)&wkvt, g_wkvt);
    cudaGetSymbolAddress((void**)&wot,  g_wot);
    cudaGetSymbolAddress((void**)&qf,   g_qf);
    cudaGetSymbolAddress((void**)&kvf,  g_kvf);
    cudaGetSymbolAddress((void**)&vt,   g_vt);
    cudaGetSymbolAddress((void**)&atf,  g_atf);
    cudaGetSymbolAddress((void**)&bkv,  g_bkv);

    const long WKV = (long)C_DIM * CTXD;
    const long SKV = (long)S_KV * C_DIM;
    const float ATTN_SCALE = 0.08838834764831845f;   // 1/sqrt(128)

    // ---- weight transposes (tf32-rounded) ----------------------------------
    transT_kernel<<<dim3(C_DIM / 32, C_DIM / 32), 256>>>(Wq, wqt, C_DIM, C_DIM);
    transT_kernel<<<dim3(C_DIM / 32, CTXD / 32), 256>>>(Wk, wkvt, CTXD, C_DIM);
    transT_kernel<<<dim3(C_DIM / 32, CTXD / 32), 256>>>(Wv, wkvt + WKV, CTXD, C_DIM);
    transT_kernel<<<dim3(C_DIM / 32, C_DIM / 32), 256>>>(Wo, wot, C_DIM, C_DIM);
    concat_bias_kernel<<<C_DIM / 256, 256>>>(bk, bv, bkv);

    // ---- projections (A = raw x/ctx, rounded in-kernel) --------------------
    tf_gemm<1,0,1><<<dim3(16, 64, 1), 256, SMF>>>(x, C_DIM, 0, wqt, C_DIM, 0,
                                                  bq, 0, qf, C_DIM, 0, C_DIM);
    tf_gemm<1,0,1><<<dim3(16, 4, 2), 256, SMF>>>(ctx, CTXD, 0, wkvt, CTXD, WKV,
                                                 bkv, C_DIM, kvf, C_DIM, SKV, CTXD);

    // ---- norms / transposes ------------------------------------------------
    rmsnorm_kernel<<<L_Q, 256>>>(qf, gq, ATTN_SCALE);
    rmsnorm_kernel<<<S_KV, 256>>>(kvf, gk, 1.0f);
    transT_kernel<<<dim3(C_DIM / 32, S_KV / 32), 256>>>(kvf + SKV, vt, S_KV, C_DIM);

    // ---- fused attention ---------------------------------------------------
    attn_fused<<<dim3(L_Q / 64, NH), 256, AF_SMB>>>(qf, kvf, vt, atf);

    // ---- output projection -------------------------------------------------
    tf_gemm<1,0,0><<<dim3(16, 64, 1), 256, SMF>>>(atf, C_DIM, 0, wot, C_DIM, 0,
                                                  bo, 0, out, C_DIM, 0, C_DIM);
}

// round 10
// speedup vs baseline: 3.2827x; 1.0481x over previous
#include <cuda_runtime.h>
#include <cstdint>
#include <math.h>

// ===========================================================================
// WanCrossAttention  (B=1, L=8192, S=512, C=2048, CTX=4096, H=16, D=128)
// Round-10: TF32 pipeline + ldmatrix fragment loads (CUTLASS tf32-via-b16
// trick): cuts shared-load instruction count 3-4x in tf_gemm and attn_fused.
// Arithmetic bit-identical to round 9.
// ===========================================================================

#define L_Q   8192
#define S_KV  512
#define C_DIM 2048
#define CTXD  4096
#define NH    16
#define HD    128

// tf32 GEMM tiling: CTA 128x128, TK=32 fp32, 4-stage cp.async pipeline
#define RSF   36
#define RSFB  144
#define MTB   (128 * RSFB)
#define STGF  (2 * MTB)
#define SMF   (4 * STGF)             // 147456 B

// attn_fused smem layout (32-bit words)
#define QRS    132                   // Q/K row stride (128 + 4)
#define AF_QW  (64 * QRS)
#define AF_KW  (128 * QRS)
#define AF_VW  (128 * 68)            // V chunk, row stride 68 words
#define AF_PO  17408
#define AF_PRS 516                   // P row stride
#define AF_RED 50432
#define AF_SMW 51456
#define AF_SMB (AF_SMW * 4)          // 205824 B

// ---------------- scratch ---------------------------------------------------
__device__ float g_wqt[C_DIM * C_DIM];
__device__ float g_wkvt[2 * C_DIM * CTXD];
__device__ float g_wot[C_DIM * C_DIM];
__device__ float g_qf[L_Q * C_DIM];
__device__ float g_kvf[2 * S_KV * C_DIM];
__device__ float g_vt[C_DIM * S_KV];
__device__ float g_atf[L_Q * C_DIM];
__device__ float g_bkv[2 * C_DIM];

// ---------------- asm helpers ----------------------------------------------
__device__ __forceinline__ uint32_t smem_u32(const void* p) {
    uint32_t a;
    asm("{ .reg .u64 t; cvta.to.shared.u64 t, %1; cvt.u32.u64 %0, t; }"
        : "=r"(a) : "l"(p));
    return a;
}
__device__ __forceinline__ float tf32r(float x) {
    uint32_t o;
    asm("cvt.rna.tf32.f32 %0, %1;" : "=r"(o) : "f"(x));
    return __uint_as_float(o);
}
__device__ __forceinline__ uint32_t tf32rb(uint32_t x) {
    uint32_t o;
    asm("cvt.rna.tf32.f32 %0, %1;" : "=r"(o) : "f"(__uint_as_float(x)));
    return o;
}
__device__ __forceinline__ void ldsm_x4(uint32_t* r, uint32_t addr) {
    asm volatile("ldmatrix.sync.aligned.m8n8.x4.shared.b16 {%0,%1,%2,%3}, [%4];"
                 : "=r"(r[0]), "=r"(r[1]), "=r"(r[2]), "=r"(r[3]) : "r"(addr));
}
__device__ __forceinline__ void mma_tf32(float* c, uint32_t a0, uint32_t a1,
                                         uint32_t a2, uint32_t a3,
                                         uint32_t b0, uint32_t b1) {
    asm volatile(
        "mma.sync.aligned.m16n8k8.row.col.f32.tf32.tf32.f32 "
        "{%0,%1,%2,%3}, {%4,%5,%6,%7}, {%8,%9}, {%0,%1,%2,%3};"
        : "+f"(c[0]), "+f"(c[1]), "+f"(c[2]), "+f"(c[3])
        : "r"(a0), "r"(a1), "r"(a2), "r"(a3), "r"(b0), "r"(b1));
}
#define CP_ASYNC16(dst, src) \
    asm volatile("cp.async.cg.shared.global [%0], [%1], 16;" :: "r"(dst), "l"(src))
#define CP_COMMIT() asm volatile("cp.async.commit_group;" ::: "memory")
#define CP_WAITG(n) asm volatile("cp.async.wait_group %0;" :: "n"(n) : "memory")

// ---------------------------------------------------------------------------
// TF32 GEMM with ldmatrix fragment loads.
// ---------------------------------------------------------------------------
template <int BIASMODE, int ROUND, int RNDA>
__global__ __launch_bounds__(256, 1)
void tf_gemm(const float* __restrict__ A, int lda, long sA,
             const float* __restrict__ B, int ldb, long sB,
             const float* __restrict__ bias, long sBias,
             float* __restrict__ C, int ldc, long sC, int K)
{
    extern __shared__ char smem[];
    const uint32_t sb = smem_u32(smem);
    const int tid = threadIdx.x, wid = tid >> 5, lid = tid & 31;
    const int m0 = blockIdx.y * 128, n0 = blockIdx.x * 128;

    if (BIASMODE != 0) bias += (long)blockIdx.z * sBias;
    const float* Ab = A + (long)blockIdx.z * sA + (long)m0 * lda;
    const float* Bb = B + (long)blockIdx.z * sB + (long)n0 * ldb;

    const float* gp[8];
    uint32_t so[8];
#pragma unroll
    for (int i = 0; i < 8; ++i) {
        const int idx = i * 256 + tid;
        const int mat = idx >> 10;
        const int row = (idx >> 3) & 127;
        const int ch  = idx & 7;
        gp[i] = (mat ? Bb : Ab) + (long)row * (mat ? ldb : lda) + ch * 4;
        so[i] = (uint32_t)(mat * MTB + row * RSFB + ch * 16);
    }

#define ISSUE_STAGE(stage, kidx) do {                                  \
        const uint32_t _db = sb + (uint32_t)(stage) * STGF;            \
        const long _go = (long)(kidx) * 32;                            \
        _Pragma("unroll")                                              \
        for (int _i = 0; _i < 8; ++_i)                                 \
            CP_ASYNC16(_db + so[_i], gp[_i] + _go);                    \
    } while (0)

    // ldmatrix thread offsets (words within a stage)
    const int lm = lid >> 3, lr8 = lid & 7;
    const int wm = wid >> 2, wn = wid & 3;
    // A: row += 8*(m&1), col16B = (m>>1)
    const uint32_t aoff = (uint32_t)((lr8 + 8 * (lm & 1)) * RSF + 4 * (lm >> 1));
    // B: row += 8*(m>>1), col16B = (m&1)
    const uint32_t boff = (uint32_t)((lr8 + 8 * (lm >> 1)) * RSF + 4 * (lm & 1));
    const uint32_t fA = (uint32_t)((wm * 64) * RSF) + aoff;
    const uint32_t fB = (uint32_t)(MTB / 4 + (wn * 32) * RSF) + boff;

    float acc[4][4][4];
#pragma unroll
    for (int i = 0; i < 4; ++i)
#pragma unroll
        for (int j = 0; j < 4; ++j)
#pragma unroll
            for (int q = 0; q < 4; ++q) acc[i][j][q] = 0.f;

    const int nch = K >> 5;

    ISSUE_STAGE(0, 0); CP_COMMIT();
    ISSUE_STAGE(1, 1); CP_COMMIT();
    ISSUE_STAGE(2, 2); CP_COMMIT();

    for (int c = 0; c < nch; ++c) {
        CP_WAITG(2);
        __syncthreads();
        if (c + 3 < nch) ISSUE_STAGE((c + 3) & 3, c + 3);
        CP_COMMIT();

        const uint32_t base = ((uint32_t)(c & 3) * STGF) >> 2;
#pragma unroll
        for (int s = 0; s < 4; ++s) {
            const uint32_t ko = s * 8;
            uint32_t a[4][4], b[2][4];
#pragma unroll
            for (int mt = 0; mt < 4; ++mt) {
                ldsm_x4(a[mt], sb + (base + fA + mt * (16 * RSF) + ko) * 4);
                if (RNDA) {
#pragma unroll
                    for (int q = 0; q < 4; ++q) a[mt][q] = tf32rb(a[mt][q]);
                }
            }
#pragma unroll
            for (int np = 0; np < 2; ++np)
                ldsm_x4(b[np], sb + (base + fB + np * (16 * RSF) + ko) * 4);
#pragma unroll
            for (int mt = 0; mt < 4; ++mt)
#pragma unroll
                for (int nt = 0; nt < 4; ++nt) {
                    const int np = nt >> 1, e = (nt & 1) * 2;
                    mma_tf32(acc[mt][nt], a[mt][0], a[mt][1], a[mt][2], a[mt][3],
                             b[np][e], b[np][e + 1]);
                }
        }
    }
#undef ISSUE_STAGE

    float* Cp = C + (long)blockIdx.z * sC;
    const int row_base = m0 + wm * 64;
    const int col_base = n0 + wn * 32;
    const int lr = lid >> 2, lc = (lid & 3) * 2;
#pragma unroll
    for (int mt = 0; mt < 4; ++mt) {
        const int r0 = row_base + mt * 16 + lr;
#pragma unroll
        for (int nt = 0; nt < 4; ++nt) {
            const int cix = col_base + nt * 8 + lc;
            float b0 = 0.f, b1 = 0.f;
            if (BIASMODE == 1) { b0 = bias[cix]; b1 = bias[cix + 1]; }
            float v00 = acc[mt][nt][0] + b0, v01 = acc[mt][nt][1] + b1;
            float v10 = acc[mt][nt][2] + b0, v11 = acc[mt][nt][3] + b1;
            if (ROUND) {
                v00 = tf32r(v00); v01 = tf32r(v01);
                v10 = tf32r(v10); v11 = tf32r(v11);
            }
            *(float2*)(Cp + (long)r0 * ldc + cix)       = make_float2(v00, v01);
            *(float2*)(Cp + (long)(r0 + 8) * ldc + cix) = make_float2(v10, v11);
        }
    }
}

// ---------------------------------------------------------------------------
// Fused attention (round-9 structure, ldmatrix fragment loads).
// ---------------------------------------------------------------------------
__global__ __launch_bounds__(256, 1)
void attn_fused(const float* __restrict__ Q, const float* __restrict__ Km,
                const float* __restrict__ Vt, float* __restrict__ O)
{
    extern __shared__ char smem[];
    const uint32_t sb = smem_u32(smem);
    float* sf = (float*)smem;
    float* redmx = sf + AF_RED;
    float* redsm = redmx + 512;

    const int tid = threadIdx.x, wid = tid >> 5, lid = tid & 31;
    const int g4 = lid >> 2, t4 = lid & 3;
    const int lm = lid >> 3, lr8 = lid & 7;
    const int m0 = blockIdx.x * 64;
    const int z  = blockIdx.y;

    const float* Qg = Q + (long)z * HD + (long)m0 * C_DIM;
    const float* Kg = Km + (long)z * HD;
    const float* Vg = Vt + (long)z * HD * S_KV;

    // ldmatrix thread offsets (words)
    const uint32_t aoffQ = (uint32_t)((lr8 + 8 * (lm & 1)) * QRS + 4 * (lm >> 1));
    const uint32_t boffK = (uint32_t)((lr8 + 8 * (lm >> 1)) * QRS + 4 * (lm & 1));
    const uint32_t aoffP = (uint32_t)((lr8 + 8 * (lm & 1)) * AF_PRS + 4 * (lm >> 1));
    const uint32_t boffV = (uint32_t)((lr8 + 8 * (lm >> 1)) * 68 + 4 * (lm & 1));

    // ---- phase 1 loads: Q tile + K0, K1 ------------------------------------
    {
#pragma unroll
        for (int i = 0; i < 8; ++i) {
            const int idx = i * 256 + tid;
            const int row = idx >> 5, ch = idx & 31;
            CP_ASYNC16(sb + (uint32_t)(row * QRS + ch * 4) * 4,
                       Qg + (long)row * C_DIM + ch * 4);
        }
#pragma unroll
        for (int i = 0; i < 16; ++i) {
            const int idx = i * 256 + tid;
            const int row = idx >> 5, ch = idx & 31;
            CP_ASYNC16(sb + (uint32_t)(AF_QW + row * QRS + ch * 4) * 4,
                       Kg + (long)row * C_DIM + ch * 4);
        }
        CP_COMMIT();
#pragma unroll
        for (int i = 0; i < 16; ++i) {
            const int idx = i * 256 + tid;
            const int row = idx >> 5, ch = idx & 31;
            CP_ASYNC16(sb + (uint32_t)(AF_QW + AF_KW + row * QRS + ch * 4) * 4,
                       Kg + (long)(128 + row) * C_DIM + ch * 4);
        }
        CP_COMMIT();
    }

    float acc[4][8][4];
#pragma unroll
    for (int i = 0; i < 4; ++i)
#pragma unroll
        for (int j = 0; j < 8; ++j)
#pragma unroll
            for (int q = 0; q < 4; ++q) acc[i][j][q] = 0.f;

    // ---- phase 1 MMA: 4 K chunks -------------------------------------------
#pragma unroll
    for (int c = 0; c < 4; ++c) {
        if (c < 3) { CP_WAITG(1); } else { CP_WAITG(0); }
        __syncthreads();

        const uint32_t kb = (uint32_t)(AF_QW + (c & 1) * AF_KW);
#pragma unroll
        for (int ks = 0; ks < 16; ++ks) {
            uint32_t a[4][4], b[4];
#pragma unroll
            for (int mt = 0; mt < 4; ++mt)
                ldsm_x4(a[mt], sb + (uint32_t)((16 * mt) * QRS + 8 * ks + aoffQ) * 4);
            // one x4 covers both nt (16 K rows of this warp)
            ldsm_x4(b, sb + (kb + (uint32_t)((wid * 16) * QRS + 8 * ks) + boffK) * 4);
#pragma unroll
            for (int nt = 0; nt < 2; ++nt) {
                const uint32_t b0 = b[nt * 2], b1 = b[nt * 2 + 1];
#pragma unroll
                for (int mt = 0; mt < 4; ++mt)
                    mma_tf32(acc[mt][2 * c + nt],
                             a[mt][0], a[mt][1], a[mt][2], a[mt][3], b0, b1);
            }
        }
        __syncthreads();
        if (c + 2 < 4) {
            const uint32_t kb2 = (uint32_t)(AF_QW + (c & 1) * AF_KW);
#pragma unroll
            for (int i = 0; i < 16; ++i) {
                const int idx = i * 256 + tid;
                const int row = idx >> 5, ch = idx & 31;
                CP_ASYNC16(sb + (kb2 + (uint32_t)(row * QRS + ch * 4)) * 4,
                           Kg + (long)((c + 2) * 128 + row) * C_DIM + ch * 4);
            }
            CP_COMMIT();
        }
    }

    // ---- prefetch V chunks 0,1 ----------------------------------------------
#pragma unroll
    for (int b = 0; b < 2; ++b) {
#pragma unroll
        for (int i = 0; i < 8; ++i) {
            const int idx = i * 256 + tid;
            const int row = idx >> 4, ch = idx & 15;
            CP_ASYNC16(sb + (uint32_t)(b * AF_VW + row * 68 + ch * 4) * 4,
                       Vg + (long)row * S_KV + b * 64 + ch * 4);
        }
        CP_COMMIT();
    }

    // ---- softmax -----------------------------------------------------------
    float gm[4][2];
#pragma unroll
    for (int mt = 0; mt < 4; ++mt)
#pragma unroll
        for (int h = 0; h < 2; ++h) {
            float m = -1e30f;
#pragma unroll
            for (int j = 0; j < 8; ++j)
                m = fmaxf(m, fmaxf(acc[mt][j][2 * h], acc[mt][j][2 * h + 1]));
            m = fmaxf(m, __shfl_xor_sync(0xffffffffu, m, 1));
            m = fmaxf(m, __shfl_xor_sync(0xffffffffu, m, 2));
            if (t4 == 0) redmx[(16 * mt + 8 * h + g4) * 8 + wid] = m;
            gm[mt][h] = m;
        }
    __syncthreads();
#pragma unroll
    for (int mt = 0; mt < 4; ++mt)
#pragma unroll
        for (int h = 0; h < 2; ++h) {
            const int row = 16 * mt + 8 * h + g4;
            float m = gm[mt][h];
#pragma unroll
            for (int w = 0; w < 8; ++w) m = fmaxf(m, redmx[row * 8 + w]);
            gm[mt][h] = m;
        }
    float gs[4][2];
#pragma unroll
    for (int mt = 0; mt < 4; ++mt)
#pragma unroll
        for (int h = 0; h < 2; ++h) {
            float s = 0.f;
            const float m = gm[mt][h];
#pragma unroll
            for (int j = 0; j < 8; ++j) {
                float e0 = __expf(acc[mt][j][2 * h] - m);
                float e1 = __expf(acc[mt][j][2 * h + 1] - m);
                acc[mt][j][2 * h] = e0; acc[mt][j][2 * h + 1] = e1;
                s += e0 + e1;
            }
            s += __shfl_xor_sync(0xffffffffu, s, 1);
            s += __shfl_xor_sync(0xffffffffu, s, 2);
            if (t4 == 0) redsm[(16 * mt + 8 * h + g4) * 8 + wid] = s;
        }
    __syncthreads();
#pragma unroll
    for (int mt = 0; mt < 4; ++mt)
#pragma unroll
        for (int h = 0; h < 2; ++h) {
            const int row = 16 * mt + 8 * h + g4;
            float s = 0.f;
#pragma unroll
            for (int w = 0; w < 8; ++w) s += redsm[row * 8 + w];
            gs[mt][h] = 1.0f / s;
        }

    // ---- stage P (tf32-rounded) into smem -----------------------------------
#pragma unroll
    for (int mt = 0; mt < 4; ++mt)
#pragma unroll
        for (int h = 0; h < 2; ++h) {
            const int row = 16 * mt + 8 * h + g4;
            const float inv = gs[mt][h];
#pragma unroll
            for (int j = 0; j < 8; ++j) {
                const int col = 128 * (j >> 1) + wid * 16 + 8 * (j & 1) + 2 * t4;
                *(float2*)(sf + AF_PO + (uint32_t)(row * AF_PRS + col)) =
                    make_float2(tf32r(acc[mt][j][2 * h] * inv),
                                tf32r(acc[mt][j][2 * h + 1] * inv));
            }
        }
    __syncthreads();

    // ---- phase 3: attn = P @ V^T  (output 64x128, warp grid 2x4) -----------
    const int pwm = wid & 1, pwn = wid >> 1;
    float accP[2][4][4];
#pragma unroll
    for (int i = 0; i < 2; ++i)
#pragma unroll
        for (int j = 0; j < 4; ++j)
#pragma unroll
            for (int q = 0; q < 4; ++q) accP[i][j][q] = 0.f;

#pragma unroll
    for (int c = 0; c < 8; ++c) {
        if (c < 7) { CP_WAITG(1); } else { CP_WAITG(0); }
        __syncthreads();

        const uint32_t vb = (uint32_t)((c & 1) * AF_VW);
#pragma unroll
        for (int ks = 0; ks < 8; ++ks) {
            uint32_t a[2][4], b[2][4];
#pragma unroll
            for (int mt = 0; mt < 2; ++mt)
                ldsm_x4(a[mt], sb + (uint32_t)(AF_PO + (32 * pwm + 16 * mt) * AF_PRS
                                               + 64 * c + 8 * ks + aoffP) * 4);
#pragma unroll
            for (int np = 0; np < 2; ++np)
                ldsm_x4(b[np], sb + (vb + (uint32_t)((32 * pwn + 16 * np) * 68
                                                     + 8 * ks) + boffV) * 4);
#pragma unroll
            for (int nt = 0; nt < 4; ++nt) {
                const int np = nt >> 1, e = (nt & 1) * 2;
#pragma unroll
                for (int mt = 0; mt < 2; ++mt)
                    mma_tf32(accP[mt][nt],
                             a[mt][0], a[mt][1], a[mt][2], a[mt][3],
                             b[np][e], b[np][e + 1]);
            }
        }
        __syncthreads();
        if (c + 2 < 8) {
            const uint32_t vb2 = (uint32_t)((c & 1) * AF_VW);
#pragma unroll
            for (int i = 0; i < 8; ++i) {
                const int idx = i * 256 + tid;
                const int row = idx >> 4, ch = idx & 15;
                CP_ASYNC16(sb + (vb2 + (uint32_t)(row * 68 + ch * 4)) * 4,
                           Vg + (long)row * S_KV + (c + 2) * 64 + ch * 4);
            }
            CP_COMMIT();
        }
    }

    // ---- epilogue -----------------------------------------------------------
    float* Og = O + (long)m0 * C_DIM + (long)z * HD;
    const int lr = lid >> 2, lc = (lid & 3) * 2;
#pragma unroll
    for (int mt = 0; mt < 2; ++mt) {
        const int r0 = 32 * pwm + 16 * mt + lr;
#pragma unroll
        for (int nt = 0; nt < 4; ++nt) {
            const int cix = 32 * pwn + 8 * nt + lc;
            *(float2*)(Og + (long)r0 * C_DIM + cix) =
                make_float2(tf32r(accP[mt][nt][0]), tf32r(accP[mt][nt][1]));
            *(float2*)(Og + (long)(r0 + 8) * C_DIM + cix) =
                make_float2(tf32r(accP[mt][nt][2]), tf32r(accP[mt][nt][3]));
        }
    }
}

// ---------------------------------------------------------------------------
// elementwise helpers (unchanged)
// ---------------------------------------------------------------------------
__global__ __launch_bounds__(256)
void transT_kernel(const float* __restrict__ W, float* __restrict__ out,
                   int Kd, int Nd)
{
    __shared__ float t[32][33];
    const int k0 = blockIdx.y * 32, n0 = blockIdx.x * 32;
    const int tx = threadIdx.x & 31, ty = threadIdx.x >> 5;
#pragma unroll
    for (int r = 0; r < 4; ++r)
        t[ty + 8 * r][tx] = W[(long)(k0 + ty + 8 * r) * Nd + n0 + tx];
    __syncthreads();
#pragma unroll
    for (int r = 0; r < 4; ++r)
        out[(long)(n0 + ty + 8 * r) * Kd + k0 + tx] = tf32r(t[tx][ty + 8 * r]);
}

__global__ void concat_bias_kernel(const float* __restrict__ bk,
                                   const float* __restrict__ bv,
                                   float* __restrict__ o)
{
    int i = blockIdx.x * 256 + threadIdx.x;
    o[i] = bk[i];
    o[C_DIM + i] = bv[i];
}

__global__ __launch_bounds__(256)
void rmsnorm_kernel(float* __restrict__ buf, const float* __restrict__ g, float scale)
{
    float* row = buf + (long)blockIdx.x * C_DIM;
    const int t = threadIdx.x;
    float4 v0 = *(float4*)(row + t * 4);
    float4 v1 = *(float4*)(row + 1024 + t * 4);
    float ss = v0.x * v0.x + v0.y * v0.y + v0.z * v0.z + v0.w * v0.w
             + v1.x * v1.x + v1.y * v1.y + v1.z * v1.z + v1.w * v1.w;
#pragma unroll
    for (int o = 16; o > 0; o >>= 1) ss += __shfl_xor_sync(0xffffffffu, ss, o);
    __shared__ float ws[8]; __shared__ float s_inv;
    if ((t & 31) == 0) ws[t >> 5] = ss;
    __syncthreads();
    if (t == 0) {
        float s = 0.f;
#pragma unroll
        for (int i = 0; i < 8; ++i) s += ws[i];
        s_inv = rsqrtf(s * (1.0f / C_DIM) + 1e-6f) * scale;
    }
    __syncthreads();
    const float inv = s_inv;
    float4 w0 = *(const float4*)(g + t * 4);
    float4 w1 = *(const float4*)(g + 1024 + t * 4);
    *(float4*)(row + t * 4) = make_float4(
        tf32r(v0.x * inv * w0.x), tf32r(v0.y * inv * w0.y),
        tf32r(v0.z * inv * w0.z), tf32r(v0.w * inv * w0.w));
    *(float4*)(row + 1024 + t * 4) = make_float4(
        tf32r(v1.x * inv * w1.x), tf32r(v1.y * inv * w1.y),
        tf32r(v1.z * inv * w1.z), tf32r(v1.w * inv * w1.w));
}

// ---------------------------------------------------------------------------
extern "C" void kernel_launch(void* const* d_in, const int* in_sizes, int n_in,
                              void* d_out, int out_size)
{
    (void)in_sizes; (void)n_in; (void)out_size;
    const float* x   = (const float*)d_in[0];
    const float* ctx = (const float*)d_in[1];
    const float* Wq  = (const float*)d_in[2];
    const float* bq  = (const float*)d_in[3];
    const float* Wk  = (const float*)d_in[4];
    const float* bk  = (const float*)d_in[5];
    const float* Wv  = (const float*)d_in[6];
    const float* bv  = (const float*)d_in[7];
    const float* Wo  = (const float*)d_in[8];
    const float* bo  = (const float*)d_in[9];
    const float* gq  = (const float*)d_in[10];
    const float* gk  = (const float*)d_in[11];
    float* out = (float*)d_out;

    cudaFuncSetAttribute(tf_gemm<1,0,1>, cudaFuncAttributeMaxDynamicSharedMemorySize, SMF);
    cudaFuncSetAttribute(tf_gemm<1,0,0>, cudaFuncAttributeMaxDynamicSharedMemorySize, SMF);
    cudaFuncSetAttribute(attn_fused, cudaFuncAttributeMaxDynamicSharedMemorySize, AF_SMB);

    float *wqt, *wkvt, *wot, *qf, *kvf, *vt, *atf, *bkv;
    cudaGetSymbolAddress((void**)&wqt,  g_wqt);
    cudaGetSymbolAddress((void**)&wkvt, g_wkvt);
    cudaGetSymbolAddress((void**)&wot,  g_wot);
    cudaGetSymbolAddress((void**)&qf,   g_qf);
    cudaGetSymbolAddress((void**)&kvf,  g_kvf);
    cudaGetSymbolAddress((void**)&vt,   g_vt);
    cudaGetSymbolAddress((void**)&atf,  g_atf);
    cudaGetSymbolAddress((void**)&bkv,  g_bkv);

    const long WKV = (long)C_DIM * CTXD;
    const long SKV = (long)S_KV * C_DIM;
    const float ATTN_SCALE = 0.08838834764831845f;   // 1/sqrt(128)

    // ---- weight transposes (tf32-rounded) ----------------------------------
    transT_kernel<<<dim3(C_DIM / 32, C_DIM / 32), 256>>>(Wq, wqt, C_DIM, C_DIM);
    transT_kernel<<<dim3(C_DIM / 32, CTXD / 32), 256>>>(Wk, wkvt, CTXD, C_DIM);
    transT_kernel<<<dim3(C_DIM / 32, CTXD / 32), 256>>>(Wv, wkvt + WKV, CTXD, C_DIM);
    transT_kernel<<<dim3(C_DIM / 32, C_DIM / 32), 256>>>(Wo, wot, C_DIM, C_DIM);
    concat_bias_kernel<<<C_DIM / 256, 256>>>(bk, bv, bkv);

    // ---- projections --------------------------------------------------------
    tf_gemm<1,0,1><<<dim3(16, 64, 1), 256, SMF>>>(x, C_DIM, 0, wqt, C_DIM, 0,
                                                  bq, 0, qf, C_DIM, 0, C_DIM);
    tf_gemm<1,0,1><<<dim3(16, 4, 2), 256, SMF>>>(ctx, CTXD, 0, wkvt, CTXD, WKV,
                                                 bkv, C_DIM, kvf, C_DIM, SKV, CTXD);

    // ---- norms / transposes -------------------------------------------------
    rmsnorm_kernel<<<L_Q, 256>>>(qf, gq, ATTN_SCALE);
    rmsnorm_kernel<<<S_KV, 256>>>(kvf, gk, 1.0f);
    transT_kernel<<<dim3(C_DIM / 32, S_KV / 32), 256>>>(kvf + SKV, vt, S_KV, C_DIM);

    // ---- fused attention ----------------------------------------------------
    attn_fused<<<dim3(L_Q / 64, NH), 256, AF_SMB>>>(qf, kvf, vt, atf);

    // ---- output projection --------------------------------------------------
    tf_gemm<1,0,0><<<dim3(16, 64, 1), 256, SMF>>>(atf, C_DIM, 0, wot, C_DIM, 0,
                                                  bo, 0, out, C_DIM, 0, C_DIM);
}

// round 11
// speedup vs baseline: 3.3428x; 1.0183x over previous
#include <cuda_runtime.h>
#include <cstdint>
#include <math.h>

// ===========================================================================
// WanCrossAttention  (B=1, L=8192, S=512, C=2048, CTX=4096, H=16, D=128)
// Round-11: TF32 pipeline, ldmatrix fragments +
//   - tf_gemm K-chunk 64 (3 stages): half the sync/wait boundaries
//   - 4 weight transposes merged into one launch
// Arithmetic bit-identical to round 10.
// ===========================================================================

#define L_Q   8192
#define S_KV  512
#define C_DIM 2048
#define CTXD  4096
#define NH    16
#define HD    128

// tf32 GEMM tiling: CTA 128x128, TK=64 fp32, 3-stage cp.async pipeline
#define RS2   68                     // smem row stride (words): 64 + 4 pad
#define RS2B  272
#define MT2   (128 * RS2B)           // 34816 B per matrix tile
#define STG2  (2 * MT2)              // 69632 B per stage (A, B)
#define SM2   (3 * STG2)             // 208896 B

// attn_fused smem layout (32-bit words) — unchanged from round 10
#define QRS    132
#define AF_QW  (64 * QRS)
#define AF_KW  (128 * QRS)
#define AF_VW  (128 * 68)
#define AF_PO  17408
#define AF_PRS 516
#define AF_RED 50432
#define AF_SMW 51456
#define AF_SMB (AF_SMW * 4)          // 205824 B

// ---------------- scratch ---------------------------------------------------
__device__ float g_wqt[C_DIM * C_DIM];
__device__ float g_wkvt[2 * C_DIM * CTXD];
__device__ float g_wot[C_DIM * C_DIM];
__device__ float g_qf[L_Q * C_DIM];
__device__ float g_kvf[2 * S_KV * C_DIM];
__device__ float g_vt[C_DIM * S_KV];
__device__ float g_atf[L_Q * C_DIM];
__device__ float g_bkv[2 * C_DIM];

// ---------------- asm helpers ----------------------------------------------
__device__ __forceinline__ uint32_t smem_u32(const void* p) {
    uint32_t a;
    asm("{ .reg .u64 t; cvta.to.shared.u64 t, %1; cvt.u32.u64 %0, t; }"
        : "=r"(a) : "l"(p));
    return a;
}
__device__ __forceinline__ float tf32r(float x) {
    uint32_t o;
    asm("cvt.rna.tf32.f32 %0, %1;" : "=r"(o) : "f"(x));
    return __uint_as_float(o);
}
__device__ __forceinline__ uint32_t tf32rb(uint32_t x) {
    uint32_t o;
    asm("cvt.rna.tf32.f32 %0, %1;" : "=r"(o) : "f"(__uint_as_float(x)));
    return o;
}
__device__ __forceinline__ void ldsm_x4(uint32_t* r, uint32_t addr) {
    asm volatile("ldmatrix.sync.aligned.m8n8.x4.shared.b16 {%0,%1,%2,%3}, [%4];"
                 : "=r"(r[0]), "=r"(r[1]), "=r"(r[2]), "=r"(r[3]) : "r"(addr));
}
__device__ __forceinline__ void mma_tf32(float* c, uint32_t a0, uint32_t a1,
                                         uint32_t a2, uint32_t a3,
                                         uint32_t b0, uint32_t b1) {
    asm volatile(
        "mma.sync.aligned.m16n8k8.row.col.f32.tf32.tf32.f32 "
        "{%0,%1,%2,%3}, {%4,%5,%6,%7}, {%8,%9}, {%0,%1,%2,%3};"
        : "+f"(c[0]), "+f"(c[1]), "+f"(c[2]), "+f"(c[3])
        : "r"(a0), "r"(a1), "r"(a2), "r"(a3), "r"(b0), "r"(b1));
}
#define CP_ASYNC16(dst, src) \
    asm volatile("cp.async.cg.shared.global [%0], [%1], 16;" :: "r"(dst), "l"(src))
#define CP_COMMIT() asm volatile("cp.async.commit_group;" ::: "memory")
#define CP_WAITG(n) asm volatile("cp.async.wait_group %0;" :: "n"(n) : "memory")

// ---------------------------------------------------------------------------
// TF32 GEMM, K-chunk 64, 3-stage pipeline, ldmatrix fragment loads.
// K % 64 == 0, K/64 >= 2.
// ---------------------------------------------------------------------------
template <int BIASMODE, int ROUND, int RNDA>
__global__ __launch_bounds__(256, 1)
void tf_gemm(const float* __restrict__ A, int lda, long sA,
             const float* __restrict__ B, int ldb, long sB,
             const float* __restrict__ bias, long sBias,
             float* __restrict__ C, int ldc, long sC, int K)
{
    extern __shared__ char smem[];
    const uint32_t sb = smem_u32(smem);
    const int tid = threadIdx.x, wid = tid >> 5, lid = tid & 31;
    const int m0 = blockIdx.y * 128, n0 = blockIdx.x * 128;

    if (BIASMODE != 0) bias += (long)blockIdx.z * sBias;
    const float* Ab = A + (long)blockIdx.z * sA + (long)m0 * lda;
    const float* Bb = B + (long)blockIdx.z * sB + (long)n0 * ldb;

    // loader: 4096 16B chunks per stage (A:2048, B:2048), 16 per thread
    const float* gp[16];
    uint32_t so[16];
#pragma unroll
    for (int i = 0; i < 16; ++i) {
        const int idx = i * 256 + tid;
        const int mat = idx >> 11;            // 0 = A, 1 = B
        const int row = (idx >> 4) & 127;
        const int ch  = idx & 15;             // 16B chunk within 256B row
        gp[i] = (mat ? Bb : Ab) + (long)row * (mat ? ldb : lda) + ch * 4;
        so[i] = (uint32_t)(mat * MT2 + row * RS2B + ch * 16);
    }

#define ISSUE_STAGE(stage, kidx) do {                                  \
        const uint32_t _db = sb + (uint32_t)(stage) * STG2;            \
        const long _go = (long)(kidx) * 64;                            \
        _Pragma("unroll")                                              \
        for (int _i = 0; _i < 16; ++_i)                                \
            CP_ASYNC16(_db + so[_i], gp[_i] + _go);                    \
    } while (0)

    // ldmatrix thread offsets (words within a stage)
    const int lm = lid >> 3, lr8 = lid & 7;
    const int wm = wid >> 2, wn = wid & 3;
    const uint32_t aoff = (uint32_t)((lr8 + 8 * (lm & 1)) * RS2 + 4 * (lm >> 1));
    const uint32_t boff = (uint32_t)((lr8 + 8 * (lm >> 1)) * RS2 + 4 * (lm & 1));
    const uint32_t fA = (uint32_t)((wm * 64) * RS2) + aoff;
    const uint32_t fB = (uint32_t)(MT2 / 4 + (wn * 32) * RS2) + boff;

    float acc[4][4][4];
#pragma unroll
    for (int i = 0; i < 4; ++i)
#pragma unroll
        for (int j = 0; j < 4; ++j)
#pragma unroll
            for (int q = 0; q < 4; ++q) acc[i][j][q] = 0.f;

    const int nch = K >> 6;

    ISSUE_STAGE(0, 0); CP_COMMIT();
    ISSUE_STAGE(1, 1); CP_COMMIT();

    int buf = 0;
    for (int c = 0; c < nch; ++c) {
        CP_WAITG(1);
        __syncthreads();
        if (c + 2 < nch) {
            int nb = buf + 2; if (nb >= 3) nb -= 3;
            ISSUE_STAGE(nb, c + 2);
        }
        CP_COMMIT();

        const uint32_t base = ((uint32_t)buf * STG2) >> 2;
#pragma unroll
        for (int s = 0; s < 8; ++s) {
            const uint32_t ko = s * 8;
            uint32_t a[4][4], b[2][4];
#pragma unroll
            for (int mt = 0; mt < 4; ++mt) {
                ldsm_x4(a[mt], sb + (base + fA + mt * (16 * RS2) + ko) * 4);
                if (RNDA) {
#pragma unroll
                    for (int q = 0; q < 4; ++q) a[mt][q] = tf32rb(a[mt][q]);
                }
            }
#pragma unroll
            for (int np = 0; np < 2; ++np)
                ldsm_x4(b[np], sb + (base + fB + np * (16 * RS2) + ko) * 4);
#pragma unroll
            for (int mt = 0; mt < 4; ++mt)
#pragma unroll
                for (int nt = 0; nt < 4; ++nt) {
                    const int np = nt >> 1, e = (nt & 1) * 2;
                    mma_tf32(acc[mt][nt], a[mt][0], a[mt][1], a[mt][2], a[mt][3],
                             b[np][e], b[np][e + 1]);
                }
        }
        if (++buf == 3) buf = 0;
    }
#undef ISSUE_STAGE

    float* Cp = C + (long)blockIdx.z * sC;
    const int row_base = m0 + wm * 64;
    const int col_base = n0 + wn * 32;
    const int lr = lid >> 2, lc = (lid & 3) * 2;
#pragma unroll
    for (int mt = 0; mt < 4; ++mt) {
        const int r0 = row_base + mt * 16 + lr;
#pragma unroll
        for (int nt = 0; nt < 4; ++nt) {
            const int cix = col_base + nt * 8 + lc;
            float b0 = 0.f, b1 = 0.f;
            if (BIASMODE == 1) { b0 = bias[cix]; b1 = bias[cix + 1]; }
            float v00 = acc[mt][nt][0] + b0, v01 = acc[mt][nt][1] + b1;
            float v10 = acc[mt][nt][2] + b0, v11 = acc[mt][nt][3] + b1;
            if (ROUND) {
                v00 = tf32r(v00); v01 = tf32r(v01);
                v10 = tf32r(v10); v11 = tf32r(v11);
            }
            *(float2*)(Cp + (long)r0 * ldc + cix)       = make_float2(v00, v01);
            *(float2*)(Cp + (long)(r0 + 8) * ldc + cix) = make_float2(v10, v11);
        }
    }
}

// ---------------------------------------------------------------------------
// Fused attention (round-10 version, unchanged).
// ---------------------------------------------------------------------------
__global__ __launch_bounds__(256, 1)
void attn_fused(const float* __restrict__ Q, const float* __restrict__ Km,
                const float* __restrict__ Vt, float* __restrict__ O)
{
    extern __shared__ char smem[];
    const uint32_t sb = smem_u32(smem);
    float* sf = (float*)smem;
    float* redmx = sf + AF_RED;
    float* redsm = redmx + 512;

    const int tid = threadIdx.x, wid = tid >> 5, lid = tid & 31;
    const int g4 = lid >> 2, t4 = lid & 3;
    const int lm = lid >> 3, lr8 = lid & 7;
    const int m0 = blockIdx.x * 64;
    const int z  = blockIdx.y;

    const float* Qg = Q + (long)z * HD + (long)m0 * C_DIM;
    const float* Kg = Km + (long)z * HD;
    const float* Vg = Vt + (long)z * HD * S_KV;

    const uint32_t aoffQ = (uint32_t)((lr8 + 8 * (lm & 1)) * QRS + 4 * (lm >> 1));
    const uint32_t boffK = (uint32_t)((lr8 + 8 * (lm >> 1)) * QRS + 4 * (lm & 1));
    const uint32_t aoffP = (uint32_t)((lr8 + 8 * (lm & 1)) * AF_PRS + 4 * (lm >> 1));
    const uint32_t boffV = (uint32_t)((lr8 + 8 * (lm >> 1)) * 68 + 4 * (lm & 1));

    {
#pragma unroll
        for (int i = 0; i < 8; ++i) {
            const int idx = i * 256 + tid;
            const int row = idx >> 5, ch = idx & 31;
            CP_ASYNC16(sb + (uint32_t)(row * QRS + ch * 4) * 4,
                       Qg + (long)row * C_DIM + ch * 4);
        }
#pragma unroll
        for (int i = 0; i < 16; ++i) {
            const int idx = i * 256 + tid;
            const int row = idx >> 5, ch = idx & 31;
            CP_ASYNC16(sb + (uint32_t)(AF_QW + row * QRS + ch * 4) * 4,
                       Kg + (long)row * C_DIM + ch * 4);
        }
        CP_COMMIT();
#pragma unroll
        for (int i = 0; i < 16; ++i) {
            const int idx = i * 256 + tid;
            const int row = idx >> 5, ch = idx & 31;
            CP_ASYNC16(sb + (uint32_t)(AF_QW + AF_KW + row * QRS + ch * 4) * 4,
                       Kg + (long)(128 + row) * C_DIM + ch * 4);
        }
        CP_COMMIT();
    }

    float acc[4][8][4];
#pragma unroll
    for (int i = 0; i < 4; ++i)
#pragma unroll
        for (int j = 0; j < 8; ++j)
#pragma unroll
            for (int q = 0; q < 4; ++q) acc[i][j][q] = 0.f;

#pragma unroll
    for (int c = 0; c < 4; ++c) {
        if (c < 3) { CP_WAITG(1); } else { CP_WAITG(0); }
        __syncthreads();

        const uint32_t kb = (uint32_t)(AF_QW + (c & 1) * AF_KW);
#pragma unroll
        for (int ks = 0; ks < 16; ++ks) {
            uint32_t a[4][4], b[4];
#pragma unroll
            for (int mt = 0; mt < 4; ++mt)
                ldsm_x4(a[mt], sb + (uint32_t)((16 * mt) * QRS + 8 * ks + aoffQ) * 4);
            ldsm_x4(b, sb + (kb + (uint32_t)((wid * 16) * QRS + 8 * ks) + boffK) * 4);
#pragma unroll
            for (int nt = 0; nt < 2; ++nt) {
                const uint32_t b0 = b[nt * 2], b1 = b[nt * 2 + 1];
#pragma unroll
                for (int mt = 0; mt < 4; ++mt)
                    mma_tf32(acc[mt][2 * c + nt],
                             a[mt][0], a[mt][1], a[mt][2], a[mt][3], b0, b1);
            }
        }
        __syncthreads();
        if (c + 2 < 4) {
            const uint32_t kb2 = (uint32_t)(AF_QW + (c & 1) * AF_KW);
#pragma unroll
            for (int i = 0; i < 16; ++i) {
                const int idx = i * 256 + tid;
                const int row = idx >> 5, ch = idx & 31;
                CP_ASYNC16(sb + (kb2 + (uint32_t)(row * QRS + ch * 4)) * 4,
                           Kg + (long)((c + 2) * 128 + row) * C_DIM + ch * 4);
            }
            CP_COMMIT();
        }
    }

#pragma unroll
    for (int b = 0; b < 2; ++b) {
#pragma unroll
        for (int i = 0; i < 8; ++i) {
            const int idx = i * 256 + tid;
            const int row = idx >> 4, ch = idx & 15;
            CP_ASYNC16(sb + (uint32_t)(b * AF_VW + row * 68 + ch * 4) * 4,
                       Vg + (long)row * S_KV + b * 64 + ch * 4);
        }
        CP_COMMIT();
    }

    float gm[4][2];
#pragma unroll
    for (int mt = 0; mt < 4; ++mt)
#pragma unroll
        for (int h = 0; h < 2; ++h) {
            float m = -1e30f;
#pragma unroll
            for (int j = 0; j < 8; ++j)
                m = fmaxf(m, fmaxf(acc[mt][j][2 * h], acc[mt][j][2 * h + 1]));
            m = fmaxf(m, __shfl_xor_sync(0xffffffffu, m, 1));
            m = fmaxf(m, __shfl_xor_sync(0xffffffffu, m, 2));
            if (t4 == 0) redmx[(16 * mt + 8 * h + g4) * 8 + wid] = m;
            gm[mt][h] = m;
        }
    __syncthreads();
#pragma unroll
    for (int mt = 0; mt < 4; ++mt)
#pragma unroll
        for (int h = 0; h < 2; ++h) {
            const int row = 16 * mt + 8 * h + g4;
            float m = gm[mt][h];
#pragma unroll
            for (int w = 0; w < 8; ++w) m = fmaxf(m, redmx[row * 8 + w]);
            gm[mt][h] = m;
        }
    float gs[4][2];
#pragma unroll
    for (int mt = 0; mt < 4; ++mt)
#pragma unroll
        for (int h = 0; h < 2; ++h) {
            float s = 0.f;
            const float m = gm[mt][h];
#pragma unroll
            for (int j = 0; j < 8; ++j) {
                float e0 = __expf(acc[mt][j][2 * h] - m);
                float e1 = __expf(acc[mt][j][2 * h + 1] - m);
                acc[mt][j][2 * h] = e0; acc[mt][j][2 * h + 1] = e1;
                s += e0 + e1;
            }
            s += __shfl_xor_sync(0xffffffffu, s, 1);
            s += __shfl_xor_sync(0xffffffffu, s, 2);
            if (t4 == 0) redsm[(16 * mt + 8 * h + g4) * 8 + wid] = s;
        }
    __syncthreads();
#pragma unroll
    for (int mt = 0; mt < 4; ++mt)
#pragma unroll
        for (int h = 0; h < 2; ++h) {
            const int row = 16 * mt + 8 * h + g4;
            float s = 0.f;
#pragma unroll
            for (int w = 0; w < 8; ++w) s += redsm[row * 8 + w];
            gs[mt][h] = 1.0f / s;
        }

#pragma unroll
    for (int mt = 0; mt < 4; ++mt)
#pragma unroll
        for (int h = 0; h < 2; ++h) {
            const int row = 16 * mt + 8 * h + g4;
            const float inv = gs[mt][h];
#pragma unroll
            for (int j = 0; j < 8; ++j) {
                const int col = 128 * (j >> 1) + wid * 16 + 8 * (j & 1) + 2 * t4;
                *(float2*)(sf + AF_PO + (uint32_t)(row * AF_PRS + col)) =
                    make_float2(tf32r(acc[mt][j][2 * h] * inv),
                                tf32r(acc[mt][j][2 * h + 1] * inv));
            }
        }
    __syncthreads();

    const int pwm = wid & 1, pwn = wid >> 1;
    float accP[2][4][4];
#pragma unroll
    for (int i = 0; i < 2; ++i)
#pragma unroll
        for (int j = 0; j < 4; ++j)
#pragma unroll
            for (int q = 0; q < 4; ++q) accP[i][j][q] = 0.f;

#pragma unroll
    for (int c = 0; c < 8; ++c) {
        if (c < 7) { CP_WAITG(1); } else { CP_WAITG(0); }
        __syncthreads();

        const uint32_t vb = (uint32_t)((c & 1) * AF_VW);
#pragma unroll
        for (int ks = 0; ks < 8; ++ks) {
            uint32_t a[2][4], b[2][4];
#pragma unroll
            for (int mt = 0; mt < 2; ++mt)
                ldsm_x4(a[mt], sb + (uint32_t)(AF_PO + (32 * pwm + 16 * mt) * AF_PRS
                                               + 64 * c + 8 * ks + aoffP) * 4);
#pragma unroll
            for (int np = 0; np < 2; ++np)
                ldsm_x4(b[np], sb + (vb + (uint32_t)((32 * pwn + 16 * np) * 68
                                                     + 8 * ks) + boffV) * 4);
#pragma unroll
            for (int nt = 0; nt < 4; ++nt) {
                const int np = nt >> 1, e = (nt & 1) * 2;
#pragma unroll
                for (int mt = 0; mt < 2; ++mt)
                    mma_tf32(accP[mt][nt],
                             a[mt][0], a[mt][1], a[mt][2], a[mt][3],
                             b[np][e], b[np][e + 1]);
            }
        }
        __syncthreads();
        if (c + 2 < 8) {
            const uint32_t vb2 = (uint32_t)((c & 1) * AF_VW);
#pragma unroll
            for (int i = 0; i < 8; ++i) {
                const int idx = i * 256 + tid;
                const int row = idx >> 4, ch = idx & 15;
                CP_ASYNC16(sb + (vb2 + (uint32_t)(row * 68 + ch * 4)) * 4,
                           Vg + (long)row * S_KV + (c + 2) * 64 + ch * 4);
            }
            CP_COMMIT();
        }
    }

    float* Og = O + (long)m0 * C_DIM + (long)z * HD;
    const int lr = lid >> 2, lc = (lid & 3) * 2;
#pragma unroll
    for (int mt = 0; mt < 2; ++mt) {
        const int r0 = 32 * pwm + 16 * mt + lr;
#pragma unroll
        for (int nt = 0; nt < 4; ++nt) {
            const int cix = 32 * pwn + 8 * nt + lc;
            *(float2*)(Og + (long)r0 * C_DIM + cix) =
                make_float2(tf32r(accP[mt][nt][0]), tf32r(accP[mt][nt][1]));
            *(float2*)(Og + (long)(r0 + 8) * C_DIM + cix) =
                make_float2(tf32r(accP[mt][nt][2]), tf32r(accP[mt][nt][3]));
        }
    }
}

// ---------------------------------------------------------------------------
// elementwise helpers
// ---------------------------------------------------------------------------
__device__ __forceinline__ void transT_body(const float* __restrict__ W,
                                            float* __restrict__ out,
                                            int Kd, int Nd, int bx, int by,
                                            int tidx)
{
    __shared__ float t[32][33];
    const int k0 = by * 32, n0 = bx * 32;
    const int tx = tidx & 31, ty = tidx >> 5;
#pragma unroll
    for (int r = 0; r < 4; ++r)
        t[ty + 8 * r][tx] = W[(long)(k0 + ty + 8 * r) * Nd + n0 + tx];
    __syncthreads();
#pragma unroll
    for (int r = 0; r < 4; ++r)
        out[(long)(n0 + ty + 8 * r) * Kd + k0 + tx] = tf32r(t[tx][ty + 8 * r]);
}

// all 4 weight transposes in one launch: grid (64, 384)
__global__ __launch_bounds__(256)
void transT4_kernel(const float* __restrict__ Wq, const float* __restrict__ Wk,
                    const float* __restrict__ Wv, const float* __restrict__ Wo,
                    float* __restrict__ wqt, float* __restrict__ wkvt,
                    float* __restrict__ wot)
{
    const int by = blockIdx.y;
    if (by < 64)
        transT_body(Wq, wqt, C_DIM, C_DIM, blockIdx.x, by, threadIdx.x);
    else if (by < 192)
        transT_body(Wk, wkvt, CTXD, C_DIM, blockIdx.x, by - 64, threadIdx.x);
    else if (by < 320)
        transT_body(Wv, wkvt + (long)C_DIM * CTXD, CTXD, C_DIM,
                    blockIdx.x, by - 192, threadIdx.x);
    else
        transT_body(Wo, wot, C_DIM, C_DIM, blockIdx.x, by - 320, threadIdx.x);
}

__global__ __launch_bounds__(256)
void transT_kernel(const float* __restrict__ W, float* __restrict__ out,
                   int Kd, int Nd)
{
    transT_body(W, out, Kd, Nd, blockIdx.x, blockIdx.y, threadIdx.x);
}

__global__ void concat_bias_kernel(const float* __restrict__ bk,
                                   const float* __restrict__ bv,
                                   float* __restrict__ o)
{
    int i = blockIdx.x * 256 + threadIdx.x;
    o[i] = bk[i];
    o[C_DIM + i] = bv[i];
}

__global__ __launch_bounds__(256)
void rmsnorm_kernel(float* __restrict__ buf, const float* __restrict__ g, float scale)
{
    float* row = buf + (long)blockIdx.x * C_DIM;
    const int t = threadIdx.x;
    float4 v0 = *(float4*)(row + t * 4);
    float4 v1 = *(float4*)(row + 1024 + t * 4);
    float ss = v0.x * v0.x + v0.y * v0.y + v0.z * v0.z + v0.w * v0.w
             + v1.x * v1.x + v1.y * v1.y + v1.z * v1.z + v1.w * v1.w;
#pragma unroll
    for (int o = 16; o > 0; o >>= 1) ss += __shfl_xor_sync(0xffffffffu, ss, o);
    __shared__ float ws[8]; __shared__ float s_inv;
    if ((t & 31) == 0) ws[t >> 5] = ss;
    __syncthreads();
    if (t == 0) {
        float s = 0.f;
#pragma unroll
        for (int i = 0; i < 8; ++i) s += ws[i];
        s_inv = rsqrtf(s * (1.0f / C_DIM) + 1e-6f) * scale;
    }
    __syncthreads();
    const float inv = s_inv;
    float4 w0 = *(const float4*)(g + t * 4);
    float4 w1 = *(const float4*)(g + 1024 + t * 4);
    *(float4*)(row + t * 4) = make_float4(
        tf32r(v0.x * inv * w0.x), tf32r(v0.y * inv * w0.y),
        tf32r(v0.z * inv * w0.z), tf32r(v0.w * inv * w0.w));
    *(float4*)(row + 1024 + t * 4) = make_float4(
        tf32r(v1.x * inv * w1.x), tf32r(v1.y * inv * w1.y),
        tf32r(v1.z * inv * w1.z), tf32r(v1.w * inv * w1.w));
}

// ---------------------------------------------------------------------------
extern "C" void kernel_launch(void* const* d_in, const int* in_sizes, int n_in,
                              void* d_out, int out_size)
{
    (void)in_sizes; (void)n_in; (void)out_size;
    const float* x   = (const float*)d_in[0];
    const float* ctx = (const float*)d_in[1];
    const float* Wq  = (const float*)d_in[2];
    const float* bq  = (const float*)d_in[3];
    const float* Wk  = (const float*)d_in[4];
    const float* bk  = (const float*)d_in[5];
    const float* Wv  = (const float*)d_in[6];
    const float* bv  = (const float*)d_in[7];
    const float* Wo  = (const float*)d_in[8];
    const float* bo  = (const float*)d_in[9];
    const float* gq  = (const float*)d_in[10];
    const float* gk  = (const float*)d_in[11];
    float* out = (float*)d_out;

    cudaFuncSetAttribute(tf_gemm<1,0,1>, cudaFuncAttributeMaxDynamicSharedMemorySize, SM2);
    cudaFuncSetAttribute(tf_gemm<1,0,0>, cudaFuncAttributeMaxDynamicSharedMemorySize, SM2);
    cudaFuncSetAttribute(attn_fused, cudaFuncAttributeMaxDynamicSharedMemorySize, AF_SMB);

    float *wqt, *wkvt, *wot, *qf, *kvf, *vt, *atf, *bkv;
    cudaGetSymbolAddress((void**)&wqt,  g_wqt);
    cudaGetSymbolAddress((void**)&wkvt, g_wkvt);
    cudaGetSymbolAddress((void**)&wot,  g_wot);
    cudaGetSymbolAddress((void**)&qf,   g_qf);
    cudaGetSymbolAddress((void**)&kvf,  g_kvf);
    cudaGetSymbolAddress((void**)&vt,   g_vt);
    cudaGetSymbolAddress((void**)&atf,  g_atf);
    cudaGetSymbolAddress((void**)&bkv,  g_bkv);

    const long WKV = (long)C_DIM * CTXD;
    const long SKV = (long)S_KV * C_DIM;
    const float ATTN_SCALE = 0.08838834764831845f;   // 1/sqrt(128)

    // ---- weight transposes (merged) + bias concat --------------------------
    transT4_kernel<<<dim3(64, 384), 256>>>(Wq, Wk, Wv, Wo, wqt, wkvt, wot);
    concat_bias_kernel<<<C_DIM / 256, 256>>>(bk, bv, bkv);

    // ---- projections --------------------------------------------------------
    tf_gemm<1,0,1><<<dim3(16, 64, 1), 256, SM2>>>(x, C_DIM, 0, wqt, C_DIM, 0,
                                                  bq, 0, qf, C_DIM, 0, C_DIM);
    tf_gemm<1,0,1><<<dim3(16, 4, 2), 256, SM2>>>(ctx, CTXD, 0, wkvt, CTXD, WKV,
                                                 bkv, C_DIM, kvf, C_DIM, SKV, CTXD);

    // ---- norms / transposes -------------------------------------------------
    rmsnorm_kernel<<<L_Q, 256>>>(qf, gq, ATTN_SCALE);
    rmsnorm_kernel<<<S_KV, 256>>>(kvf, gk, 1.0f);
    transT_kernel<<<dim3(C_DIM / 32, S_KV / 32), 256>>>(kvf + SKV, vt, S_KV, C_DIM);

    // ---- fused attention ----------------------------------------------------
    attn_fused<<<dim3(L_Q / 64, NH), 256, AF_SMB>>>(qf, kvf, vt, atf);

    // ---- output projection --------------------------------------------------
    tf_gemm<1,0,0><<<dim3(16, 64, 1), 256, SM2>>>(atf, C_DIM, 0, wot, C_DIM, 0,
                                                  bo, 0, out, C_DIM, 0, C_DIM);
}

// round 12
// speedup vs baseline: 3.7009x; 1.1071x over previous
#include <cuda_runtime.h>
#include <cstdint>
#include <math.h>

// ===========================================================================
// WanCrossAttention  (B=1, L=8192, S=512, C=2048, CTX=4096, H=16, D=128)
// Round-12: TF32 pipeline; tf_gemm reworked for 2 CTAs/SM:
//   K-chunk 32, 3 stages (108 KB smem), __launch_bounds__(256,2) (<=128 regs),
//   pointer state compressed to 2 bases + 32-bit offsets.
// ncu R11 showed tf_gemm at occ=12.5%, tensor=42.9% -> occupancy-bound.
// Arithmetic bit-identical to rounds 9-11.
// ===========================================================================

#define L_Q   8192
#define S_KV  512
#define C_DIM 2048
#define CTXD  4096
#define NH    16
#define HD    128

// tf32 GEMM tiling: CTA 128x128, TK=32 fp32, 3-stage cp.async pipeline
#define RS3   36                     // smem row stride (words): 32 + 4 pad
#define RS3B  144
#define MT3   (128 * RS3B)           // 18432 B per matrix tile
#define STG3  (2 * MT3)              // 36864 B per stage (A, B)
#define SM3   (3 * STG3)             // 110592 B  -> 2 CTAs/SM

// attn_fused smem layout (unchanged)
#define QRS    132
#define AF_QW  (64 * QRS)
#define AF_KW  (128 * QRS)
#define AF_VW  (128 * 68)
#define AF_PO  17408
#define AF_PRS 516
#define AF_RED 50432
#define AF_SMW 51456
#define AF_SMB (AF_SMW * 4)          // 205824 B

// ---------------- scratch ---------------------------------------------------
__device__ float g_wqt[C_DIM * C_DIM];
__device__ float g_wkvt[2 * C_DIM * CTXD];
__device__ float g_wot[C_DIM * C_DIM];
__device__ float g_qf[L_Q * C_DIM];
__device__ float g_kvf[2 * S_KV * C_DIM];
__device__ float g_vt[C_DIM * S_KV];
__device__ float g_atf[L_Q * C_DIM];
__device__ float g_bkv[2 * C_DIM];

// ---------------- asm helpers ----------------------------------------------
__device__ __forceinline__ uint32_t smem_u32(const void* p) {
    uint32_t a;
    asm("{ .reg .u64 t; cvta.to.shared.u64 t, %1; cvt.u32.u64 %0, t; }"
        : "=r"(a) : "l"(p));
    return a;
}
__device__ __forceinline__ float tf32r(float x) {
    uint32_t o;
    asm("cvt.rna.tf32.f32 %0, %1;" : "=r"(o) : "f"(x));
    return __uint_as_float(o);
}
__device__ __forceinline__ uint32_t tf32rb(uint32_t x) {
    uint32_t o;
    asm("cvt.rna.tf32.f32 %0, %1;" : "=r"(o) : "f"(__uint_as_float(x)));
    return o;
}
__device__ __forceinline__ void ldsm_x4(uint32_t* r, uint32_t addr) {
    asm volatile("ldmatrix.sync.aligned.m8n8.x4.shared.b16 {%0,%1,%2,%3}, [%4];"
                 : "=r"(r[0]), "=r"(r[1]), "=r"(r[2]), "=r"(r[3]) : "r"(addr));
}
__device__ __forceinline__ void mma_tf32(float* c, uint32_t a0, uint32_t a1,
                                         uint32_t a2, uint32_t a3,
                                         uint32_t b0, uint32_t b1) {
    asm volatile(
        "mma.sync.aligned.m16n8k8.row.col.f32.tf32.tf32.f32 "
        "{%0,%1,%2,%3}, {%4,%5,%6,%7}, {%8,%9}, {%0,%1,%2,%3};"
        : "+f"(c[0]), "+f"(c[1]), "+f"(c[2]), "+f"(c[3])
        : "r"(a0), "r"(a1), "r"(a2), "r"(a3), "r"(b0), "r"(b1));
}
#define CP_ASYNC16(dst, src) \
    asm volatile("cp.async.cg.shared.global [%0], [%1], 16;" :: "r"(dst), "l"(src))
#define CP_COMMIT() asm volatile("cp.async.commit_group;" ::: "memory")
#define CP_WAITG(n) asm volatile("cp.async.wait_group %0;" :: "n"(n) : "memory")

// ---------------------------------------------------------------------------
// TF32 GEMM, K-chunk 32, 3-stage pipeline, 2 CTAs/SM.
// K % 32 == 0, K/32 >= 2.
// ---------------------------------------------------------------------------
template <int BIASMODE, int ROUND, int RNDA>
__global__ __launch_bounds__(256, 2)
void tf_gemm(const float* __restrict__ A, int lda, long sA,
             const float* __restrict__ B, int ldb, long sB,
             const float* __restrict__ bias, long sBias,
             float* __restrict__ C, int ldc, long sC, int K)
{
    extern __shared__ char smem[];
    const uint32_t sb = smem_u32(smem);
    const int tid = threadIdx.x, wid = tid >> 5, lid = tid & 31;
    const int m0 = blockIdx.y * 128, n0 = blockIdx.x * 128;

    const float* Ab = A + (long)blockIdx.z * sA + (long)m0 * lda;
    const float* Bb = B + (long)blockIdx.z * sB + (long)n0 * ldb;

    // loader: 2048 16B chunks per stage (A:1024, B:1024), 8 per thread.
    // i<4 -> A, i>=4 -> B (compile-time). 32-bit element offsets save regs.
    uint32_t goff[8], so[8];
#pragma unroll
    for (int i = 0; i < 8; ++i) {
        const int idx = i * 256 + tid;
        const int row = (idx >> 3) & 127;
        const int ch  = idx & 7;
        goff[i] = (uint32_t)(row * ((i < 4) ? lda : ldb) + ch * 4);
        so[i] = (uint32_t)(((i < 4) ? 0 : MT3) + row * RS3B + ch * 16);
    }

#define ISSUE_STAGE(stage, kidx) do {                                       \
        const uint32_t _db = sb + (uint32_t)(stage) * STG3;                 \
        const uint32_t _go = (uint32_t)(kidx) * 32;                         \
        _Pragma("unroll")                                                   \
        for (int _i = 0; _i < 4; ++_i)                                      \
            CP_ASYNC16(_db + so[_i], Ab + goff[_i] + _go);                  \
        _Pragma("unroll")                                                   \
        for (int _i = 4; _i < 8; ++_i)                                      \
            CP_ASYNC16(_db + so[_i], Bb + goff[_i] + _go);                  \
    } while (0)

    // ldmatrix thread offsets (words within a stage)
    const int lm = lid >> 3, lr8 = lid & 7;
    const int wm = wid >> 2, wn = wid & 3;
    const uint32_t fA = (uint32_t)((wm * 64 + lr8 + 8 * (lm & 1)) * RS3
                                   + 4 * (lm >> 1));
    const uint32_t fB = (uint32_t)(MT3 / 4 + (wn * 32 + lr8 + 8 * (lm >> 1)) * RS3
                                   + 4 * (lm & 1));

    float acc[4][4][4];
#pragma unroll
    for (int i = 0; i < 4; ++i)
#pragma unroll
        for (int j = 0; j < 4; ++j)
#pragma unroll
            for (int q = 0; q < 4; ++q) acc[i][j][q] = 0.f;

    const int nch = K >> 5;

    ISSUE_STAGE(0, 0); CP_COMMIT();
    ISSUE_STAGE(1, 1); CP_COMMIT();

    int buf = 0;
    for (int c = 0; c < nch; ++c) {
        CP_WAITG(1);
        __syncthreads();
        if (c + 2 < nch) {
            int nb = buf + 2; if (nb >= 3) nb -= 3;
            ISSUE_STAGE(nb, c + 2);
        }
        CP_COMMIT();

        const uint32_t base = ((uint32_t)buf * STG3) >> 2;
#pragma unroll
        for (int s = 0; s < 4; ++s) {
            const uint32_t ko = s * 8;
            uint32_t a[4][4], b[2][4];
#pragma unroll
            for (int mt = 0; mt < 4; ++mt) {
                ldsm_x4(a[mt], sb + (base + fA + mt * (16 * RS3) + ko) * 4);
                if (RNDA) {
#pragma unroll
                    for (int q = 0; q < 4; ++q) a[mt][q] = tf32rb(a[mt][q]);
                }
            }
#pragma unroll
            for (int np = 0; np < 2; ++np)
                ldsm_x4(b[np], sb + (base + fB + np * (16 * RS3) + ko) * 4);
#pragma unroll
            for (int mt = 0; mt < 4; ++mt)
#pragma unroll
                for (int nt = 0; nt < 4; ++nt) {
                    const int np = nt >> 1, e = (nt & 1) * 2;
                    mma_tf32(acc[mt][nt], a[mt][0], a[mt][1], a[mt][2], a[mt][3],
                             b[np][e], b[np][e + 1]);
                }
        }
        if (++buf == 3) buf = 0;
        __syncthreads();
    }
#undef ISSUE_STAGE

    const float* bp = (BIASMODE != 0) ? (bias + (long)blockIdx.z * sBias) : bias;
    float* Cp = C + (long)blockIdx.z * sC;
    const int row_base = m0 + wm * 64;
    const int col_base = n0 + wn * 32;
    const int lr = lid >> 2, lc = (lid & 3) * 2;
#pragma unroll
    for (int mt = 0; mt < 4; ++mt) {
        const int r0 = row_base + mt * 16 + lr;
#pragma unroll
        for (int nt = 0; nt < 4; ++nt) {
            const int cix = col_base + nt * 8 + lc;
            float b0 = 0.f, b1 = 0.f;
            if (BIASMODE == 1) { b0 = bp[cix]; b1 = bp[cix + 1]; }
            float v00 = acc[mt][nt][0] + b0, v01 = acc[mt][nt][1] + b1;
            float v10 = acc[mt][nt][2] + b0, v11 = acc[mt][nt][3] + b1;
            if (ROUND) {
                v00 = tf32r(v00); v01 = tf32r(v01);
                v10 = tf32r(v10); v11 = tf32r(v11);
            }
            *(float2*)(Cp + (long)r0 * ldc + cix)       = make_float2(v00, v01);
            *(float2*)(Cp + (long)(r0 + 8) * ldc + cix) = make_float2(v10, v11);
        }
    }
}

// ---------------------------------------------------------------------------
// Fused attention (unchanged from round 10/11).
// ---------------------------------------------------------------------------
__global__ __launch_bounds__(256, 1)
void attn_fused(const float* __restrict__ Q, const float* __restrict__ Km,
                const float* __restrict__ Vt, float* __restrict__ O)
{
    extern __shared__ char smem[];
    const uint32_t sb = smem_u32(smem);
    float* sf = (float*)smem;
    float* redmx = sf + AF_RED;
    float* redsm = redmx + 512;

    const int tid = threadIdx.x, wid = tid >> 5, lid = tid & 31;
    const int g4 = lid >> 2, t4 = lid & 3;
    const int lm = lid >> 3, lr8 = lid & 7;
    const int m0 = blockIdx.x * 64;
    const int z  = blockIdx.y;

    const float* Qg = Q + (long)z * HD + (long)m0 * C_DIM;
    const float* Kg = Km + (long)z * HD;
    const float* Vg = Vt + (long)z * HD * S_KV;

    const uint32_t aoffQ = (uint32_t)((lr8 + 8 * (lm & 1)) * QRS + 4 * (lm >> 1));
    const uint32_t boffK = (uint32_t)((lr8 + 8 * (lm >> 1)) * QRS + 4 * (lm & 1));
    const uint32_t aoffP = (uint32_t)((lr8 + 8 * (lm & 1)) * AF_PRS + 4 * (lm >> 1));
    const uint32_t boffV = (uint32_t)((lr8 + 8 * (lm >> 1)) * 68 + 4 * (lm & 1));

    {
#pragma unroll
        for (int i = 0; i < 8; ++i) {
            const int idx = i * 256 + tid;
            const int row = idx >> 5, ch = idx & 31;
            CP_ASYNC16(sb + (uint32_t)(row * QRS + ch * 4) * 4,
                       Qg + (long)row * C_DIM + ch * 4);
        }
#pragma unroll
        for (int i = 0; i < 16; ++i) {
            const int idx = i * 256 + tid;
            const int row = idx >> 5, ch = idx & 31;
            CP_ASYNC16(sb + (uint32_t)(AF_QW + row * QRS + ch * 4) * 4,
                       Kg + (long)row * C_DIM + ch * 4);
        }
        CP_COMMIT();
#pragma unroll
        for (int i = 0; i < 16; ++i) {
            const int idx = i * 256 + tid;
            const int row = idx >> 5, ch = idx & 31;
            CP_ASYNC16(sb + (uint32_t)(AF_QW + AF_KW + row * QRS + ch * 4) * 4,
                       Kg + (long)(128 + row) * C_DIM + ch * 4);
        }
        CP_COMMIT();
    }

    float acc[4][8][4];
#pragma unroll
    for (int i = 0; i < 4; ++i)
#pragma unroll
        for (int j = 0; j < 8; ++j)
#pragma unroll
            for (int q = 0; q < 4; ++q) acc[i][j][q] = 0.f;

#pragma unroll
    for (int c = 0; c < 4; ++c) {
        if (c < 3) { CP_WAITG(1); } else { CP_WAITG(0); }
        __syncthreads();

        const uint32_t kb = (uint32_t)(AF_QW + (c & 1) * AF_KW);
#pragma unroll
        for (int ks = 0; ks < 16; ++ks) {
            uint32_t a[4][4], b[4];
#pragma unroll
            for (int mt = 0; mt < 4; ++mt)
                ldsm_x4(a[mt], sb + (uint32_t)((16 * mt) * QRS + 8 * ks + aoffQ) * 4);
            ldsm_x4(b, sb + (kb + (uint32_t)((wid * 16) * QRS + 8 * ks) + boffK) * 4);
#pragma unroll
            for (int nt = 0; nt < 2; ++nt) {
                const uint32_t b0 = b[nt * 2], b1 = b[nt * 2 + 1];
#pragma unroll
                for (int mt = 0; mt < 4; ++mt)
                    mma_tf32(acc[mt][2 * c + nt],
                             a[mt][0], a[mt][1], a[mt][2], a[mt][3], b0, b1);
            }
        }
        __syncthreads();
        if (c + 2 < 4) {
            const uint32_t kb2 = (uint32_t)(AF_QW + (c & 1) * AF_KW);
#pragma unroll
            for (int i = 0; i < 16; ++i) {
                const int idx = i * 256 + tid;
                const int row = idx >> 5, ch = idx & 31;
                CP_ASYNC16(sb + (kb2 + (uint32_t)(row * QRS + ch * 4)) * 4,
                           Kg + (long)((c + 2) * 128 + row) * C_DIM + ch * 4);
            }
            CP_COMMIT();
        }
    }

#pragma unroll
    for (int b = 0; b < 2; ++b) {
#pragma unroll
        for (int i = 0; i < 8; ++i) {
            const int idx = i * 256 + tid;
            const int row = idx >> 4, ch = idx & 15;
            CP_ASYNC16(sb + (uint32_t)(b * AF_VW + row * 68 + ch * 4) * 4,
                       Vg + (long)row * S_KV + b * 64 + ch * 4);
        }
        CP_COMMIT();
    }

    float gm[4][2];
#pragma unroll
    for (int mt = 0; mt < 4; ++mt)
#pragma unroll
        for (int h = 0; h < 2; ++h) {
            float m = -1e30f;
#pragma unroll
            for (int j = 0; j < 8; ++j)
                m = fmaxf(m, fmaxf(acc[mt][j][2 * h], acc[mt][j][2 * h + 1]));
            m = fmaxf(m, __shfl_xor_sync(0xffffffffu, m, 1));
            m = fmaxf(m, __shfl_xor_sync(0xffffffffu, m, 2));
            if (t4 == 0) redmx[(16 * mt + 8 * h + g4) * 8 + wid] = m;
            gm[mt][h] = m;
        }
    __syncthreads();
#pragma unroll
    for (int mt = 0; mt < 4; ++mt)
#pragma unroll
        for (int h = 0; h < 2; ++h) {
            const int row = 16 * mt + 8 * h + g4;
            float m = gm[mt][h];
#pragma unroll
            for (int w = 0; w < 8; ++w) m = fmaxf(m, redmx[row * 8 + w]);
            gm[mt][h] = m;
        }
    float gs[4][2];
#pragma unroll
    for (int mt = 0; mt < 4; ++mt)
#pragma unroll
        for (int h = 0; h < 2; ++h) {
            float s = 0.f;
            const float m = gm[mt][h];
#pragma unroll
            for (int j = 0; j < 8; ++j) {
                float e0 = __expf(acc[mt][j][2 * h] - m);
                float e1 = __expf(acc[mt][j][2 * h + 1] - m);
                acc[mt][j][2 * h] = e0; acc[mt][j][2 * h + 1] = e1;
                s += e0 + e1;
            }
            s += __shfl_xor_sync(0xffffffffu, s, 1);
            s += __shfl_xor_sync(0xffffffffu, s, 2);
            if (t4 == 0) redsm[(16 * mt + 8 * h + g4) * 8 + wid] = s;
        }
    __syncthreads();
#pragma unroll
    for (int mt = 0; mt < 4; ++mt)
#pragma unroll
        for (int h = 0; h < 2; ++h) {
            const int row = 16 * mt + 8 * h + g4;
            float s = 0.f;
#pragma unroll
            for (int w = 0; w < 8; ++w) s += redsm[row * 8 + w];
            gs[mt][h] = 1.0f / s;
        }

#pragma unroll
    for (int mt = 0; mt < 4; ++mt)
#pragma unroll
        for (int h = 0; h < 2; ++h) {
            const int row = 16 * mt + 8 * h + g4;
            const float inv = gs[mt][h];
#pragma unroll
            for (int j = 0; j < 8; ++j) {
                const int col = 128 * (j >> 1) + wid * 16 + 8 * (j & 1) + 2 * t4;
                *(float2*)(sf + AF_PO + (uint32_t)(row * AF_PRS + col)) =
                    make_float2(tf32r(acc[mt][j][2 * h] * inv),
                                tf32r(acc[mt][j][2 * h + 1] * inv));
            }
        }
    __syncthreads();

    const int pwm = wid & 1, pwn = wid >> 1;
    float accP[2][4][4];
#pragma unroll
    for (int i = 0; i < 2; ++i)
#pragma unroll
        for (int j = 0; j < 4; ++j)
#pragma unroll
            for (int q = 0; q < 4; ++q) accP[i][j][q] = 0.f;

#pragma unroll
    for (int c = 0; c < 8; ++c) {
        if (c < 7) { CP_WAITG(1); } else { CP_WAITG(0); }
        __syncthreads();

        const uint32_t vb = (uint32_t)((c & 1) * AF_VW);
#pragma unroll
        for (int ks = 0; ks < 8; ++ks) {
            uint32_t a[2][4], b[2][4];
#pragma unroll
            for (int mt = 0; mt < 2; ++mt)
                ldsm_x4(a[mt], sb + (uint32_t)(AF_PO + (32 * pwm + 16 * mt) * AF_PRS
                                               + 64 * c + 8 * ks + aoffP) * 4);
#pragma unroll
            for (int np = 0; np < 2; ++np)
                ldsm_x4(b[np], sb + (vb + (uint32_t)((32 * pwn + 16 * np) * 68
                                                     + 8 * ks) + boffV) * 4);
#pragma unroll
            for (int nt = 0; nt < 4; ++nt) {
                const int np = nt >> 1, e = (nt & 1) * 2;
#pragma unroll
                for (int mt = 0; mt < 2; ++mt)
                    mma_tf32(accP[mt][nt],
                             a[mt][0], a[mt][1], a[mt][2], a[mt][3],
                             b[np][e], b[np][e + 1]);
            }
        }
        __syncthreads();
        if (c + 2 < 8) {
            const uint32_t vb2 = (uint32_t)((c & 1) * AF_VW);
#pragma unroll
            for (int i = 0; i < 8; ++i) {
                const int idx = i * 256 + tid;
                const int row = idx >> 4, ch = idx & 15;
                CP_ASYNC16(sb + (vb2 + (uint32_t)(row * 68 + ch * 4)) * 4,
                           Vg + (long)row * S_KV + (c + 2) * 64 + ch * 4);
            }
            CP_COMMIT();
        }
    }

    float* Og = O + (long)m0 * C_DIM + (long)z * HD;
    const int lr = lid >> 2, lc = (lid & 3) * 2;
#pragma unroll
    for (int mt = 0; mt < 2; ++mt) {
        const int r0 = 32 * pwm + 16 * mt + lr;
#pragma unroll
        for (int nt = 0; nt < 4; ++nt) {
            const int cix = 32 * pwn + 8 * nt + lc;
            *(float2*)(Og + (long)r0 * C_DIM + cix) =
                make_float2(tf32r(accP[mt][nt][0]), tf32r(accP[mt][nt][1]));
            *(float2*)(Og + (long)(r0 + 8) * C_DIM + cix) =
                make_float2(tf32r(accP[mt][nt][2]), tf32r(accP[mt][nt][3]));
        }
    }
}

// ---------------------------------------------------------------------------
// elementwise helpers (unchanged)
// ---------------------------------------------------------------------------
__device__ __forceinline__ void transT_body(const float* __restrict__ W,
                                            float* __restrict__ out,
                                            int Kd, int Nd, int bx, int by,
                                            int tidx)
{
    __shared__ float t[32][33];
    const int k0 = by * 32, n0 = bx * 32;
    const int tx = tidx & 31, ty = tidx >> 5;
#pragma unroll
    for (int r = 0; r < 4; ++r)
        t[ty + 8 * r][tx] = W[(long)(k0 + ty + 8 * r) * Nd + n0 + tx];
    __syncthreads();
#pragma unroll
    for (int r = 0; r < 4; ++r)
        out[(long)(n0 + ty + 8 * r) * Kd + k0 + tx] = tf32r(t[tx][ty + 8 * r]);
}

__global__ __launch_bounds__(256)
void transT4_kernel(const float* __restrict__ Wq, const float* __restrict__ Wk,
                    const float* __restrict__ Wv, const float* __restrict__ Wo,
                    float* __restrict__ wqt, float* __restrict__ wkvt,
                    float* __restrict__ wot)
{
    const int by = blockIdx.y;
    if (by < 64)
        transT_body(Wq, wqt, C_DIM, C_DIM, blockIdx.x, by, threadIdx.x);
    else if (by < 192)
        transT_body(Wk, wkvt, CTXD, C_DIM, blockIdx.x, by - 64, threadIdx.x);
    else if (by < 320)
        transT_body(Wv, wkvt + (long)C_DIM * CTXD, CTXD, C_DIM,
                    blockIdx.x, by - 192, threadIdx.x);
    else
        transT_body(Wo, wot, C_DIM, C_DIM, blockIdx.x, by - 320, threadIdx.x);
}

__global__ __launch_bounds__(256)
void transT_kernel(const float* __restrict__ W, float* __restrict__ out,
                   int Kd, int Nd)
{
    transT_body(W, out, Kd, Nd, blockIdx.x, blockIdx.y, threadIdx.x);
}

__global__ void concat_bias_kernel(const float* __restrict__ bk,
                                   const float* __restrict__ bv,
                                   float* __restrict__ o)
{
    int i = blockIdx.x * 256 + threadIdx.x;
    o[i] = bk[i];
    o[C_DIM + i] = bv[i];
}

__global__ __launch_bounds__(256)
void rmsnorm_kernel(float* __restrict__ buf, const float* __restrict__ g, float scale)
{
    float* row = buf + (long)blockIdx.x * C_DIM;
    const int t = threadIdx.x;
    float4 v0 = *(float4*)(row + t * 4);
    float4 v1 = *(float4*)(row + 1024 + t * 4);
    float ss = v0.x * v0.x + v0.y * v0.y + v0.z * v0.z + v0.w * v0.w
             + v1.x * v1.x + v1.y * v1.y + v1.z * v1.z + v1.w * v1.w;
#pragma unroll
    for (int o = 16; o > 0; o >>= 1) ss += __shfl_xor_sync(0xffffffffu, ss, o);
    __shared__ float ws[8]; __shared__ float s_inv;
    if ((t & 31) == 0) ws[t >> 5] = ss;
    __syncthreads();
    if (t == 0) {
        float s = 0.f;
#pragma unroll
        for (int i = 0; i < 8; ++i) s += ws[i];
        s_inv = rsqrtf(s * (1.0f / C_DIM) + 1e-6f) * scale;
    }
    __syncthreads();
    const float inv = s_inv;
    float4 w0 = *(const float4*)(g + t * 4);
    float4 w1 = *(const float4*)(g + 1024 + t * 4);
    *(float4*)(row + t * 4) = make_float4(
        tf32r(v0.x * inv * w0.x), tf32r(v0.y * inv * w0.y),
        tf32r(v0.z * inv * w0.z), tf32r(v0.w * inv * w0.w));
    *(float4*)(row + 1024 + t * 4) = make_float4(
        tf32r(v1.x * inv * w1.x), tf32r(v1.y * inv * w1.y),
        tf32r(v1.z * inv * w1.z), tf32r(v1.w * inv * w1.w));
}

// ---------------------------------------------------------------------------
extern "C" void kernel_launch(void* const* d_in, const int* in_sizes, int n_in,
                              void* d_out, int out_size)
{
    (void)in_sizes; (void)n_in; (void)out_size;
    const float* x   = (const float*)d_in[0];
    const float* ctx = (const float*)d_in[1];
    const float* Wq  = (const float*)d_in[2];
    const float* bq  = (const float*)d_in[3];
    const float* Wk  = (const float*)d_in[4];
    const float* bk  = (const float*)d_in[5];
    const float* Wv  = (const float*)d_in[6];
    const float* bv  = (const float*)d_in[7];
    const float* Wo  = (const float*)d_in[8];
    const float* bo  = (const float*)d_in[9];
    const float* gq  = (const float*)d_in[10];
    const float* gk  = (const float*)d_in[11];
    float* out = (float*)d_out;

    cudaFuncSetAttribute(tf_gemm<1,0,1>, cudaFuncAttributeMaxDynamicSharedMemorySize, SM3);
    cudaFuncSetAttribute(tf_gemm<1,0,0>, cudaFuncAttributeMaxDynamicSharedMemorySize, SM3);
    cudaFuncSetAttribute(attn_fused, cudaFuncAttributeMaxDynamicSharedMemorySize, AF_SMB);

    float *wqt, *wkvt, *wot, *qf, *kvf, *vt, *atf, *bkv;
    cudaGetSymbolAddress((void**)&wqt,  g_wqt);
    cudaGetSymbolAddress((void**)&wkvt, g_wkvt);
    cudaGetSymbolAddress((void**)&wot,  g_wot);
    cudaGetSymbolAddress((void**)&qf,   g_qf);
    cudaGetSymbolAddress((void**)&kvf,  g_kvf);
    cudaGetSymbolAddress((void**)&vt,   g_vt);
    cudaGetSymbolAddress((void**)&atf,  g_atf);
    cudaGetSymbolAddress((void**)&bkv,  g_bkv);

    const long WKV = (long)C_DIM * CTXD;
    const long SKV = (long)S_KV * C_DIM;
    const float ATTN_SCALE = 0.08838834764831845f;   // 1/sqrt(128)

    // ---- weight transposes (merged) + bias concat --------------------------
    transT4_kernel<<<dim3(64, 384), 256>>>(Wq, Wk, Wv, Wo, wqt, wkvt, wot);
    concat_bias_kernel<<<C_DIM / 256, 256>>>(bk, bv, bkv);

    // ---- projections --------------------------------------------------------
    tf_gemm<1,0,1><<<dim3(16, 64, 1), 256, SM3>>>(x, C_DIM, 0, wqt, C_DIM, 0,
                                                  bq, 0, qf, C_DIM, 0, C_DIM);
    tf_gemm<1,0,1><<<dim3(16, 4, 2), 256, SM3>>>(ctx, CTXD, 0, wkvt, CTXD, WKV,
                                                 bkv, C_DIM, kvf, C_DIM, SKV, CTXD);

    // ---- norms / transposes -------------------------------------------------
    rmsnorm_kernel<<<L_Q, 256>>>(qf, gq, ATTN_SCALE);
    rmsnorm_kernel<<<S_KV, 256>>>(kvf, gk, 1.0f);
    transT_kernel<<<dim3(C_DIM / 32, S_KV / 32), 256>>>(kvf + SKV, vt, S_KV, C_DIM);

    // ---- fused attention ----------------------------------------------------
    attn_fused<<<dim3(L_Q / 64, NH), 256, AF_SMB>>>(qf, kvf, vt, atf);

    // ---- output projection --------------------------------------------------
    tf_gemm<1,0,0><<<dim3(16, 64, 1), 256, SM3>>>(atf, C_DIM, 0, wot, C_DIM, 0,
                                                  bo, 0, out, C_DIM, 0, C_DIM);
}

// round 13
// speedup vs baseline: 3.7109x; 1.0027x over previous
#include <cuda_runtime.h>
#include <cstdint>
#include <math.h>

// ===========================================================================
// WanCrossAttention  (B=1, L=8192, S=512, C=2048, CTX=4096, H=16, D=128)
// Round-12: TF32 pipeline; tf_gemm reworked for 2 CTAs/SM:
//   K-chunk 32, 3 stages (108 KB smem), __launch_bounds__(256,2) (<=128 regs),
//   pointer state compressed to 2 bases + 32-bit offsets.
// ncu R11 showed tf_gemm at occ=12.5%, tensor=42.9% -> occupancy-bound.
// Arithmetic bit-identical to rounds 9-11.
// ===========================================================================

#define L_Q   8192
#define S_KV  512
#define C_DIM 2048
#define CTXD  4096
#define NH    16
#define HD    128

// tf32 GEMM tiling: CTA 128x128, TK=32 fp32, 3-stage cp.async pipeline
#define RS3   36                     // smem row stride (words): 32 + 4 pad
#define RS3B  144
#define MT3   (128 * RS3B)           // 18432 B per matrix tile
#define STG3  (2 * MT3)              // 36864 B per stage (A, B)
#define SM3   (3 * STG3)             // 110592 B  -> 2 CTAs/SM

// attn_fused smem layout (unchanged)
#define QRS    132
#define AF_QW  (64 * QRS)
#define AF_KW  (128 * QRS)
#define AF_VW  (128 * 68)
#define AF_PO  17408
#define AF_PRS 516
#define AF_RED 50432
#define AF_SMW 51456
#define AF_SMB (AF_SMW * 4)          // 205824 B

// ---------------- scratch ---------------------------------------------------
__device__ float g_wqt[C_DIM * C_DIM];
__device__ float g_wkvt[2 * C_DIM * CTXD];
__device__ float g_wot[C_DIM * C_DIM];
__device__ float g_qf[L_Q * C_DIM];
__device__ float g_kvf[2 * S_KV * C_DIM];
__device__ float g_vt[C_DIM * S_KV];
__device__ float g_atf[L_Q * C_DIM];
__device__ float g_bkv[2 * C_DIM];

// ---------------- asm helpers ----------------------------------------------
__device__ __forceinline__ uint32_t smem_u32(const void* p) {
    uint32_t a;
    asm("{ .reg .u64 t; cvta.to.shared.u64 t, %1; cvt.u32.u64 %0, t; }"
        : "=r"(a) : "l"(p));
    return a;
}
__device__ __forceinline__ float tf32r(float x) {
    uint32_t o;
    asm("cvt.rna.tf32.f32 %0, %1;" : "=r"(o) : "f"(x));
    return __uint_as_float(o);
}
__device__ __forceinline__ uint32_t tf32rb(uint32_t x) {
    uint32_t o;
    asm("cvt.rna.tf32.f32 %0, %1;" : "=r"(o) : "f"(__uint_as_float(x)));
    return o;
}
__device__ __forceinline__ void ldsm_x4(uint32_t* r, uint32_t addr) {
    asm volatile("ldmatrix.sync.aligned.m8n8.x4.shared.b16 {%0,%1,%2,%3}, [%4];"
                 : "=r"(r[0]), "=r"(r[1]), "=r"(r[2]), "=r"(r[3]) : "r"(addr));
}
__device__ __forceinline__ void mma_tf32(float* c, uint32_t a0, uint32_t a1,
                                         uint32_t a2, uint32_t a3,
                                         uint32_t b0, uint32_t b1) {
    asm volatile(
        "mma.sync.aligned.m16n8k8.row.col.f32.tf32.tf32.f32 "
        "{%0,%1,%2,%3}, {%4,%5,%6,%7}, {%8,%9}, {%0,%1,%2,%3};"
        : "+f"(c[0]), "+f"(c[1]), "+f"(c[2]), "+f"(c[3])
        : "r"(a0), "r"(a1), "r"(a2), "r"(a3), "r"(b0), "r"(b1));
}
#define CP_ASYNC16(dst, src) \
    asm volatile("cp.async.cg.shared.global [%0], [%1], 16;" :: "r"(dst), "l"(src))
#define CP_COMMIT() asm volatile("cp.async.commit_group;" ::: "memory")
#define CP_WAITG(n) asm volatile("cp.async.wait_group %0;" :: "n"(n) : "memory")

// ---------------------------------------------------------------------------
// TF32 GEMM, K-chunk 32, 3-stage pipeline, 2 CTAs/SM.
// K % 32 == 0, K/32 >= 2.
// ---------------------------------------------------------------------------
template <int BIASMODE, int ROUND, int RNDA>
__global__ __launch_bounds__(256, 2)
void tf_gemm(const float* __restrict__ A, int lda, long sA,
             const float* __restrict__ B, int ldb, long sB,
             const float* __restrict__ bias, long sBias,
             float* __restrict__ C, int ldc, long sC, int K)
{
    extern __shared__ char smem[];
    const uint32_t sb = smem_u32(smem);
    const int tid = threadIdx.x, wid = tid >> 5, lid = tid & 31;
    const int m0 = blockIdx.y * 128, n0 = blockIdx.x * 128;

    const float* Ab = A + (long)blockIdx.z * sA + (long)m0 * lda;
    const float* Bb = B + (long)blockIdx.z * sB + (long)n0 * ldb;

    // loader: 2048 16B chunks per stage (A:1024, B:1024), 8 per thread.
    // i<4 -> A, i>=4 -> B (compile-time). 32-bit element offsets save regs.
    uint32_t goff[8], so[8];
#pragma unroll
    for (int i = 0; i < 8; ++i) {
        const int idx = i * 256 + tid;
        const int row = (idx >> 3) & 127;
        const int ch  = idx & 7;
        goff[i] = (uint32_t)(row * ((i < 4) ? lda : ldb) + ch * 4);
        so[i] = (uint32_t)(((i < 4) ? 0 : MT3) + row * RS3B + ch * 16);
    }

#define ISSUE_STAGE(stage, kidx) do {                                       \
        const uint32_t _db = sb + (uint32_t)(stage) * STG3;                 \
        const uint32_t _go = (uint32_t)(kidx) * 32;                         \
        _Pragma("unroll")                                                   \
        for (int _i = 0; _i < 4; ++_i)                                      \
            CP_ASYNC16(_db + so[_i], Ab + goff[_i] + _go);                  \
        _Pragma("unroll")                                                   \
        for (int _i = 4; _i < 8; ++_i)                                      \
            CP_ASYNC16(_db + so[_i], Bb + goff[_i] + _go);                  \
    } while (0)

    // ldmatrix thread offsets (words within a stage)
    const int lm = lid >> 3, lr8 = lid & 7;
    const int wm = wid >> 2, wn = wid & 3;
    const uint32_t fA = (uint32_t)((wm * 64 + lr8 + 8 * (lm & 1)) * RS3
                                   + 4 * (lm >> 1));
    const uint32_t fB = (uint32_t)(MT3 / 4 + (wn * 32 + lr8 + 8 * (lm >> 1)) * RS3
                                   + 4 * (lm & 1));

    float acc[4][4][4];
#pragma unroll
    for (int i = 0; i < 4; ++i)
#pragma unroll
        for (int j = 0; j < 4; ++j)
#pragma unroll
            for (int q = 0; q < 4; ++q) acc[i][j][q] = 0.f;

    const int nch = K >> 5;

    ISSUE_STAGE(0, 0); CP_COMMIT();
    ISSUE_STAGE(1, 1); CP_COMMIT();

    int buf = 0;
    for (int c = 0; c < nch; ++c) {
        CP_WAITG(1);
        __syncthreads();
        if (c + 2 < nch) {
            int nb = buf + 2; if (nb >= 3) nb -= 3;
            ISSUE_STAGE(nb, c + 2);
        }
        CP_COMMIT();

        const uint32_t base = ((uint32_t)buf * STG3) >> 2;
#pragma unroll
        for (int s = 0; s < 4; ++s) {
            const uint32_t ko = s * 8;
            uint32_t a[4][4], b[2][4];
#pragma unroll
            for (int mt = 0; mt < 4; ++mt) {
                ldsm_x4(a[mt], sb + (base + fA + mt * (16 * RS3) + ko) * 4);
                if (RNDA) {
#pragma unroll
                    for (int q = 0; q < 4; ++q) a[mt][q] = tf32rb(a[mt][q]);
                }
            }
#pragma unroll
            for (int np = 0; np < 2; ++np)
                ldsm_x4(b[np], sb + (base + fB + np * (16 * RS3) + ko) * 4);
#pragma unroll
            for (int mt = 0; mt < 4; ++mt)
#pragma unroll
                for (int nt = 0; nt < 4; ++nt) {
                    const int np = nt >> 1, e = (nt & 1) * 2;
                    mma_tf32(acc[mt][nt], a[mt][0], a[mt][1], a[mt][2], a[mt][3],
                             b[np][e], b[np][e + 1]);
                }
        }
        if (++buf == 3) buf = 0;
        __syncthreads();
    }
#undef ISSUE_STAGE

    const float* bp = (BIASMODE != 0) ? (bias + (long)blockIdx.z * sBias) : bias;
    float* Cp = C + (long)blockIdx.z * sC;
    const int row_base = m0 + wm * 64;
    const int col_base = n0 + wn * 32;
    const int lr = lid >> 2, lc = (lid & 3) * 2;
#pragma unroll
    for (int mt = 0; mt < 4; ++mt) {
        const int r0 = row_base + mt * 16 + lr;
#pragma unroll
        for (int nt = 0; nt < 4; ++nt) {
            const int cix = col_base + nt * 8 + lc;
            float b0 = 0.f, b1 = 0.f;
            if (BIASMODE == 1) { b0 = bp[cix]; b1 = bp[cix + 1]; }
            float v00 = acc[mt][nt][0] + b0, v01 = acc[mt][nt][1] + b1;
            float v10 = acc[mt][nt][2] + b0, v11 = acc[mt][nt][3] + b1;
            if (ROUND) {
                v00 = tf32r(v00); v01 = tf32r(v01);
                v10 = tf32r(v10); v11 = tf32r(v11);
            }
            *(float2*)(Cp + (long)r0 * ldc + cix)       = make_float2(v00, v01);
            *(float2*)(Cp + (long)(r0 + 8) * ldc + cix) = make_float2(v10, v11);
        }
    }
}

// ---------------------------------------------------------------------------
// Fused attention (unchanged from round 10/11).
// ---------------------------------------------------------------------------
__global__ __launch_bounds__(256, 1)
void attn_fused(const float* __restrict__ Q, const float* __restrict__ Km,
                const float* __restrict__ Vt, float* __restrict__ O)
{
    extern __shared__ char smem[];
    const uint32_t sb = smem_u32(smem);
    float* sf = (float*)smem;
    float* redmx = sf + AF_RED;
    float* redsm = redmx + 512;

    const int tid = threadIdx.x, wid = tid >> 5, lid = tid & 31;
    const int g4 = lid >> 2, t4 = lid & 3;
    const int lm = lid >> 3, lr8 = lid & 7;
    const int m0 = blockIdx.x * 64;
    const int z  = blockIdx.y;

    const float* Qg = Q + (long)z * HD + (long)m0 * C_DIM;
    const float* Kg = Km + (long)z * HD;
    const float* Vg = Vt + (long)z * HD * S_KV;

    const uint32_t aoffQ = (uint32_t)((lr8 + 8 * (lm & 1)) * QRS + 4 * (lm >> 1));
    const uint32_t boffK = (uint32_t)((lr8 + 8 * (lm >> 1)) * QRS + 4 * (lm & 1));
    const uint32_t aoffP = (uint32_t)((lr8 + 8 * (lm & 1)) * AF_PRS + 4 * (lm >> 1));
    const uint32_t boffV = (uint32_t)((lr8 + 8 * (lm >> 1)) * 68 + 4 * (lm & 1));

    {
#pragma unroll
        for (int i = 0; i < 8; ++i) {
            const int idx = i * 256 + tid;
            const int row = idx >> 5, ch = idx & 31;
            CP_ASYNC16(sb + (uint32_t)(row * QRS + ch * 4) * 4,
                       Qg + (long)row * C_DIM + ch * 4);
        }
#pragma unroll
        for (int i = 0; i < 16; ++i) {
            const int idx = i * 256 + tid;
            const int row = idx >> 5, ch = idx & 31;
            CP_ASYNC16(sb + (uint32_t)(AF_QW + row * QRS + ch * 4) * 4,
                       Kg + (long)row * C_DIM + ch * 4);
        }
        CP_COMMIT();
#pragma unroll
        for (int i = 0; i < 16; ++i) {
            const int idx = i * 256 + tid;
            const int row = idx >> 5, ch = idx & 31;
            CP_ASYNC16(sb + (uint32_t)(AF_QW + AF_KW + row * QRS + ch * 4) * 4,
                       Kg + (long)(128 + row) * C_DIM + ch * 4);
        }
        CP_COMMIT();
    }

    float acc[4][8][4];
#pragma unroll
    for (int i = 0; i < 4; ++i)
#pragma unroll
        for (int j = 0; j < 8; ++j)
#pragma unroll
            for (int q = 0; q < 4; ++q) acc[i][j][q] = 0.f;

#pragma unroll
    for (int c = 0; c < 4; ++c) {
        if (c < 3) { CP_WAITG(1); } else { CP_WAITG(0); }
        __syncthreads();

        const uint32_t kb = (uint32_t)(AF_QW + (c & 1) * AF_KW);
#pragma unroll
        for (int ks = 0; ks < 16; ++ks) {
            uint32_t a[4][4], b[4];
#pragma unroll
            for (int mt = 0; mt < 4; ++mt)
                ldsm_x4(a[mt], sb + (uint32_t)((16 * mt) * QRS + 8 * ks + aoffQ) * 4);
            ldsm_x4(b, sb + (kb + (uint32_t)((wid * 16) * QRS + 8 * ks) + boffK) * 4);
#pragma unroll
            for (int nt = 0; nt < 2; ++nt) {
                const uint32_t b0 = b[nt * 2], b1 = b[nt * 2 + 1];
#pragma unroll
                for (int mt = 0; mt < 4; ++mt)
                    mma_tf32(acc[mt][2 * c + nt],
                             a[mt][0], a[mt][1], a[mt][2], a[mt][3], b0, b1);
            }
        }
        __syncthreads();
        if (c + 2 < 4) {
            const uint32_t kb2 = (uint32_t)(AF_QW + (c & 1) * AF_KW);
#pragma unroll
            for (int i = 0; i < 16; ++i) {
                const int idx = i * 256 + tid;
                const int row = idx >> 5, ch = idx & 31;
                CP_ASYNC16(sb + (kb2 + (uint32_t)(row * QRS + ch * 4)) * 4,
                           Kg + (long)((c + 2) * 128 + row) * C_DIM + ch * 4);
            }
            CP_COMMIT();
        }
    }

#pragma unroll
    for (int b = 0; b < 2; ++b) {
#pragma unroll
        for (int i = 0; i < 8; ++i) {
            const int idx = i * 256 + tid;
            const int row = idx >> 4, ch = idx & 15;
            CP_ASYNC16(sb + (uint32_t)(b * AF_VW + row * 68 + ch * 4) * 4,
                       Vg + (long)row * S_KV + b * 64 + ch * 4);
        }
        CP_COMMIT();
    }

    float gm[4][2];
#pragma unroll
    for (int mt = 0; mt < 4; ++mt)
#pragma unroll
        for (int h = 0; h < 2; ++h) {
            float m = -1e30f;
#pragma unroll
            for (int j = 0; j < 8; ++j)
                m = fmaxf(m, fmaxf(acc[mt][j][2 * h], acc[mt][j][2 * h + 1]));
            m = fmaxf(m, __shfl_xor_sync(0xffffffffu, m, 1));
            m = fmaxf(m, __shfl_xor_sync(0xffffffffu, m, 2));
            if (t4 == 0) redmx[(16 * mt + 8 * h + g4) * 8 + wid] = m;
            gm[mt][h] = m;
        }
    __syncthreads();
#pragma unroll
    for (int mt = 0; mt < 4; ++mt)
#pragma unroll
        for (int h = 0; h < 2; ++h) {
            const int row = 16 * mt + 8 * h + g4;
            float m = gm[mt][h];
#pragma unroll
            for (int w = 0; w < 8; ++w) m = fmaxf(m, redmx[row * 8 + w]);
            gm[mt][h] = m;
        }
    float gs[4][2];
#pragma unroll
    for (int mt = 0; mt < 4; ++mt)
#pragma unroll
        for (int h = 0; h < 2; ++h) {
            float s = 0.f;
            const float m = gm[mt][h];
#pragma unroll
            for (int j = 0; j < 8; ++j) {
                float e0 = __expf(acc[mt][j][2 * h] - m);
                float e1 = __expf(acc[mt][j][2 * h + 1] - m);
                acc[mt][j][2 * h] = e0; acc[mt][j][2 * h + 1] = e1;
                s += e0 + e1;
            }
            s += __shfl_xor_sync(0xffffffffu, s, 1);
            s += __shfl_xor_sync(0xffffffffu, s, 2);
            if (t4 == 0) redsm[(16 * mt + 8 * h + g4) * 8 + wid] = s;
        }
    __syncthreads();
#pragma unroll
    for (int mt = 0; mt < 4; ++mt)
#pragma unroll
        for (int h = 0; h < 2; ++h) {
            const int row = 16 * mt + 8 * h + g4;
            float s = 0.f;
#pragma unroll
            for (int w = 0; w < 8; ++w) s += redsm[row * 8 + w];
            gs[mt][h] = 1.0f / s;
        }

#pragma unroll
    for (int mt = 0; mt < 4; ++mt)
#pragma unroll
        for (int h = 0; h < 2; ++h) {
            const int row = 16 * mt + 8 * h + g4;
            const float inv = gs[mt][h];
#pragma unroll
            for (int j = 0; j < 8; ++j) {
                const int col = 128 * (j >> 1) + wid * 16 + 8 * (j & 1) + 2 * t4;
                *(float2*)(sf + AF_PO + (uint32_t)(row * AF_PRS + col)) =
                    make_float2(tf32r(acc[mt][j][2 * h] * inv),
                                tf32r(acc[mt][j][2 * h + 1] * inv));
            }
        }
    __syncthreads();

    const int pwm = wid & 1, pwn = wid >> 1;
    float accP[2][4][4];
#pragma unroll
    for (int i = 0; i < 2; ++i)
#pragma unroll
        for (int j = 0; j < 4; ++j)
#pragma unroll
            for (int q = 0; q < 4; ++q) accP[i][j][q] = 0.f;

#pragma unroll
    for (int c = 0; c < 8; ++c) {
        if (c < 7) { CP_WAITG(1); } else { CP_WAITG(0); }
        __syncthreads();

        const uint32_t vb = (uint32_t)((c & 1) * AF_VW);
#pragma unroll
        for (int ks = 0; ks < 8; ++ks) {
            uint32_t a[2][4], b[2][4];
#pragma unroll
            for (int mt = 0; mt < 2; ++mt)
                ldsm_x4(a[mt], sb + (uint32_t)(AF_PO + (32 * pwm + 16 * mt) * AF_PRS
                                               + 64 * c + 8 * ks + aoffP) * 4);
#pragma unroll
            for (int np = 0; np < 2; ++np)
                ldsm_x4(b[np], sb + (vb + (uint32_t)((32 * pwn + 16 * np) * 68
                                                     + 8 * ks) + boffV) * 4);
#pragma unroll
            for (int nt = 0; nt < 4; ++nt) {
                const int np = nt >> 1, e = (nt & 1) * 2;
#pragma unroll
                for (int mt = 0; mt < 2; ++mt)
                    mma_tf32(accP[mt][nt],
                             a[mt][0], a[mt][1], a[mt][2], a[mt][3],
                             b[np][e], b[np][e + 1]);
            }
        }
        __syncthreads();
        if (c + 2 < 8) {
            const uint32_t vb2 = (uint32_t)((c & 1) * AF_VW);
#pragma unroll
            for (int i = 0; i < 8; ++i) {
                const int idx = i * 256 + tid;
                const int row = idx >> 4, ch = idx & 15;
                CP_ASYNC16(sb + (vb2 + (uint32_t)(row * 68 + ch * 4)) * 4,
                           Vg + (long)row * S_KV + (c + 2) * 64 + ch * 4);
            }
            CP_COMMIT();
        }
    }

    float* Og = O + (long)m0 * C_DIM + (long)z * HD;
    const int lr = lid >> 2, lc = (lid & 3) * 2;
#pragma unroll
    for (int mt = 0; mt < 2; ++mt) {
        const int r0 = 32 * pwm + 16 * mt + lr;
#pragma unroll
        for (int nt = 0; nt < 4; ++nt) {
            const int cix = 32 * pwn + 8 * nt + lc;
            *(float2*)(Og + (long)r0 * C_DIM + cix) =
                make_float2(tf32r(accP[mt][nt][0]), tf32r(accP[mt][nt][1]));
            *(float2*)(Og + (long)(r0 + 8) * C_DIM + cix) =
                make_float2(tf32r(accP[mt][nt][2]), tf32r(accP[mt][nt][3]));
        }
    }
}

// ---------------------------------------------------------------------------
// elementwise helpers (unchanged)
// ---------------------------------------------------------------------------
__device__ __forceinline__ void transT_body(const float* __restrict__ W,
                                            float* __restrict__ out,
                                            int Kd, int Nd, int bx, int by,
                                            int tidx)
{
    __shared__ float t[32][33];
    const int k0 = by * 32, n0 = bx * 32;
    const int tx = tidx & 31, ty = tidx >> 5;
#pragma unroll
    for (int r = 0; r < 4; ++r)
        t[ty + 8 * r][tx] = W[(long)(k0 + ty + 8 * r) * Nd + n0 + tx];
    __syncthreads();
#pragma unroll
    for (int r = 0; r < 4; ++r)
        out[(long)(n0 + ty + 8 * r) * Kd + k0 + tx] = tf32r(t[tx][ty + 8 * r]);
}

__global__ __launch_bounds__(256)
void transT4_kernel(const float* __restrict__ Wq, const float* __restrict__ Wk,
                    const float* __restrict__ Wv, const float* __restrict__ Wo,
                    float* __restrict__ wqt, float* __restrict__ wkvt,
                    float* __restrict__ wot)
{
    const int by = blockIdx.y;
    if (by < 64)
        transT_body(Wq, wqt, C_DIM, C_DIM, blockIdx.x, by, threadIdx.x);
    else if (by < 192)
        transT_body(Wk, wkvt, CTXD, C_DIM, blockIdx.x, by - 64, threadIdx.x);
    else if (by < 320)
        transT_body(Wv, wkvt + (long)C_DIM * CTXD, CTXD, C_DIM,
                    blockIdx.x, by - 192, threadIdx.x);
    else
        transT_body(Wo, wot, C_DIM, C_DIM, blockIdx.x, by - 320, threadIdx.x);
}

__global__ __launch_bounds__(256)
void transT_kernel(const float* __restrict__ W, float* __restrict__ out,
                   int Kd, int Nd)
{
    transT_body(W, out, Kd, Nd, blockIdx.x, blockIdx.y, threadIdx.x);
}

__global__ void concat_bias_kernel(const float* __restrict__ bk,
                                   const float* __restrict__ bv,
                                   float* __restrict__ o)
{
    int i = blockIdx.x * 256 + threadIdx.x;
    o[i] = bk[i];
    o[C_DIM + i] = bv[i];
}

__global__ __launch_bounds__(256)
void rmsnorm_kernel(float* __restrict__ buf, const float* __restrict__ g, float scale)
{
    float* row = buf + (long)blockIdx.x * C_DIM;
    const int t = threadIdx.x;
    float4 v0 = *(float4*)(row + t * 4);
    float4 v1 = *(float4*)(row + 1024 + t * 4);
    float ss = v0.x * v0.x + v0.y * v0.y + v0.z * v0.z + v0.w * v0.w
             + v1.x * v1.x + v1.y * v1.y + v1.z * v1.z + v1.w * v1.w;
#pragma unroll
    for (int o = 16; o > 0; o >>= 1) ss += __shfl_xor_sync(0xffffffffu, ss, o);
    __shared__ float ws[8]; __shared__ float s_inv;
    if ((t & 31) == 0) ws[t >> 5] = ss;
    __syncthreads();
    if (t == 0) {
        float s = 0.f;
#pragma unroll
        for (int i = 0; i < 8; ++i) s += ws[i];
        s_inv = rsqrtf(s * (1.0f / C_DIM) + 1e-6f) * scale;
    }
    __syncthreads();
    const float inv = s_inv;
    float4 w0 = *(const float4*)(g + t * 4);
    float4 w1 = *(const float4*)(g + 1024 + t * 4);
    *(float4*)(row + t * 4) = make_float4(
        tf32r(v0.x * inv * w0.x), tf32r(v0.y * inv * w0.y),
        tf32r(v0.z * inv * w0.z), tf32r(v0.w * inv * w0.w));
    *(float4*)(row + 1024 + t * 4) = make_float4(
        tf32r(v1.x * inv * w1.x), tf32r(v1.y * inv * w1.y),
        tf32r(v1.z * inv * w1.z), tf32r(v1.w * inv * w1.w));
}

// ---------------------------------------------------------------------------
extern "C" void kernel_launch(void* const* d_in, const int* in_sizes, int n_in,
                              void* d_out, int out_size)
{
    (void)in_sizes; (void)n_in; (void)out_size;
    const float* x   = (const float*)d_in[0];
    const float* ctx = (const float*)d_in[1];
    const float* Wq  = (const float*)d_in[2];
    const float* bq  = (const float*)d_in[3];
    const float* Wk  = (const float*)d_in[4];
    const float* bk  = (const float*)d_in[5];
    const float* Wv  = (const float*)d_in[6];
    const float* bv  = (const float*)d_in[7];
    const float* Wo  = (const float*)d_in[8];
    const float* bo  = (const float*)d_in[9];
    const float* gq  = (const float*)d_in[10];
    const float* gk  = (const float*)d_in[11];
    float* out = (float*)d_out;

    cudaFuncSetAttribute(tf_gemm<1,0,1>, cudaFuncAttributeMaxDynamicSharedMemorySize, SM3);
    cudaFuncSetAttribute(tf_gemm<1,0,0>, cudaFuncAttributeMaxDynamicSharedMemorySize, SM3);
    cudaFuncSetAttribute(attn_fused, cudaFuncAttributeMaxDynamicSharedMemorySize, AF_SMB);

    float *wqt, *wkvt, *wot, *qf, *kvf, *vt, *atf, *bkv;
    cudaGetSymbolAddress((void**)&wqt,  g_wqt);
    cudaGetSymbolAddress((void**)&wkvt, g_wkvt);
    cudaGetSymbolAddress((void**)&wot,  g_wot);
    cudaGetSymbolAddress((void**)&qf,   g_qf);
    cudaGetSymbolAddress((void**)&kvf,  g_kvf);
    cudaGetSymbolAddress((void**)&vt,   g_vt);
    cudaGetSymbolAddress((void**)&atf,  g_atf);
    cudaGetSymbolAddress((void**)&bkv,  g_bkv);

    const long WKV = (long)C_DIM * CTXD;
    const long SKV = (long)S_KV * C_DIM;
    const float ATTN_SCALE = 0.08838834764831845f;   // 1/sqrt(128)

    // ---- weight transposes (merged) + bias concat --------------------------
    transT4_kernel<<<dim3(64, 384), 256>>>(Wq, Wk, Wv, Wo, wqt, wkvt, wot);
    concat_bias_kernel<<<C_DIM / 256, 256>>>(bk, bv, bkv);

    // ---- projections --------------------------------------------------------
    tf_gemm<1,0,1><<<dim3(16, 64, 1), 256, SM3>>>(x, C_DIM, 0, wqt, C_DIM, 0,
                                                  bq, 0, qf, C_DIM, 0, C_DIM);
    tf_gemm<1,0,1><<<dim3(16, 4, 2), 256, SM3>>>(ctx, CTXD, 0, wkvt, CTXD, WKV,
                                                 bkv, C_DIM, kvf, C_DIM, SKV, CTXD);

    // ---- norms / transposes -------------------------------------------------
    rmsnorm_kernel<<<L_Q, 256>>>(qf, gq, ATTN_SCALE);
    rmsnorm_kernel<<<S_KV, 256>>>(kvf, gk, 1.0f);
    transT_kernel<<<dim3(C_DIM / 32, S_KV / 32), 256>>>(kvf + SKV, vt, S_KV, C_DIM);

    // ---- fused attention ----------------------------------------------------
    attn_fused<<<dim3(L_Q / 64, NH), 256, AF_SMB>>>(qf, kvf, vt, atf);

    // ---- output projection --------------------------------------------------
    tf_gemm<1,0,0><<<dim3(16, 64, 1), 256, SM3>>>(atf, C_DIM, 0, wot, C_DIM, 0,
                                                  bo, 0, out, C_DIM, 0, C_DIM);
}